// round 2
// baseline (speedup 1.0000x reference)
#include <cuda_runtime.h>
#include <math.h>

#define CC 64
#define SP 9216
#define PP 102
#define SPP 10404
#define NLN 665856

__device__ float g_band[4][SP];
__device__ float g_opout[4][SP];
__device__ float g_feat[8][CC * SP];
__device__ float g_dwo[CC * SPP];
__device__ float g_pwo[CC * SPP];
__device__ float g_l1o[4 * CC * SP];
__device__ float g_l1wT[6 * CC * 49 * 256];
__device__ float g_red[2];
__device__ float g_stats[2];
__device__ float g_G[4096];
__device__ float g_s[64];
__device__ float g_M[4096];
__device__ float g_bias[64];

__global__ void __launch_bounds__(256) k_dwt(const float* __restrict__ img) {
    int idx = blockIdx.x * 256 + threadIdx.x;
    if (idx >= SP) return;
    int i = idx / 96, j = idx % 96;
    float a = img[(2 * i) * 192 + 2 * j];
    float b = img[(2 * i + 1) * 192 + 2 * j];
    float c = img[(2 * i) * 192 + 2 * j + 1];
    float d = img[(2 * i + 1) * 192 + 2 * j + 1];
    g_band[0][idx] = (a + b + c + d) * 0.5f;
    g_band[1][idx] = (a + b - c - d) * 0.5f;
    g_band[2][idx] = (a - b + c - d) * 0.5f;
    g_band[3][idx] = (a - b - c + d) * 0.5f;
}

__global__ void __launch_bounds__(256) k_l1wt(const float* __restrict__ w) {
    int idx = blockIdx.x * 256 + threadIdx.x;
    if (idx >= 6 * 256 * 64 * 49) return;
    int k = idx % 49; int t = idx / 49;
    int ic = t % 64; t /= 64;
    int oc = t % 256; int blk = t / 256;
    g_l1wT[blk * (64 * 49 * 256) + (ic * 49 + k) * 256 + oc] = w[idx];
}

__global__ void __launch_bounds__(256) k_ip(int bi, int fi, const float* __restrict__ w,
                                            const float* __restrict__ bb) {
    __shared__ float sw[576];
    __shared__ float sb2[64];
    for (int t = threadIdx.x; t < 576; t += 256) sw[t] = w[t];
    if (threadIdx.x < 64) sb2[threadIdx.x] = bb[threadIdx.x];
    __syncthreads();
    int idx = blockIdx.x * 256 + threadIdx.x;
    if (idx >= CC * SP) return;
    int v = idx % 96; int u = (idx / 96) % 96; int ch = idx / SP;
    const float* src = g_band[bi];
    float acc = sb2[ch];
#pragma unroll
    for (int a = 0; a < 3; a++) {
        int x0 = u + a - 1;
        if ((unsigned)x0 < 96u) {
#pragma unroll
            for (int b2 = 0; b2 < 3; b2++) {
                int y0 = v + b2 - 1;
                if ((unsigned)y0 < 96u) acc += src[y0 * 96 + x0] * sw[ch * 9 + a * 3 + b2];
            }
        }
    }
    g_feat[fi][idx] = acc;
}

__global__ void __launch_bounds__(256) k_dw7(int fi, const float* __restrict__ dww) {
    __shared__ float sw[49];
    __shared__ float spt[484];
    const int ch = blockIdx.z;
    const int ty0 = blockIdx.y * 16, tx0 = blockIdx.x * 16;
    if (threadIdx.x < 49) sw[threadIdx.x] = dww[ch * 49 + threadIdx.x];
    const float* src = g_feat[fi] + ch * SP;
    for (int t = threadIdx.x; t < 484; t += 256) {
        int r = t / 22, c2 = t % 22;
        int gy = ty0 - 6 + r, gx = tx0 - 6 + c2;
        spt[t] = (gy >= 0 && gy < 96 && gx >= 0 && gx < 96) ? src[gy * 96 + gx] : 0.f;
    }
    __syncthreads();
    int ly = threadIdx.x / 16, lx = threadIdx.x % 16;
    int oy = ty0 + ly, ox = tx0 + lx;
    if (oy >= PP || ox >= PP) return;
    float acc = 0.f;
#pragma unroll
    for (int a = 0; a < 7; a++)
#pragma unroll
        for (int b = 0; b < 7; b++)
            acc += spt[(ly + a) * 22 + lx + b] * sw[a * 7 + b];
    g_dwo[ch * SPP + oy * PP + ox] = acc;
}

__global__ void k_zero2() { if (threadIdx.x < 2) g_red[threadIdx.x] = 0.f; }

__global__ void __launch_bounds__(256) k_zeroG() {
    int i = blockIdx.x * 256 + threadIdx.x;
    if (i < 4096) g_G[i] = 0.f;
    if (i < 64) g_s[i] = 0.f;
}

__global__ void __launch_bounds__(256) k_pw(const float* __restrict__ W) {
    __shared__ float swT[64 * 68];
    __shared__ float sin_[4096];
    __shared__ float sr[2][8];
    const int p0 = blockIdx.x * 64;
    for (int t = threadIdx.x; t < 4096; t += 256) {
        int co = t >> 6, ci = t & 63;
        swT[ci * 68 + co] = W[t];
    }
    for (int t = threadIdx.x; t < 4096; t += 256) {
        int ci = t >> 6, p = t & 63; int gp = p0 + p;
        sin_[t] = (gp < SPP) ? g_dwo[ci * SPP + gp] : 0.f;
    }
    __syncthreads();
    const int ocg = threadIdx.x >> 4, pg = threadIdx.x & 15;
    float acc[4][4] = {};
#pragma unroll 4
    for (int ci = 0; ci < 64; ci++) {
        float4 w4 = *(const float4*)&swT[ci * 68 + ocg * 4];
        float4 i4 = *(const float4*)&sin_[ci * 64 + pg * 4];
        acc[0][0] += w4.x * i4.x; acc[0][1] += w4.x * i4.y; acc[0][2] += w4.x * i4.z; acc[0][3] += w4.x * i4.w;
        acc[1][0] += w4.y * i4.x; acc[1][1] += w4.y * i4.y; acc[1][2] += w4.y * i4.z; acc[1][3] += w4.y * i4.w;
        acc[2][0] += w4.z * i4.x; acc[2][1] += w4.z * i4.y; acc[2][2] += w4.z * i4.z; acc[2][3] += w4.z * i4.w;
        acc[3][0] += w4.w * i4.x; acc[3][1] += w4.w * i4.y; acc[3][2] += w4.w * i4.z; acc[3][3] += w4.w * i4.w;
    }
    float ls = 0.f, ls2 = 0.f;
#pragma unroll
    for (int o = 0; o < 4; o++) {
        int oc = ocg * 4 + o;
#pragma unroll
        for (int p = 0; p < 4; p++) {
            int gp = p0 + pg * 4 + p;
            if (gp < SPP) {
                float v = acc[o][p];
                g_pwo[oc * SPP + gp] = v;
                ls += v; ls2 += v * v;
            }
        }
    }
    for (int off = 16; off; off >>= 1) {
        ls += __shfl_down_sync(0xffffffffu, ls, off);
        ls2 += __shfl_down_sync(0xffffffffu, ls2, off);
    }
    if ((threadIdx.x & 31) == 0) { sr[0][threadIdx.x >> 5] = ls; sr[1][threadIdx.x >> 5] = ls2; }
    __syncthreads();
    if (threadIdx.x == 0) {
        float a = 0.f, b = 0.f;
        for (int w2 = 0; w2 < 8; w2++) { a += sr[0][w2]; b += sr[1][w2]; }
        atomicAdd(&g_red[0], a); atomicAdd(&g_red[1], b);
    }
}

__global__ void k_stats() {
    float m = g_red[0] / (float)NLN;
    float v = g_red[1] / (float)NLN - m * m;
    g_stats[0] = m;
    g_stats[1] = rsqrtf(v + 1e-5f);
}

__global__ void __launch_bounds__(256) k_l1(int blk, const float* __restrict__ l1b) {
    __shared__ float s_in[4 * 196];
    __shared__ float s_w[4 * 49 * 32];
    const float m = g_stats[0], inv = g_stats[1];
    const int og = blockIdx.z;
    const int ty0 = blockIdx.y * 8, tx0 = blockIdx.x * 8;
    const int oc_thr = threadIdx.x >> 5, sp_thr = threadIdx.x & 31;
    const int py = sp_thr >> 2, px = (sp_thr & 3) << 1;
    float acc[8] = {};
    const float* wbase = g_l1wT + blk * (64 * 49 * 256) + og * 32;
    for (int ic0 = 0; ic0 < 64; ic0 += 4) {
        __syncthreads();
        for (int t = threadIdx.x; t < 784; t += 256) {
            int ic = t / 196, r2 = t % 196; int rr = r2 / 14, cc = r2 % 14;
            s_in[t] = (g_pwo[(ic0 + ic) * SPP + (ty0 + rr) * PP + (tx0 + cc)] - m) * inv;
        }
        for (int t = threadIdx.x; t < 6272; t += 256) {
            int ick = t >> 5, j = t & 31;
            s_w[t] = wbase[(ic0 * 49 + ick) * 256 + j];
        }
        __syncthreads();
#pragma unroll
        for (int ic = 0; ic < 4; ic++) {
#pragma unroll
            for (int a = 0; a < 7; a++) {
                float r[8];
                const float* rp = &s_in[ic * 196 + (py + a) * 14 + px];
                float2 t0 = *(const float2*)(rp);
                float2 t1 = *(const float2*)(rp + 2);
                float2 t2 = *(const float2*)(rp + 4);
                float2 t3 = *(const float2*)(rp + 6);
                r[0] = t0.x; r[1] = t0.y; r[2] = t1.x; r[3] = t1.y;
                r[4] = t2.x; r[5] = t2.y; r[6] = t3.x; r[7] = t3.y;
                const float* wp = &s_w[(ic * 49 + a * 7) * 32 + (oc_thr << 2)];
#pragma unroll
                for (int b = 0; b < 7; b++) {
                    float4 w4 = *(const float4*)(wp + b * 32);
                    acc[0] += w4.x * r[b]; acc[1] += w4.x * r[b + 1];
                    acc[2] += w4.y * r[b]; acc[3] += w4.y * r[b + 1];
                    acc[4] += w4.z * r[b]; acc[5] += w4.z * r[b + 1];
                    acc[6] += w4.w * r[b]; acc[7] += w4.w * r[b + 1];
                }
            }
        }
    }
    const int u = ty0 + py, v = tx0 + px;
    const int ocb = og * 32 + (oc_thr << 2);
#pragma unroll
    for (int o = 0; o < 4; o++) {
        float bia = l1b[ocb + o];
#pragma unroll
        for (int s2 = 0; s2 < 2; s2++) {
            float x = acc[o * 2 + s2] + bia;
            g_l1o[(ocb + o) * SP + u * 96 + v + s2] =
                0.5f * x * (1.0f + erff(x * 0.70710678118654752f));
        }
    }
}

__global__ void __launch_bounds__(256) k_l2(const float* __restrict__ W, const float* __restrict__ bias,
                                            int r1, int r2, int dst) {
    __shared__ float swT[64 * 68];
    __shared__ float sin_[4096];
    const int p0 = blockIdx.x * 64;
    const int ocg = threadIdx.x >> 4, pg = threadIdx.x & 15;
    float acc[4][4] = {};
    for (int c0 = 0; c0 < 256; c0 += 64) {
        __syncthreads();
        for (int t = threadIdx.x; t < 4096; t += 256) {
            int co = t >> 6, ci = t & 63;
            swT[ci * 68 + co] = W[co * 256 + c0 + ci];
        }
        for (int t = threadIdx.x; t < 4096; t += 256) {
            int ci = t >> 6, p = t & 63;
            sin_[t] = g_l1o[(c0 + ci) * SP + p0 + p];
        }
        __syncthreads();
#pragma unroll 4
        for (int ci = 0; ci < 64; ci++) {
            float4 w4 = *(const float4*)&swT[ci * 68 + ocg * 4];
            float4 i4 = *(const float4*)&sin_[ci * 64 + pg * 4];
            acc[0][0] += w4.x * i4.x; acc[0][1] += w4.x * i4.y; acc[0][2] += w4.x * i4.z; acc[0][3] += w4.x * i4.w;
            acc[1][0] += w4.y * i4.x; acc[1][1] += w4.y * i4.y; acc[1][2] += w4.y * i4.z; acc[1][3] += w4.y * i4.w;
            acc[2][0] += w4.z * i4.x; acc[2][1] += w4.z * i4.y; acc[2][2] += w4.z * i4.z; acc[2][3] += w4.z * i4.w;
            acc[3][0] += w4.w * i4.x; acc[3][1] += w4.w * i4.y; acc[3][2] += w4.w * i4.z; acc[3][3] += w4.w * i4.w;
        }
    }
    float* dstp = g_feat[dst];
    const float* rp1 = g_feat[r1];
    const float* rp2 = (r2 >= 0) ? g_feat[r2] : 0;
#pragma unroll
    for (int o = 0; o < 4; o++) {
        int oc = ocg * 4 + o;
        float bi = bias[oc];
#pragma unroll
        for (int p = 0; p < 4; p++) {
            int idx = oc * SP + p0 + pg * 4 + p;
            float v = acc[o][p] + bi + rp1[idx];
            if (rp2) v += rp2[idx];
            dstp[idx] = v;
        }
    }
}

__global__ void __launch_bounds__(256) k_xg(int fi) {
    __shared__ float sf[1024];
    const float* f = g_feat[fi];
    const int ag = threadIdx.x >> 4, bg = threadIdx.x & 15;
    float acc[4][4] = {};
    float sacc[4] = {};
    const int tok0 = blockIdx.x * 144;
    for (int tb = 0; tb < 144; tb += 16) {
        __syncthreads();
        for (int t2 = threadIdx.x; t2 < 1024; t2 += 256) sf[t2] = f[(tok0 + tb) * 64 + t2];
        __syncthreads();
#pragma unroll
        for (int tk = 0; tk < 16; tk++) {
            float4 fa = *(const float4*)&sf[tk * 64 + ag * 4];
            float4 fb = *(const float4*)&sf[tk * 64 + bg * 4];
            acc[0][0] += fa.x * fb.x; acc[0][1] += fa.x * fb.y; acc[0][2] += fa.x * fb.z; acc[0][3] += fa.x * fb.w;
            acc[1][0] += fa.y * fb.x; acc[1][1] += fa.y * fb.y; acc[1][2] += fa.y * fb.z; acc[1][3] += fa.y * fb.w;
            acc[2][0] += fa.z * fb.x; acc[2][1] += fa.z * fb.y; acc[2][2] += fa.z * fb.z; acc[2][3] += fa.z * fb.w;
            acc[3][0] += fa.w * fb.x; acc[3][1] += fa.w * fb.y; acc[3][2] += fa.w * fb.z; acc[3][3] += fa.w * fb.w;
            if (ag == 0) { sacc[0] += fb.x; sacc[1] += fb.y; sacc[2] += fb.z; sacc[3] += fb.w; }
        }
    }
    for (int i2 = 0; i2 < 4; i2++)
        for (int j2 = 0; j2 < 4; j2++)
            atomicAdd(&g_G[(ag * 4 + i2) * 64 + bg * 4 + j2], acc[i2][j2]);
    if (ag == 0)
        for (int j2 = 0; j2 < 4; j2++) atomicAdd(&g_s[bg * 4 + j2], sacc[j2]);
}

__global__ void __launch_bounds__(256) k_xatt(const float* __restrict__ Qw, const float* __restrict__ Qb,
                                              const float* __restrict__ Kw, const float* __restrict__ Kb,
                                              const float* __restrict__ Vw, const float* __restrict__ Vb,
                                              float scale) {
    __shared__ float sA[4096];
    __shared__ float sGK[4096];
    __shared__ float ss[64], sQs[64], sKs[64];
    const int t = threadIdx.x;
    for (int i = t; i < 4096; i += 256) sA[i] = g_G[i];
    if (t < 64) ss[t] = g_s[t];
    __syncthreads();
    if (t < 64) {
        float q = 0.f;
        for (int a2 = 0; a2 < 64; a2++) q += Qw[t * 64 + a2] * ss[a2];
        sQs[t] = q;
    } else if (t < 128) {
        int d = t - 64; float q = 0.f;
        for (int b2 = 0; b2 < 64; b2++) q += Kw[d * 64 + b2] * ss[b2];
        sKs[d] = q;
    }
    for (int i = t; i < 4096; i += 256) {
        int a2 = i >> 6, d = i & 63;
        float s2 = 0.f;
        for (int b2 = 0; b2 < 64; b2++) s2 += sA[a2 * 64 + b2] * Kw[d * 64 + b2];
        sGK[i] = s2;
    }
    __syncthreads();
    for (int i = t; i < 4096; i += 256) {
        int c = i >> 6, d = i & 63;
        float s2 = Qb[c] * sKs[d] + sQs[c] * Kb[d] + 9216.0f * Qb[c] * Kb[d];
        for (int a2 = 0; a2 < 64; a2++) s2 += Qw[c * 64 + a2] * sGK[a2 * 64 + d];
        sA[i] = s2 * scale;
    }
    __syncthreads();
    if (t < 64) {
        float mx = -1e30f;
        for (int d = 0; d < 64; d++) mx = fmaxf(mx, sA[t * 64 + d]);
        float sm = 0.f;
        for (int d = 0; d < 64; d++) { float e = expf(sA[t * 64 + d] - mx); sA[t * 64 + d] = e; sm += e; }
        float r = 1.0f / sm;
        for (int d = 0; d < 64; d++) sA[t * 64 + d] *= r;
    }
    __syncthreads();
    for (int i = t; i < 4096; i += 256) {
        int a2 = i >> 6, d = i & 63;
        float s2 = 0.f;
        for (int c = 0; c < 64; c++) s2 += Vw[c * 64 + a2] * sA[c * 64 + d];
        g_M[i] = s2;
    }
    if (t < 64) {
        float s2 = 0.f;
        for (int c = 0; c < 64; c++) s2 += Vb[c] * sA[c * 64 + t];
        g_bias[t] = s2;
    }
}

__global__ void __launch_bounds__(256) k_xapply(int fi, int dst) {
    __shared__ float sM[4096];
    __shared__ float sb[64];
    __shared__ float sf[2048];
    for (int t = threadIdx.x; t < 4096; t += 256) sM[t] = g_M[t];
    if (threadIdx.x < 64) sb[threadIdx.x] = g_bias[threadIdx.x];
    const int tok0 = blockIdx.x * 32;
    const float* f = g_feat[fi];
    for (int t = threadIdx.x; t < 2048; t += 256) sf[t] = f[tok0 * 64 + t];
    __syncthreads();
    const int tk = threadIdx.x >> 3, dg = threadIdx.x & 7;
    float acc[8] = {};
#pragma unroll 8
    for (int a2 = 0; a2 < 64; a2++) {
        float fa = sf[tk * 64 + a2];
        float4 m0 = *(const float4*)&sM[a2 * 64 + dg * 8];
        float4 m1 = *(const float4*)&sM[a2 * 64 + dg * 8 + 4];
        acc[0] += fa * m0.x; acc[1] += fa * m0.y; acc[2] += fa * m0.z; acc[3] += fa * m0.w;
        acc[4] += fa * m1.x; acc[5] += fa * m1.y; acc[6] += fa * m1.z; acc[7] += fa * m1.w;
    }
    float* dp = g_feat[dst];
    const int base = (tok0 + tk) * 64 + dg * 8;
#pragma unroll
    for (int d2 = 0; d2 < 8; d2++) dp[base + d2] = sf[tk * 64 + dg * 8 + d2] + acc[d2] + sb[dg * 8 + d2];
}

__global__ void __launch_bounds__(256) k_op(int fi, int oi, const float* __restrict__ w,
                                            const float* __restrict__ bb) {
    __shared__ float sw[576];
    for (int t = threadIdx.x; t < 576; t += 256) {
        int ch = t / 9, k2 = t % 9; int a = k2 / 3, b2 = k2 % 3;
        sw[t] = w[ch * 9 + (2 - a) * 3 + (2 - b2)];
    }
    __syncthreads();
    int idx = blockIdx.x * 256 + threadIdx.x;
    if (idx >= SP) return;
    int u = idx / 96, v = idx % 96;
    const float* x = g_feat[fi];
    float acc = bb[0];
    for (int ch = 0; ch < 64; ch++) {
#pragma unroll
        for (int a = 0; a < 3; a++) {
            int y = u + a - 1; if ((unsigned)y >= 96u) continue;
#pragma unroll
            for (int b2 = 0; b2 < 3; b2++) {
                int xx = v + b2 - 1; if ((unsigned)xx >= 96u) continue;
                acc += x[ch * SP + y * 96 + xx] * sw[ch * 9 + a * 3 + b2];
            }
        }
    }
    g_opout[oi][v * 96 + u] = acc;
}

__global__ void __launch_bounds__(256) k_idwt(const float* __restrict__ img, float* __restrict__ out) {
    int idx = blockIdx.x * 256 + threadIdx.x;
    if (idx >= SP) return;
    int i = idx / 96, j = idx % 96;
    float a = g_opout[0][idx], b = g_opout[1][idx], c = g_opout[2][idx], d = g_opout[3][idx];
    int r0 = (2 * i) * 192 + 2 * j;
    int r1 = (2 * i + 1) * 192 + 2 * j;
    out[r0]     = 0.5f * (a + b + c + d) + img[r0];
    out[r0 + 1] = 0.5f * (a - b + c - d) + img[r0 + 1];
    out[r1]     = 0.5f * (a + b - c - d) + img[r1];
    out[r1 + 1] = 0.5f * (a - b - c + d) + img[r1 + 1];
}

extern "C" void kernel_launch(void* const* d_in, const int* in_sizes, int n_in,
                              void* d_out, int out_size) {
    (void)in_sizes; (void)n_in; (void)out_size;
    const float* images = (const float*)d_in[0];
    const float* ip_w  = (const float*)d_in[1];
    const float* ip_b  = (const float*)d_in[2];
    const float* op_w  = (const float*)d_in[3];
    const float* op_b  = (const float*)d_in[4];
    const float* cb_dw = (const float*)d_in[5];
    const float* cb_pw = (const float*)d_in[6];
    const float* cb_l1w = (const float*)d_in[7];
    const float* cb_l1b = (const float*)d_in[8];
    const float* cb_l2w = (const float*)d_in[9];
    const float* cb_l2b = (const float*)d_in[10];
    const float* xqw = (const float*)d_in[11];
    const float* xqb = (const float*)d_in[12];
    const float* xkw = (const float*)d_in[13];
    const float* xkb = (const float*)d_in[14];
    const float* xvw = (const float*)d_in[15];
    const float* xvb = (const float*)d_in[16];
    float* out = (float*)d_out;

    k_dwt<<<36, 256>>>(images);
    k_l1wt<<<(6 * 256 * 64 * 49 + 255) / 256, 256>>>(cb_l1w);

    auto cb = [&](int blk, int src, int r2, int dst) {
        k_dw7<<<dim3(7, 7, 64), 256>>>(src, cb_dw + blk * 3136);
        k_zero2<<<1, 32>>>();
        k_pw<<<163, 256>>>(cb_pw + blk * 4096);
        k_stats<<<1, 1>>>();
        k_l1<<<dim3(12, 12, 8), 256>>>(blk, cb_l1b + blk * 256);
        k_l2<<<144, 256>>>(cb_l2w + blk * 16384, cb_l2b + blk * 64, src, r2, dst);
    };
    auto xb = [&](int i, int src, int dst, float scale) {
        k_zeroG<<<16, 256>>>();
        k_xg<<<64, 256>>>(src);
        k_xatt<<<1, 256>>>(xqw + i * 4096, xqb + i * 64, xkw + i * 4096, xkb + i * 64,
                           xvw + i * 4096, xvb + i * 64, scale);
        k_xapply<<<288, 256>>>(src, dst);
    };

    k_ip<<<2304, 256>>>(0, 0, ip_w, ip_b);
    cb(0, 0, -1, 1);                       // c1 -> feat1
    cb(1, 1, 1, 2);                        // c2 = cb(c1)+c1 -> feat2
    xb(0, 1, 3, 0.44721359549995793f);     // xlow -> feat3
    cb(2, 3, 2, 4);                        // c3 = cb(xlow)+c2 -> feat4
    cb(3, 4, 1, 5);                        // c4 = cb(c3)+c1 -> feat5
    k_op<<<36, 256>>>(5, 0, op_w, op_b);

    for (int bi = 1; bi <= 3; bi++) {
        k_ip<<<2304, 256>>>(bi, 6, ip_w, ip_b);
        cb(4, 6, -1, 7);                   // h1 -> feat7
        xb(1, 7, 3, 0.70710678118654752f); // hx -> feat3
        cb(5, 3, 7, 4);                    // h2 = cb(hx)+h1 -> feat4
        k_op<<<36, 256>>>(4, bi, op_w, op_b);
    }
    k_idwt<<<36, 256>>>(images, out);
}

// round 3
// speedup vs baseline: 1.0072x; 1.0072x over previous
#include <cuda_runtime.h>
#include <math.h>

#define CC 64
#define SP 9216
#define PP 102
#define SPP 10404
#define NLN 665856

typedef unsigned long long ull;

__device__ __forceinline__ void ffma2(ull &d, ull a, ull b) {
    asm("fma.rn.f32x2 %0, %1, %2, %0;" : "+l"(d) : "l"(a), "l"(b));
}
__device__ __forceinline__ ull bcast2(float x) {
    ull r;
    asm("mov.b64 %0, {%1, %1};" : "=l"(r) : "f"(x));
    return r;
}
__device__ __forceinline__ float2 unpack2(ull v) {
    float2 f;
    asm("mov.b64 {%0, %1}, %2;" : "=f"(f.x), "=f"(f.y) : "l"(v));
    return f;
}

__device__ float g_band[4][SP];
__device__ float g_opout[4][SP];
__device__ float g_feat[8][CC * SP];
__device__ float g_dwo[CC * SPP];
__device__ float g_pwo[CC * SPP];
__device__ float g_l1o[4 * CC * SP];
__device__ float g_l1wT[6 * CC * 49 * 256];
__device__ float g_red[2];
__device__ float g_stats[2];
__device__ float g_G[4096];
__device__ float g_s[64];
__device__ float g_M[4096];
__device__ float g_bias[64];

__global__ void __launch_bounds__(256) k_dwt(const float* __restrict__ img) {
    int idx = blockIdx.x * 256 + threadIdx.x;
    if (idx >= SP) return;
    int i = idx / 96, j = idx % 96;
    float a = img[(2 * i) * 192 + 2 * j];
    float b = img[(2 * i + 1) * 192 + 2 * j];
    float c = img[(2 * i) * 192 + 2 * j + 1];
    float d = img[(2 * i + 1) * 192 + 2 * j + 1];
    g_band[0][idx] = (a + b + c + d) * 0.5f;
    g_band[1][idx] = (a + b - c - d) * 0.5f;
    g_band[2][idx] = (a - b + c - d) * 0.5f;
    g_band[3][idx] = (a - b - c + d) * 0.5f;
}

__global__ void __launch_bounds__(256) k_l1wt(const float* __restrict__ w) {
    int idx = blockIdx.x * 256 + threadIdx.x;
    if (idx >= 6 * 256 * 64 * 49) return;
    int k = idx % 49; int t = idx / 49;
    int ic = t % 64; t /= 64;
    int oc = t % 256; int blk = t / 256;
    g_l1wT[blk * (64 * 49 * 256) + (ic * 49 + k) * 256 + oc] = w[idx];
}

__global__ void __launch_bounds__(256) k_ip(int bi, int fi, const float* __restrict__ w,
                                            const float* __restrict__ bb) {
    __shared__ float sw[576];
    __shared__ float sb2[64];
    for (int t = threadIdx.x; t < 576; t += 256) sw[t] = w[t];
    if (threadIdx.x < 64) sb2[threadIdx.x] = bb[threadIdx.x];
    __syncthreads();
    int idx = blockIdx.x * 256 + threadIdx.x;
    if (idx >= CC * SP) return;
    int v = idx % 96; int u = (idx / 96) % 96; int ch = idx / SP;
    const float* src = g_band[bi];
    float acc = sb2[ch];
#pragma unroll
    for (int a = 0; a < 3; a++) {
        int x0 = u + a - 1;
        if ((unsigned)x0 < 96u) {
#pragma unroll
            for (int b2 = 0; b2 < 3; b2++) {
                int y0 = v + b2 - 1;
                if ((unsigned)y0 < 96u) acc += src[y0 * 96 + x0] * sw[ch * 9 + a * 3 + b2];
            }
        }
    }
    g_feat[fi][idx] = acc;
}

__global__ void __launch_bounds__(256) k_dw7(int fi, const float* __restrict__ dww) {
    __shared__ float sw[49];
    __shared__ float spt[484];
    const int ch = blockIdx.z;
    const int ty0 = blockIdx.y * 16, tx0 = blockIdx.x * 16;
    if (threadIdx.x < 49) sw[threadIdx.x] = dww[ch * 49 + threadIdx.x];
    const float* src = g_feat[fi] + ch * SP;
    for (int t = threadIdx.x; t < 484; t += 256) {
        int r = t / 22, c2 = t % 22;
        int gy = ty0 - 6 + r, gx = tx0 - 6 + c2;
        spt[t] = (gy >= 0 && gy < 96 && gx >= 0 && gx < 96) ? src[gy * 96 + gx] : 0.f;
    }
    __syncthreads();
    int ly = threadIdx.x / 16, lx = threadIdx.x % 16;
    int oy = ty0 + ly, ox = tx0 + lx;
    if (oy >= PP || ox >= PP) return;
    float acc = 0.f;
#pragma unroll
    for (int a = 0; a < 7; a++)
#pragma unroll
        for (int b = 0; b < 7; b++)
            acc += spt[(ly + a) * 22 + lx + b] * sw[a * 7 + b];
    g_dwo[ch * SPP + oy * PP + ox] = acc;
}

__global__ void k_zero2() { if (threadIdx.x < 2) g_red[threadIdx.x] = 0.f; }

__global__ void __launch_bounds__(256) k_zeroG() {
    int i = blockIdx.x * 256 + threadIdx.x;
    if (i < 4096) g_G[i] = 0.f;
    if (i < 64) g_s[i] = 0.f;
}

__global__ void __launch_bounds__(256) k_pw(const float* __restrict__ W) {
    __shared__ float swT[64 * 68];
    __shared__ float sin_[4096];
    __shared__ float sr[2][8];
    const int p0 = blockIdx.x * 64;
    for (int t = threadIdx.x; t < 4096; t += 256) {
        int co = t >> 6, ci = t & 63;
        swT[ci * 68 + co] = W[t];
    }
    for (int t = threadIdx.x; t < 4096; t += 256) {
        int ci = t >> 6, p = t & 63; int gp = p0 + p;
        sin_[t] = (gp < SPP) ? g_dwo[ci * SPP + gp] : 0.f;
    }
    __syncthreads();
    const int ocg = threadIdx.x >> 4, pg = threadIdx.x & 15;
    float acc[4][4] = {};
#pragma unroll 4
    for (int ci = 0; ci < 64; ci++) {
        float4 w4 = *(const float4*)&swT[ci * 68 + ocg * 4];
        float4 i4 = *(const float4*)&sin_[ci * 64 + pg * 4];
        acc[0][0] += w4.x * i4.x; acc[0][1] += w4.x * i4.y; acc[0][2] += w4.x * i4.z; acc[0][3] += w4.x * i4.w;
        acc[1][0] += w4.y * i4.x; acc[1][1] += w4.y * i4.y; acc[1][2] += w4.y * i4.z; acc[1][3] += w4.y * i4.w;
        acc[2][0] += w4.z * i4.x; acc[2][1] += w4.z * i4.y; acc[2][2] += w4.z * i4.z; acc[2][3] += w4.z * i4.w;
        acc[3][0] += w4.w * i4.x; acc[3][1] += w4.w * i4.y; acc[3][2] += w4.w * i4.z; acc[3][3] += w4.w * i4.w;
    }
    float ls = 0.f, ls2 = 0.f;
#pragma unroll
    for (int o = 0; o < 4; o++) {
        int oc = ocg * 4 + o;
#pragma unroll
        for (int p = 0; p < 4; p++) {
            int gp = p0 + pg * 4 + p;
            if (gp < SPP) {
                float v = acc[o][p];
                g_pwo[oc * SPP + gp] = v;
                ls += v; ls2 += v * v;
            }
        }
    }
    for (int off = 16; off; off >>= 1) {
        ls += __shfl_down_sync(0xffffffffu, ls, off);
        ls2 += __shfl_down_sync(0xffffffffu, ls2, off);
    }
    if ((threadIdx.x & 31) == 0) { sr[0][threadIdx.x >> 5] = ls; sr[1][threadIdx.x >> 5] = ls2; }
    __syncthreads();
    if (threadIdx.x == 0) {
        float a = 0.f, b = 0.f;
        for (int w2 = 0; w2 < 8; w2++) { a += sr[0][w2]; b += sr[1][w2]; }
        atomicAdd(&g_red[0], a); atomicAdd(&g_red[1], b);
    }
}

__global__ void k_stats() {
    float m = g_red[0] / (float)NLN;
    float v = g_red[1] / (float)NLN - m * m;
    g_stats[0] = m;
    g_stats[1] = rsqrtf(v + 1e-5f);
}

__global__ void __launch_bounds__(256) k_l1(int blk, const float* __restrict__ l1b) {
    __shared__ float s_in[4 * 196];
    __shared__ float s_w[4 * 49 * 32];
    const float m = g_stats[0], inv = g_stats[1];
    const int og = blockIdx.z;
    const int ty0 = blockIdx.y * 8, tx0 = blockIdx.x * 8;
    const int oc_thr = threadIdx.x >> 5, sp_thr = threadIdx.x & 31;
    const int py = sp_thr >> 2, px = (sp_thr & 3) << 1;
    // acc2[0]=(oc0,oc1)@px0  acc2[1]=(oc0,oc1)@px1  acc2[2]=(oc2,oc3)@px0  acc2[3]=(oc2,oc3)@px1
    ull acc2[4] = {0ull, 0ull, 0ull, 0ull};
    const float* wbase = g_l1wT + blk * (64 * 49 * 256) + og * 32;
    for (int ic0 = 0; ic0 < 64; ic0 += 4) {
        __syncthreads();
        for (int t = threadIdx.x; t < 784; t += 256) {
            int ic = t / 196, r2 = t % 196; int rr = r2 / 14, cc = r2 % 14;
            s_in[t] = (g_pwo[(ic0 + ic) * SPP + (ty0 + rr) * PP + (tx0 + cc)] - m) * inv;
        }
        for (int t = threadIdx.x; t < 6272; t += 256) {
            int ick = t >> 5, j = t & 31;
            s_w[t] = wbase[(ic0 * 49 + ick) * 256 + j];
        }
        __syncthreads();
#pragma unroll
        for (int ic = 0; ic < 4; ic++) {
#pragma unroll
            for (int a = 0; a < 7; a++) {
                const float* rp = &s_in[ic * 196 + (py + a) * 14 + px];
                float2 t0 = *(const float2*)(rp);
                float2 t1 = *(const float2*)(rp + 2);
                float2 t2 = *(const float2*)(rp + 4);
                float2 t3 = *(const float2*)(rp + 6);
                ull rr[8];
                rr[0] = bcast2(t0.x); rr[1] = bcast2(t0.y);
                rr[2] = bcast2(t1.x); rr[3] = bcast2(t1.y);
                rr[4] = bcast2(t2.x); rr[5] = bcast2(t2.y);
                rr[6] = bcast2(t3.x); rr[7] = bcast2(t3.y);
                const float* wp = &s_w[(ic * 49 + a * 7) * 32 + (oc_thr << 2)];
#pragma unroll
                for (int b = 0; b < 7; b++) {
                    const ull* w2p = (const ull*)(wp + b * 32);
                    ull w01 = w2p[0];
                    ull w23 = w2p[1];
                    ffma2(acc2[0], w01, rr[b]);
                    ffma2(acc2[1], w01, rr[b + 1]);
                    ffma2(acc2[2], w23, rr[b]);
                    ffma2(acc2[3], w23, rr[b + 1]);
                }
            }
        }
    }
    float2 a00 = unpack2(acc2[0]);  // (oc0@px0, oc1@px0)
    float2 a01 = unpack2(acc2[1]);  // (oc0@px1, oc1@px1)
    float2 a10 = unpack2(acc2[2]);
    float2 a11 = unpack2(acc2[3]);
    float accf[8] = {a00.x, a01.x, a00.y, a01.y, a10.x, a11.x, a10.y, a11.y};
    const int u = ty0 + py, v = tx0 + px;
    const int ocb = og * 32 + (oc_thr << 2);
#pragma unroll
    for (int o = 0; o < 4; o++) {
        float bia = l1b[ocb + o];
#pragma unroll
        for (int s2 = 0; s2 < 2; s2++) {
            float x = accf[o * 2 + s2] + bia;
            g_l1o[(ocb + o) * SP + u * 96 + v + s2] =
                0.5f * x * (1.0f + erff(x * 0.70710678118654752f));
        }
    }
}

__global__ void __launch_bounds__(256) k_l2(const float* __restrict__ W, const float* __restrict__ bias,
                                            int r1, int r2, int dst) {
    __shared__ float swT[64 * 68];
    __shared__ float sin_[4096];
    const int p0 = blockIdx.x * 64;
    const int ocg = threadIdx.x >> 4, pg = threadIdx.x & 15;
    float acc[4][4] = {};
    for (int c0 = 0; c0 < 256; c0 += 64) {
        __syncthreads();
        for (int t = threadIdx.x; t < 4096; t += 256) {
            int co = t >> 6, ci = t & 63;
            swT[ci * 68 + co] = W[co * 256 + c0 + ci];
        }
        for (int t = threadIdx.x; t < 4096; t += 256) {
            int ci = t >> 6, p = t & 63;
            sin_[t] = g_l1o[(c0 + ci) * SP + p0 + p];
        }
        __syncthreads();
#pragma unroll 4
        for (int ci = 0; ci < 64; ci++) {
            float4 w4 = *(const float4*)&swT[ci * 68 + ocg * 4];
            float4 i4 = *(const float4*)&sin_[ci * 64 + pg * 4];
            acc[0][0] += w4.x * i4.x; acc[0][1] += w4.x * i4.y; acc[0][2] += w4.x * i4.z; acc[0][3] += w4.x * i4.w;
            acc[1][0] += w4.y * i4.x; acc[1][1] += w4.y * i4.y; acc[1][2] += w4.y * i4.z; acc[1][3] += w4.y * i4.w;
            acc[2][0] += w4.z * i4.x; acc[2][1] += w4.z * i4.y; acc[2][2] += w4.z * i4.z; acc[2][3] += w4.z * i4.w;
            acc[3][0] += w4.w * i4.x; acc[3][1] += w4.w * i4.y; acc[3][2] += w4.w * i4.z; acc[3][3] += w4.w * i4.w;
        }
    }
    float* dstp = g_feat[dst];
    const float* rp1 = g_feat[r1];
    const float* rp2 = (r2 >= 0) ? g_feat[r2] : 0;
#pragma unroll
    for (int o = 0; o < 4; o++) {
        int oc = ocg * 4 + o;
        float bi = bias[oc];
#pragma unroll
        for (int p = 0; p < 4; p++) {
            int idx = oc * SP + p0 + pg * 4 + p;
            float v = acc[o][p] + bi + rp1[idx];
            if (rp2) v += rp2[idx];
            dstp[idx] = v;
        }
    }
}

__global__ void __launch_bounds__(256) k_xg(int fi) {
    __shared__ float sf[1024];
    const float* f = g_feat[fi];
    const int ag = threadIdx.x >> 4, bg = threadIdx.x & 15;
    float acc[4][4] = {};
    float sacc[4] = {};
    const int tok0 = blockIdx.x * 144;
    for (int tb = 0; tb < 144; tb += 16) {
        __syncthreads();
        for (int t2 = threadIdx.x; t2 < 1024; t2 += 256) sf[t2] = f[(tok0 + tb) * 64 + t2];
        __syncthreads();
#pragma unroll
        for (int tk = 0; tk < 16; tk++) {
            float4 fa = *(const float4*)&sf[tk * 64 + ag * 4];
            float4 fb = *(const float4*)&sf[tk * 64 + bg * 4];
            acc[0][0] += fa.x * fb.x; acc[0][1] += fa.x * fb.y; acc[0][2] += fa.x * fb.z; acc[0][3] += fa.x * fb.w;
            acc[1][0] += fa.y * fb.x; acc[1][1] += fa.y * fb.y; acc[1][2] += fa.y * fb.z; acc[1][3] += fa.y * fb.w;
            acc[2][0] += fa.z * fb.x; acc[2][1] += fa.z * fb.y; acc[2][2] += fa.z * fb.z; acc[2][3] += fa.z * fb.w;
            acc[3][0] += fa.w * fb.x; acc[3][1] += fa.w * fb.y; acc[3][2] += fa.w * fb.z; acc[3][3] += fa.w * fb.w;
            if (ag == 0) { sacc[0] += fb.x; sacc[1] += fb.y; sacc[2] += fb.z; sacc[3] += fb.w; }
        }
    }
    for (int i2 = 0; i2 < 4; i2++)
        for (int j2 = 0; j2 < 4; j2++)
            atomicAdd(&g_G[(ag * 4 + i2) * 64 + bg * 4 + j2], acc[i2][j2]);
    if (ag == 0)
        for (int j2 = 0; j2 < 4; j2++) atomicAdd(&g_s[bg * 4 + j2], sacc[j2]);
}

__global__ void __launch_bounds__(256) k_xatt(const float* __restrict__ Qw, const float* __restrict__ Qb,
                                              const float* __restrict__ Kw, const float* __restrict__ Kb,
                                              const float* __restrict__ Vw, const float* __restrict__ Vb,
                                              float scale) {
    __shared__ float sA[4096];
    __shared__ float sGK[4096];
    __shared__ float ss[64], sQs[64], sKs[64];
    const int t = threadIdx.x;
    for (int i = t; i < 4096; i += 256) sA[i] = g_G[i];
    if (t < 64) ss[t] = g_s[t];
    __syncthreads();
    if (t < 64) {
        float q = 0.f;
        for (int a2 = 0; a2 < 64; a2++) q += Qw[t * 64 + a2] * ss[a2];
        sQs[t] = q;
    } else if (t < 128) {
        int d = t - 64; float q = 0.f;
        for (int b2 = 0; b2 < 64; b2++) q += Kw[d * 64 + b2] * ss[b2];
        sKs[d] = q;
    }
    for (int i = t; i < 4096; i += 256) {
        int a2 = i >> 6, d = i & 63;
        float s2 = 0.f;
        for (int b2 = 0; b2 < 64; b2++) s2 += sA[a2 * 64 + b2] * Kw[d * 64 + b2];
        sGK[i] = s2;
    }
    __syncthreads();
    for (int i = t; i < 4096; i += 256) {
        int c = i >> 6, d = i & 63;
        float s2 = Qb[c] * sKs[d] + sQs[c] * Kb[d] + 9216.0f * Qb[c] * Kb[d];
        for (int a2 = 0; a2 < 64; a2++) s2 += Qw[c * 64 + a2] * sGK[a2 * 64 + d];
        sA[i] = s2 * scale;
    }
    __syncthreads();
    if (t < 64) {
        float mx = -1e30f;
        for (int d = 0; d < 64; d++) mx = fmaxf(mx, sA[t * 64 + d]);
        float sm = 0.f;
        for (int d = 0; d < 64; d++) { float e = expf(sA[t * 64 + d] - mx); sA[t * 64 + d] = e; sm += e; }
        float r = 1.0f / sm;
        for (int d = 0; d < 64; d++) sA[t * 64 + d] *= r;
    }
    __syncthreads();
    for (int i = t; i < 4096; i += 256) {
        int a2 = i >> 6, d = i & 63;
        float s2 = 0.f;
        for (int c = 0; c < 64; c++) s2 += Vw[c * 64 + a2] * sA[c * 64 + d];
        g_M[i] = s2;
    }
    if (t < 64) {
        float s2 = 0.f;
        for (int c = 0; c < 64; c++) s2 += Vb[c] * sA[c * 64 + t];
        g_bias[t] = s2;
    }
}

__global__ void __launch_bounds__(256) k_xapply(int fi, int dst) {
    __shared__ float sM[4096];
    __shared__ float sb[64];
    __shared__ float sf[2048];
    for (int t = threadIdx.x; t < 4096; t += 256) sM[t] = g_M[t];
    if (threadIdx.x < 64) sb[threadIdx.x] = g_bias[threadIdx.x];
    const int tok0 = blockIdx.x * 32;
    const float* f = g_feat[fi];
    for (int t = threadIdx.x; t < 2048; t += 256) sf[t] = f[tok0 * 64 + t];
    __syncthreads();
    const int tk = threadIdx.x >> 3, dg = threadIdx.x & 7;
    float acc[8] = {};
#pragma unroll 8
    for (int a2 = 0; a2 < 64; a2++) {
        float fa = sf[tk * 64 + a2];
        float4 m0 = *(const float4*)&sM[a2 * 64 + dg * 8];
        float4 m1 = *(const float4*)&sM[a2 * 64 + dg * 8 + 4];
        acc[0] += fa * m0.x; acc[1] += fa * m0.y; acc[2] += fa * m0.z; acc[3] += fa * m0.w;
        acc[4] += fa * m1.x; acc[5] += fa * m1.y; acc[6] += fa * m1.z; acc[7] += fa * m1.w;
    }
    float* dp = g_feat[dst];
    const int base = (tok0 + tk) * 64 + dg * 8;
#pragma unroll
    for (int d2 = 0; d2 < 8; d2++) dp[base + d2] = sf[tk * 64 + dg * 8 + d2] + acc[d2] + sb[dg * 8 + d2];
}

__global__ void __launch_bounds__(256) k_op(int fi, int oi, const float* __restrict__ w,
                                            const float* __restrict__ bb) {
    __shared__ float sw[576];
    for (int t = threadIdx.x; t < 576; t += 256) {
        int ch = t / 9, k2 = t % 9; int a = k2 / 3, b2 = k2 % 3;
        sw[t] = w[ch * 9 + (2 - a) * 3 + (2 - b2)];
    }
    __syncthreads();
    int idx = blockIdx.x * 256 + threadIdx.x;
    if (idx >= SP) return;
    int u = idx / 96, v = idx % 96;
    const float* x = g_feat[fi];
    float acc = bb[0];
    for (int ch = 0; ch < 64; ch++) {
#pragma unroll
        for (int a = 0; a < 3; a++) {
            int y = u + a - 1; if ((unsigned)y >= 96u) continue;
#pragma unroll
            for (int b2 = 0; b2 < 3; b2++) {
                int xx = v + b2 - 1; if ((unsigned)xx >= 96u) continue;
                acc += x[ch * SP + y * 96 + xx] * sw[ch * 9 + a * 3 + b2];
            }
        }
    }
    g_opout[oi][v * 96 + u] = acc;
}

__global__ void __launch_bounds__(256) k_idwt(const float* __restrict__ img, float* __restrict__ out) {
    int idx = blockIdx.x * 256 + threadIdx.x;
    if (idx >= SP) return;
    int i = idx / 96, j = idx % 96;
    float a = g_opout[0][idx], b = g_opout[1][idx], c = g_opout[2][idx], d = g_opout[3][idx];
    int r0 = (2 * i) * 192 + 2 * j;
    int r1 = (2 * i + 1) * 192 + 2 * j;
    out[r0]     = 0.5f * (a + b + c + d) + img[r0];
    out[r0 + 1] = 0.5f * (a - b + c - d) + img[r0 + 1];
    out[r1]     = 0.5f * (a + b - c - d) + img[r1];
    out[r1 + 1] = 0.5f * (a - b - c + d) + img[r1 + 1];
}

extern "C" void kernel_launch(void* const* d_in, const int* in_sizes, int n_in,
                              void* d_out, int out_size) {
    (void)in_sizes; (void)n_in; (void)out_size;
    const float* images = (const float*)d_in[0];
    const float* ip_w  = (const float*)d_in[1];
    const float* ip_b  = (const float*)d_in[2];
    const float* op_w  = (const float*)d_in[3];
    const float* op_b  = (const float*)d_in[4];
    const float* cb_dw = (const float*)d_in[5];
    const float* cb_pw = (const float*)d_in[6];
    const float* cb_l1w = (const float*)d_in[7];
    const float* cb_l1b = (const float*)d_in[8];
    const float* cb_l2w = (const float*)d_in[9];
    const float* cb_l2b = (const float*)d_in[10];
    const float* xqw = (const float*)d_in[11];
    const float* xqb = (const float*)d_in[12];
    const float* xkw = (const float*)d_in[13];
    const float* xkb = (const float*)d_in[14];
    const float* xvw = (const float*)d_in[15];
    const float* xvb = (const float*)d_in[16];
    float* out = (float*)d_out;

    k_dwt<<<36, 256>>>(images);
    k_l1wt<<<(6 * 256 * 64 * 49 + 255) / 256, 256>>>(cb_l1w);

    auto cb = [&](int blk, int src, int r2, int dst) {
        k_dw7<<<dim3(7, 7, 64), 256>>>(src, cb_dw + blk * 3136);
        k_zero2<<<1, 32>>>();
        k_pw<<<163, 256>>>(cb_pw + blk * 4096);
        k_stats<<<1, 1>>>();
        k_l1<<<dim3(12, 12, 8), 256>>>(blk, cb_l1b + blk * 256);
        k_l2<<<144, 256>>>(cb_l2w + blk * 16384, cb_l2b + blk * 64, src, r2, dst);
    };
    auto xb = [&](int i, int src, int dst, float scale) {
        k_zeroG<<<16, 256>>>();
        k_xg<<<64, 256>>>(src);
        k_xatt<<<1, 256>>>(xqw + i * 4096, xqb + i * 64, xkw + i * 4096, xkb + i * 64,
                           xvw + i * 4096, xvb + i * 64, scale);
        k_xapply<<<288, 256>>>(src, dst);
    };

    k_ip<<<2304, 256>>>(0, 0, ip_w, ip_b);
    cb(0, 0, -1, 1);
    cb(1, 1, 1, 2);
    xb(0, 1, 3, 0.44721359549995793f);
    cb(2, 3, 2, 4);
    cb(3, 4, 1, 5);
    k_op<<<36, 256>>>(5, 0, op_w, op_b);

    for (int bi = 1; bi <= 3; bi++) {
        k_ip<<<2304, 256>>>(bi, 6, ip_w, ip_b);
        cb(4, 6, -1, 7);
        xb(1, 7, 3, 0.70710678118654752f);
        cb(5, 3, 7, 4);
        k_op<<<36, 256>>>(4, bi, op_w, op_b);
    }
    k_idwt<<<36, 256>>>(images, out);
}

// round 5
// speedup vs baseline: 2.2012x; 2.1855x over previous
#include <cuda_runtime.h>
#include <math.h>
#include <stdint.h>

#define CC 64
#define SP 9216
#define PP 102
#define SPP 10404
#define NLN 665856

// ---------------- scratch ----------------
__device__ float g_band[4][SP];
__device__ float g_opout[4][SP];
__device__ float g_feat[8][CC * SP];
__device__ float g_dwo[CC * SPP];
__device__ float g_pwo[CC * SPP];
__device__ float g_l1o[4 * CC * SP];
// prepacked l1 weights: [blk][ic 64][a 7][oc 256][j 4][2] ; elem = w[b=j + e*4], b==7 -> 0, tf32-rounded
__device__ float g_l1wT2[6 * 64 * 7 * 256 * 8];
__device__ float g_red[2];
__device__ float g_stats[2];
__device__ float g_G[4096];
__device__ float g_s[64];
__device__ float g_M[4096];
__device__ float g_bias[64];

__device__ __forceinline__ uint32_t f2tf32(float x) {
    uint32_t r;
    asm("cvt.rna.tf32.f32 %0, %1;" : "=r"(r) : "f"(x));
    return r;
}
__device__ __forceinline__ void mma8(float* c, const uint32_t* a, uint32_t b0, uint32_t b1) {
    asm volatile(
        "mma.sync.aligned.m16n8k8.row.col.f32.tf32.tf32.f32 "
        "{%0,%1,%2,%3}, {%4,%5,%6,%7}, {%8,%9}, {%0,%1,%2,%3};"
        : "+f"(c[0]), "+f"(c[1]), "+f"(c[2]), "+f"(c[3])
        : "r"(a[0]), "r"(a[1]), "r"(a[2]), "r"(a[3]), "r"(b0), "r"(b1));
}
__device__ __forceinline__ float gelu(float x) {
    return 0.5f * x * (1.0f + erff(x * 0.70710678118654752f));
}

__global__ void __launch_bounds__(256) k_dwt(const float* __restrict__ img) {
    int idx = blockIdx.x * 256 + threadIdx.x;
    if (idx >= SP) return;
    int i = idx / 96, j = idx % 96;
    float a = img[(2 * i) * 192 + 2 * j];
    float b = img[(2 * i + 1) * 192 + 2 * j];
    float c = img[(2 * i) * 192 + 2 * j + 1];
    float d = img[(2 * i + 1) * 192 + 2 * j + 1];
    g_band[0][idx] = (a + b + c + d) * 0.5f;
    g_band[1][idx] = (a + b - c - d) * 0.5f;
    g_band[2][idx] = (a - b + c - d) * 0.5f;
    g_band[3][idx] = (a - b - c + d) * 0.5f;
}

// prepack l1 weights with tf32 rounding + b=7 zero pad
__global__ void __launch_bounds__(256) k_l1wt2(const float* __restrict__ w) {
    int idx = blockIdx.x * 256 + threadIdx.x;
    const int total = 6 * 64 * 7 * 256 * 8;
    if (idx >= total) return;
    int t = idx;
    int e = t & 1; t >>= 1;
    int j = t & 3; t >>= 2;
    int oc = t & 255; t >>= 8;
    int a = t % 7; t /= 7;
    int ic = t % 64;
    int blk = t / 64;
    int b = j + e * 4;
    float v = 0.f;
    if (b < 7) v = w[((blk * 256 + oc) * 64 + ic) * 49 + a * 7 + b];
    g_l1wT2[idx] = __uint_as_float(f2tf32(v));
}

__global__ void __launch_bounds__(256) k_ip(int bi, int fi, const float* __restrict__ w,
                                            const float* __restrict__ bb) {
    __shared__ float sw[576];
    __shared__ float sb2[64];
    for (int t = threadIdx.x; t < 576; t += 256) sw[t] = w[t];
    if (threadIdx.x < 64) sb2[threadIdx.x] = bb[threadIdx.x];
    __syncthreads();
    int idx = blockIdx.x * 256 + threadIdx.x;
    if (idx >= CC * SP) return;
    int v = idx % 96; int u = (idx / 96) % 96; int ch = idx / SP;
    const float* src = g_band[bi];
    float acc = sb2[ch];
#pragma unroll
    for (int a = 0; a < 3; a++) {
        int x0 = u + a - 1;
        if ((unsigned)x0 < 96u) {
#pragma unroll
            for (int b2 = 0; b2 < 3; b2++) {
                int y0 = v + b2 - 1;
                if ((unsigned)y0 < 96u) acc += src[y0 * 96 + x0] * sw[ch * 9 + a * 3 + b2];
            }
        }
    }
    g_feat[fi][idx] = acc;
}

__global__ void __launch_bounds__(256) k_dw7(int fi, const float* __restrict__ dww) {
    __shared__ float sw[49];
    __shared__ float spt[484];
    const int ch = blockIdx.z;
    const int ty0 = blockIdx.y * 16, tx0 = blockIdx.x * 16;
    if (threadIdx.x < 49) sw[threadIdx.x] = dww[ch * 49 + threadIdx.x];
    const float* src = g_feat[fi] + ch * SP;
    for (int t = threadIdx.x; t < 484; t += 256) {
        int r = t / 22, c2 = t % 22;
        int gy = ty0 - 6 + r, gx = tx0 - 6 + c2;
        spt[t] = (gy >= 0 && gy < 96 && gx >= 0 && gx < 96) ? src[gy * 96 + gx] : 0.f;
    }
    __syncthreads();
    int ly = threadIdx.x / 16, lx = threadIdx.x % 16;
    int oy = ty0 + ly, ox = tx0 + lx;
    if (oy >= PP || ox >= PP) return;
    float acc = 0.f;
#pragma unroll
    for (int a = 0; a < 7; a++)
#pragma unroll
        for (int b = 0; b < 7; b++)
            acc += spt[(ly + a) * 22 + lx + b] * sw[a * 7 + b];
    g_dwo[ch * SPP + oy * PP + ox] = acc;
}

__global__ void k_zero2() { if (threadIdx.x < 2) g_red[threadIdx.x] = 0.f; }

__global__ void __launch_bounds__(256) k_zeroG() {
    int i = blockIdx.x * 256 + threadIdx.x;
    if (i < 4096) g_G[i] = 0.f;
    if (i < 64) g_s[i] = 0.f;
}

__global__ void __launch_bounds__(256) k_pw(const float* __restrict__ W) {
    __shared__ float swT[64 * 68];
    __shared__ float sin_[4096];
    __shared__ float sr[2][8];
    const int p0 = blockIdx.x * 64;
    for (int t = threadIdx.x; t < 4096; t += 256) {
        int co = t >> 6, ci = t & 63;
        swT[ci * 68 + co] = W[t];
    }
    for (int t = threadIdx.x; t < 4096; t += 256) {
        int ci = t >> 6, p = t & 63; int gp = p0 + p;
        sin_[t] = (gp < SPP) ? g_dwo[ci * SPP + gp] : 0.f;
    }
    __syncthreads();
    const int ocg = threadIdx.x >> 4, pg = threadIdx.x & 15;
    float acc[4][4] = {};
#pragma unroll 4
    for (int ci = 0; ci < 64; ci++) {
        float4 w4 = *(const float4*)&swT[ci * 68 + ocg * 4];
        float4 i4 = *(const float4*)&sin_[ci * 64 + pg * 4];
        acc[0][0] += w4.x * i4.x; acc[0][1] += w4.x * i4.y; acc[0][2] += w4.x * i4.z; acc[0][3] += w4.x * i4.w;
        acc[1][0] += w4.y * i4.x; acc[1][1] += w4.y * i4.y; acc[1][2] += w4.y * i4.z; acc[1][3] += w4.y * i4.w;
        acc[2][0] += w4.z * i4.x; acc[2][1] += w4.z * i4.y; acc[2][2] += w4.z * i4.z; acc[2][3] += w4.z * i4.w;
        acc[3][0] += w4.w * i4.x; acc[3][1] += w4.w * i4.y; acc[3][2] += w4.w * i4.z; acc[3][3] += w4.w * i4.w;
    }
    float ls = 0.f, ls2 = 0.f;
#pragma unroll
    for (int o = 0; o < 4; o++) {
        int oc = ocg * 4 + o;
#pragma unroll
        for (int p = 0; p < 4; p++) {
            int gp = p0 + pg * 4 + p;
            if (gp < SPP) {
                float v = acc[o][p];
                g_pwo[oc * SPP + gp] = v;
                ls += v; ls2 += v * v;
            }
        }
    }
    for (int off = 16; off; off >>= 1) {
        ls += __shfl_down_sync(0xffffffffu, ls, off);
        ls2 += __shfl_down_sync(0xffffffffu, ls2, off);
    }
    if ((threadIdx.x & 31) == 0) { sr[0][threadIdx.x >> 5] = ls; sr[1][threadIdx.x >> 5] = ls2; }
    __syncthreads();
    if (threadIdx.x == 0) {
        float a = 0.f, b = 0.f;
        for (int w2 = 0; w2 < 8; w2++) { a += sr[0][w2]; b += sr[1][w2]; }
        atomicAdd(&g_red[0], a); atomicAdd(&g_red[1], b);
    }
}

__global__ void k_stats() {
    float m = g_red[0] / (float)NLN;
    float v = g_red[1] / (float)NLN - m * m;
    g_stats[0] = m;
    g_stats[1] = rsqrtf(v + 1e-5f);
}

// ---------------- l1 via tf32 mma.sync implicit GEMM ----------------
// block: 128 oc x (16y x 8x) px ; 8 warps: warp = 32 oc x (8y x 8x)
// grid: (12 x-tiles, 6 y-tiles, 2 oc-halves)
#define L1_SW 28672              // 4ic * 7a * 128oc * 8 floats
#define L1_SIN 1248              // 4ic * 308 + 16 guard
#define L1_SMEM ((L1_SW + L1_SIN) * 4)

__global__ void __launch_bounds__(256) k_l1mma(int blk, const float* __restrict__ l1b) {
    extern __shared__ float smem[];
    float* s_w = smem;
    float* s_in = smem + L1_SW;
    const float m = g_stats[0], inv = g_stats[1];
    const int tx = blockIdx.x * 8, ty = blockIdx.y * 16;
    const int ochalf = blockIdx.z;
    const int tid = threadIdx.x;
    const int wid = tid >> 5, lane = tid & 31;
    const int ocg = wid >> 1, pxg = wid & 1;
    const int g = lane >> 2, j4 = lane & 3;

    if (tid < 16) s_in[L1_SIN - 16 + tid] = 0.f;   // guard for b=7 pad reads

    float c[2][8][4] = {};

    for (int icg = 0; icg < 16; icg++) {
        __syncthreads();
        // stage input patch (normalized + tf32-rounded): 4 ic x 22 x 14
        for (int t = tid; t < 1232; t += 256) {
            int ic = t / 308, r2 = t % 308;
            int r = r2 / 14, cl = r2 % 14;
            float v = (g_pwo[(icg * 4 + ic) * SPP + (ty + r) * PP + (tx + cl)] - m) * inv;
            s_in[t] = __uint_as_float(f2tf32(v));
        }
        // stage weights: 28 segments of 1024 contiguous floats
        for (int q = tid; q < 7168; q += 256) {
            int seg = q >> 8, within = q & 255;
            int ic = seg / 7, a = seg % 7;
            const float4* src = (const float4*)(g_l1wT2 +
                ((((size_t)blk * 64 + icg * 4 + ic) * 7 + a) * 256 + ochalf * 128) * 8) + within;
            ((float4*)s_w)[seg * 256 + within] = *src;
        }
        __syncthreads();

        for (int ic4 = 0; ic4 < 4; ic4++) {
            const uint32_t* pb = (const uint32_t*)s_in + ic4 * 308 + (pxg * 8) * 14 + g + j4;
#pragma unroll
            for (int a = 0; a < 7; a++) {
                const float* wb = s_w + (ic4 * 7 + a) * 1024;
                uint32_t A0[4], A1[4];
                {
                    int r0 = ocg * 32 + g;
                    float2 lo = *(const float2*)(wb + r0 * 8 + j4 * 2);
                    float2 hi = *(const float2*)(wb + (r0 + 8) * 8 + j4 * 2);
                    A0[0] = __float_as_uint(lo.x); A0[2] = __float_as_uint(lo.y);
                    A0[1] = __float_as_uint(hi.x); A0[3] = __float_as_uint(hi.y);
                    float2 lo2 = *(const float2*)(wb + (r0 + 16) * 8 + j4 * 2);
                    float2 hi2 = *(const float2*)(wb + (r0 + 24) * 8 + j4 * 2);
                    A1[0] = __float_as_uint(lo2.x); A1[2] = __float_as_uint(lo2.y);
                    A1[1] = __float_as_uint(hi2.x); A1[3] = __float_as_uint(hi2.y);
                }
                const uint32_t* p = pb + a * 14;
#pragma unroll
                for (int j = 0; j < 8; j++) {
                    uint32_t b0 = p[0], b1 = p[4];
                    mma8(c[0][j], A0, b0, b1);
                    mma8(c[1][j], A1, b0, b1);
                    p += 14;
                }
            }
        }
    }

    // epilogue: bias + exact gelu
#pragma unroll
    for (int mm = 0; mm < 2; mm++) {
        int ocb = ochalf * 128 + ocg * 32 + mm * 16 + g;
        float b_lo = l1b[ocb], b_hi = l1b[ocb + 8];
#pragma unroll
        for (int j = 0; j < 8; j++) {
            int y = ty + pxg * 8 + j;
            int xb = tx + 2 * j4;
            float* o_lo = &g_l1o[ocb * SP + y * 96 + xb];
            float* o_hi = &g_l1o[(ocb + 8) * SP + y * 96 + xb];
            o_lo[0] = gelu(c[mm][j][0] + b_lo);
            o_lo[1] = gelu(c[mm][j][1] + b_lo);
            o_hi[0] = gelu(c[mm][j][2] + b_hi);
            o_hi[1] = gelu(c[mm][j][3] + b_hi);
        }
    }
}

__global__ void __launch_bounds__(256) k_l2(const float* __restrict__ W, const float* __restrict__ bias,
                                            int r1, int r2, int dst) {
    __shared__ float swT[64 * 68];
    __shared__ float sin_[4096];
    const int p0 = blockIdx.x * 64;
    const int ocg = threadIdx.x >> 4, pg = threadIdx.x & 15;
    float acc[4][4] = {};
    for (int c0 = 0; c0 < 256; c0 += 64) {
        __syncthreads();
        for (int t = threadIdx.x; t < 4096; t += 256) {
            int co = t >> 6, ci = t & 63;
            swT[ci * 68 + co] = W[co * 256 + c0 + ci];
        }
        for (int t = threadIdx.x; t < 4096; t += 256) {
            int ci = t >> 6, p = t & 63;
            sin_[t] = g_l1o[(c0 + ci) * SP + p0 + p];
        }
        __syncthreads();
#pragma unroll 4
        for (int ci = 0; ci < 64; ci++) {
            float4 w4 = *(const float4*)&swT[ci * 68 + ocg * 4];
            float4 i4 = *(const float4*)&sin_[ci * 64 + pg * 4];
            acc[0][0] += w4.x * i4.x; acc[0][1] += w4.x * i4.y; acc[0][2] += w4.x * i4.z; acc[0][3] += w4.x * i4.w;
            acc[1][0] += w4.y * i4.x; acc[1][1] += w4.y * i4.y; acc[1][2] += w4.y * i4.z; acc[1][3] += w4.y * i4.w;
            acc[2][0] += w4.z * i4.x; acc[2][1] += w4.z * i4.y; acc[2][2] += w4.z * i4.z; acc[2][3] += w4.z * i4.w;
            acc[3][0] += w4.w * i4.x; acc[3][1] += w4.w * i4.y; acc[3][2] += w4.w * i4.z; acc[3][3] += w4.w * i4.w;
        }
    }
    float* dstp = g_feat[dst];
    const float* rp1 = g_feat[r1];
    const float* rp2 = (r2 >= 0) ? g_feat[r2] : 0;
#pragma unroll
    for (int o = 0; o < 4; o++) {
        int oc = ocg * 4 + o;
        float bi = bias[oc];
#pragma unroll
        for (int p = 0; p < 4; p++) {
            int idx = oc * SP + p0 + pg * 4 + p;
            float v = acc[o][p] + bi + rp1[idx];
            if (rp2) v += rp2[idx];
            dstp[idx] = v;
        }
    }
}

__global__ void __launch_bounds__(256) k_xg(int fi) {
    __shared__ float sf[1024];
    const float* f = g_feat[fi];
    const int ag = threadIdx.x >> 4, bg = threadIdx.x & 15;
    float acc[4][4] = {};
    float sacc[4] = {};
    const int tok0 = blockIdx.x * 144;
    for (int tb = 0; tb < 144; tb += 16) {
        __syncthreads();
        for (int t2 = threadIdx.x; t2 < 1024; t2 += 256) sf[t2] = f[(tok0 + tb) * 64 + t2];
        __syncthreads();
#pragma unroll
        for (int tk = 0; tk < 16; tk++) {
            float4 fa = *(const float4*)&sf[tk * 64 + ag * 4];
            float4 fb = *(const float4*)&sf[tk * 64 + bg * 4];
            acc[0][0] += fa.x * fb.x; acc[0][1] += fa.x * fb.y; acc[0][2] += fa.x * fb.z; acc[0][3] += fa.x * fb.w;
            acc[1][0] += fa.y * fb.x; acc[1][1] += fa.y * fb.y; acc[1][2] += fa.y * fb.z; acc[1][3] += fa.y * fb.w;
            acc[2][0] += fa.z * fb.x; acc[2][1] += fa.z * fb.y; acc[2][2] += fa.z * fb.z; acc[2][3] += fa.z * fb.w;
            acc[3][0] += fa.w * fb.x; acc[3][1] += fa.w * fb.y; acc[3][2] += fa.w * fb.z; acc[3][3] += fa.w * fb.w;
            if (ag == 0) { sacc[0] += fb.x; sacc[1] += fb.y; sacc[2] += fb.z; sacc[3] += fb.w; }
        }
    }
    for (int i2 = 0; i2 < 4; i2++)
        for (int j2 = 0; j2 < 4; j2++)
            atomicAdd(&g_G[(ag * 4 + i2) * 64 + bg * 4 + j2], acc[i2][j2]);
    if (ag == 0)
        for (int j2 = 0; j2 < 4; j2++) atomicAdd(&g_s[bg * 4 + j2], sacc[j2]);
}

__global__ void __launch_bounds__(256) k_xatt(const float* __restrict__ Qw, const float* __restrict__ Qb,
                                              const float* __restrict__ Kw, const float* __restrict__ Kb,
                                              const float* __restrict__ Vw, const float* __restrict__ Vb,
                                              float scale) {
    __shared__ float sA[4096];
    __shared__ float sGK[4096];
    __shared__ float ss[64], sQs[64], sKs[64];
    const int t = threadIdx.x;
    for (int i = t; i < 4096; i += 256) sA[i] = g_G[i];
    if (t < 64) ss[t] = g_s[t];
    __syncthreads();
    if (t < 64) {
        float q = 0.f;
        for (int a2 = 0; a2 < 64; a2++) q += Qw[t * 64 + a2] * ss[a2];
        sQs[t] = q;
    } else if (t < 128) {
        int d = t - 64; float q = 0.f;
        for (int b2 = 0; b2 < 64; b2++) q += Kw[d * 64 + b2] * ss[b2];
        sKs[d] = q;
    }
    for (int i = t; i < 4096; i += 256) {
        int a2 = i >> 6, d = i & 63;
        float s2 = 0.f;
        for (int b2 = 0; b2 < 64; b2++) s2 += sA[a2 * 64 + b2] * Kw[d * 64 + b2];
        sGK[i] = s2;
    }
    __syncthreads();
    for (int i = t; i < 4096; i += 256) {
        int c = i >> 6, d = i & 63;
        float s2 = Qb[c] * sKs[d] + sQs[c] * Kb[d] + 9216.0f * Qb[c] * Kb[d];
        for (int a2 = 0; a2 < 64; a2++) s2 += Qw[c * 64 + a2] * sGK[a2 * 64 + d];
        sA[i] = s2 * scale;
    }
    __syncthreads();
    if (t < 64) {
        float mx = -1e30f;
        for (int d = 0; d < 64; d++) mx = fmaxf(mx, sA[t * 64 + d]);
        float sm = 0.f;
        for (int d = 0; d < 64; d++) { float e = expf(sA[t * 64 + d] - mx); sA[t * 64 + d] = e; sm += e; }
        float r = 1.0f / sm;
        for (int d = 0; d < 64; d++) sA[t * 64 + d] *= r;
    }
    __syncthreads();
    for (int i = t; i < 4096; i += 256) {
        int a2 = i >> 6, d = i & 63;
        float s2 = 0.f;
        for (int c = 0; c < 64; c++) s2 += Vw[c * 64 + a2] * sA[c * 64 + d];
        g_M[i] = s2;
    }
    if (t < 64) {
        float s2 = 0.f;
        for (int c = 0; c < 64; c++) s2 += Vb[c] * sA[c * 64 + t];
        g_bias[t] = s2;
    }
}

__global__ void __launch_bounds__(256) k_xapply(int fi, int dst) {
    __shared__ float sM[4096];
    __shared__ float sb[64];
    __shared__ float sf[2048];
    for (int t = threadIdx.x; t < 4096; t += 256) sM[t] = g_M[t];
    if (threadIdx.x < 64) sb[threadIdx.x] = g_bias[threadIdx.x];
    const int tok0 = blockIdx.x * 32;
    const float* f = g_feat[fi];
    for (int t = threadIdx.x; t < 2048; t += 256) sf[t] = f[tok0 * 64 + t];
    __syncthreads();
    const int tk = threadIdx.x >> 3, dg = threadIdx.x & 7;
    float acc[8] = {};
#pragma unroll 8
    for (int a2 = 0; a2 < 64; a2++) {
        float fa = sf[tk * 64 + a2];
        float4 m0 = *(const float4*)&sM[a2 * 64 + dg * 8];
        float4 m1 = *(const float4*)&sM[a2 * 64 + dg * 8 + 4];
        acc[0] += fa * m0.x; acc[1] += fa * m0.y; acc[2] += fa * m0.z; acc[3] += fa * m0.w;
        acc[4] += fa * m1.x; acc[5] += fa * m1.y; acc[6] += fa * m1.z; acc[7] += fa * m1.w;
    }
    float* dp = g_feat[dst];
    const int base = (tok0 + tk) * 64 + dg * 8;
#pragma unroll
    for (int d2 = 0; d2 < 8; d2++) dp[base + d2] = sf[tk * 64 + dg * 8 + d2] + acc[d2] + sb[dg * 8 + d2];
}

__global__ void __launch_bounds__(256) k_op(int fi, int oi, const float* __restrict__ w,
                                            const float* __restrict__ bb) {
    __shared__ float sw[576];
    for (int t = threadIdx.x; t < 576; t += 256) {
        int ch = t / 9, k2 = t % 9; int a = k2 / 3, b2 = k2 % 3;
        sw[t] = w[ch * 9 + (2 - a) * 3 + (2 - b2)];
    }
    __syncthreads();
    int idx = blockIdx.x * 256 + threadIdx.x;
    if (idx >= SP) return;
    int u = idx / 96, v = idx % 96;
    const float* x = g_feat[fi];
    float acc = bb[0];
    for (int ch = 0; ch < 64; ch++) {
#pragma unroll
        for (int a = 0; a < 3; a++) {
            int y = u + a - 1; if ((unsigned)y >= 96u) continue;
#pragma unroll
            for (int b2 = 0; b2 < 3; b2++) {
                int xx = v + b2 - 1; if ((unsigned)xx >= 96u) continue;
                acc += x[ch * SP + y * 96 + xx] * sw[ch * 9 + a * 3 + b2];
            }
        }
    }
    g_opout[oi][v * 96 + u] = acc;
}

__global__ void __launch_bounds__(256) k_idwt(const float* __restrict__ img, float* __restrict__ out) {
    int idx = blockIdx.x * 256 + threadIdx.x;
    if (idx >= SP) return;
    int i = idx / 96, j = idx % 96;
    float a = g_opout[0][idx], b = g_opout[1][idx], c = g_opout[2][idx], d = g_opout[3][idx];
    int r0 = (2 * i) * 192 + 2 * j;
    int r1 = (2 * i + 1) * 192 + 2 * j;
    out[r0]     = 0.5f * (a + b + c + d) + img[r0];
    out[r0 + 1] = 0.5f * (a - b + c - d) + img[r0 + 1];
    out[r1]     = 0.5f * (a + b - c - d) + img[r1];
    out[r1 + 1] = 0.5f * (a - b - c + d) + img[r1 + 1];
}

extern "C" void kernel_launch(void* const* d_in, const int* in_sizes, int n_in,
                              void* d_out, int out_size) {
    (void)in_sizes; (void)n_in; (void)out_size;
    const float* images = (const float*)d_in[0];
    const float* ip_w  = (const float*)d_in[1];
    const float* ip_b  = (const float*)d_in[2];
    const float* op_w  = (const float*)d_in[3];
    const float* op_b  = (const float*)d_in[4];
    const float* cb_dw = (const float*)d_in[5];
    const float* cb_pw = (const float*)d_in[6];
    const float* cb_l1w = (const float*)d_in[7];
    const float* cb_l1b = (const float*)d_in[8];
    const float* cb_l2w = (const float*)d_in[9];
    const float* cb_l2b = (const float*)d_in[10];
    const float* xqw = (const float*)d_in[11];
    const float* xqb = (const float*)d_in[12];
    const float* xkw = (const float*)d_in[13];
    const float* xkb = (const float*)d_in[14];
    const float* xvw = (const float*)d_in[15];
    const float* xvb = (const float*)d_in[16];
    float* out = (float*)d_out;

    cudaFuncSetAttribute(k_l1mma, cudaFuncAttributeMaxDynamicSharedMemorySize, L1_SMEM);

    k_dwt<<<36, 256>>>(images);
    k_l1wt2<<<(6 * 64 * 7 * 256 * 8 + 255) / 256, 256>>>(cb_l1w);

    auto cb = [&](int blk, int src, int r2, int dst) {
        k_dw7<<<dim3(7, 7, 64), 256>>>(src, cb_dw + blk * 3136);
        k_zero2<<<1, 32>>>();
        k_pw<<<163, 256>>>(cb_pw + blk * 4096);
        k_stats<<<1, 1>>>();
        k_l1mma<<<dim3(12, 6, 2), 256, L1_SMEM>>>(blk, cb_l1b + blk * 256);
        k_l2<<<144, 256>>>(cb_l2w + blk * 16384, cb_l2b + blk * 64, src, r2, dst);
    };
    auto xb = [&](int i, int src, int dst, float scale) {
        k_zeroG<<<16, 256>>>();
        k_xg<<<64, 256>>>(src);
        k_xatt<<<1, 256>>>(xqw + i * 4096, xqb + i * 64, xkw + i * 4096, xkb + i * 64,
                           xvw + i * 4096, xvb + i * 64, scale);
        k_xapply<<<288, 256>>>(src, dst);
    };

    k_ip<<<2304, 256>>>(0, 0, ip_w, ip_b);
    cb(0, 0, -1, 1);
    cb(1, 1, 1, 2);
    xb(0, 1, 3, 0.44721359549995793f);
    cb(2, 3, 2, 4);
    cb(3, 4, 1, 5);
    k_op<<<36, 256>>>(5, 0, op_w, op_b);

    for (int bi = 1; bi <= 3; bi++) {
        k_ip<<<2304, 256>>>(bi, 6, ip_w, ip_b);
        cb(4, 6, -1, 7);
        xb(1, 7, 3, 0.70710678118654752f);
        cb(5, 3, 7, 4);
        k_op<<<36, 256>>>(4, bi, op_w, op_b);
    }
    k_idwt<<<36, 256>>>(images, out);
}

// round 8
// speedup vs baseline: 3.0876x; 1.4027x over previous
#include <cuda_runtime.h>
#include <cuda_bf16.h>
#include <math.h>
#include <stdint.h>

#define CC 64
#define SP 9216
#define PP 102
#define SPP 10404
#define NLN 665856

typedef unsigned long long u64t;

// ---------------- scratch ----------------
__device__ float g_band[4][SP];
__device__ float g_opout[4][SP];
__device__ float g_feat[8][CC * SP];
__device__ float g_dwo[CC * SPP];
__device__ float g_pwo[CC * SPP];
__device__ float g_l1o[4 * CC * SP];
// bf16-packed l1 weights: [blk][icg 16][ochalf 2][seg 14 (pair*7+a)][oc 128][q 8] u32
// q = 2*j4 + h ; u32 = bf16x2 of taps (2j4, 2j4+1) of ic = icg*4 + pair*2 + h ; tap7 -> 0
__device__ __align__(16) uint32_t g_l1w_bf[6 * 16 * 2 * 14 * 128 * 8];
__device__ float g_red[2];
__device__ float g_G[4096];
__device__ float g_s[64];
__device__ float g_M[4096];
__device__ float g_bias[64];

__device__ __forceinline__ float gelu(float x) {
    return 0.5f * x * (1.0f + erff(x * 0.70710678118654752f));
}
__device__ __forceinline__ void mma_bf16(float* c, uint32_t a0, uint32_t a1, uint32_t a2,
                                         uint32_t a3, uint32_t b0, uint32_t b1) {
    asm volatile(
        "mma.sync.aligned.m16n8k16.row.col.f32.bf16.bf16.f32 "
        "{%0,%1,%2,%3}, {%4,%5,%6,%7}, {%8,%9}, {%0,%1,%2,%3};"
        : "+f"(c[0]), "+f"(c[1]), "+f"(c[2]), "+f"(c[3])
        : "r"(a0), "r"(a1), "r"(a2), "r"(a3), "r"(b0), "r"(b1));
}

// ---------------- DWT (+ initial zero of attention accumulators) ----------------
__global__ void __launch_bounds__(256) k_dwt(const float* __restrict__ img) {
    if (blockIdx.x == 0) {
        for (int t = threadIdx.x; t < 4096; t += 256) g_G[t] = 0.f;
        if (threadIdx.x < 64) g_s[threadIdx.x] = 0.f;
    }
    int idx = blockIdx.x * 256 + threadIdx.x;
    if (idx >= SP) return;
    int i = idx / 96, j = idx % 96;
    float a = img[(2 * i) * 192 + 2 * j];
    float b = img[(2 * i + 1) * 192 + 2 * j];
    float c = img[(2 * i) * 192 + 2 * j + 1];
    float d = img[(2 * i + 1) * 192 + 2 * j + 1];
    g_band[0][idx] = (a + b + c + d) * 0.5f;
    g_band[1][idx] = (a + b - c - d) * 0.5f;
    g_band[2][idx] = (a - b + c - d) * 0.5f;
    g_band[3][idx] = (a - b - c + d) * 0.5f;
}

// ---------------- l1 weight prepack to bf16 ----------------
__global__ void __launch_bounds__(256) k_l1wtb(const float* __restrict__ w) {
    int idx = blockIdx.x * 256 + threadIdx.x;
    const int total = 6 * 16 * 2 * 14 * 128 * 8;
    if (idx >= total) return;
    int q = idx & 7;
    int j4 = q >> 1, h = q & 1;
    int t = idx >> 3;
    int oc_l = t & 127; t >>= 7;
    int seg = t % 14; t /= 14;
    int ochalf = t & 1; t >>= 1;
    int icg = t & 15;
    int blk = t >> 4;
    int pair = seg / 7, a = seg % 7;
    int ic = icg * 4 + pair * 2 + h;
    int oc = ochalf * 128 + oc_l;
    int b0t = 2 * j4, b1t = 2 * j4 + 1;
    const float* wb = w + ((size_t)(blk * 256 + oc) * 64 + ic) * 49 + a * 7;
    float w0 = wb[b0t];
    float w1 = (b1t < 7) ? wb[b1t] : 0.f;
    uint32_t lo = __bfloat16_as_ushort(__float2bfloat16(w0));
    uint32_t hi = __bfloat16_as_ushort(__float2bfloat16(w1));
    g_l1w_bf[idx] = lo | (hi << 16);
}

__global__ void __launch_bounds__(256) k_ip(int bi, int fi, const float* __restrict__ w,
                                            const float* __restrict__ bb) {
    __shared__ float sw[576];
    __shared__ float sb2[64];
    for (int t = threadIdx.x; t < 576; t += 256) sw[t] = w[t];
    if (threadIdx.x < 64) sb2[threadIdx.x] = bb[threadIdx.x];
    __syncthreads();
    int idx = blockIdx.x * 256 + threadIdx.x;
    if (idx >= CC * SP) return;
    int v = idx % 96; int u = (idx / 96) % 96; int ch = idx / SP;
    const float* src = g_band[bi];
    float acc = sb2[ch];
#pragma unroll
    for (int a = 0; a < 3; a++) {
        int x0 = u + a - 1;
        if ((unsigned)x0 < 96u) {
#pragma unroll
            for (int b2 = 0; b2 < 3; b2++) {
                int y0 = v + b2 - 1;
                if ((unsigned)y0 < 96u) acc += src[y0 * 96 + x0] * sw[ch * 9 + a * 3 + b2];
            }
        }
    }
    g_feat[fi][idx] = acc;
}

// ---------------- depthwise 7x7 (+ zero LN reduction) ----------------
__global__ void __launch_bounds__(256) k_dw7(int fi, const float* __restrict__ dww) {
    __shared__ float sw[49];
    __shared__ float spt[484];
    if (blockIdx.x == 0 && blockIdx.y == 0 && blockIdx.z == 0 && threadIdx.x < 2)
        g_red[threadIdx.x] = 0.f;
    const int ch = blockIdx.z;
    const int ty0 = blockIdx.y * 16, tx0 = blockIdx.x * 16;
    if (threadIdx.x < 49) sw[threadIdx.x] = dww[ch * 49 + threadIdx.x];
    const float* src = g_feat[fi] + ch * SP;
    for (int t = threadIdx.x; t < 484; t += 256) {
        int r = t / 22, c2 = t % 22;
        int gy = ty0 - 6 + r, gx = tx0 - 6 + c2;
        spt[t] = (gy >= 0 && gy < 96 && gx >= 0 && gx < 96) ? src[gy * 96 + gx] : 0.f;
    }
    __syncthreads();
    int ly = threadIdx.x / 16, lx = threadIdx.x % 16;
    int oy = ty0 + ly, ox = tx0 + lx;
    if (oy >= PP || ox >= PP) return;
    float acc = 0.f;
#pragma unroll
    for (int a = 0; a < 7; a++)
#pragma unroll
        for (int b = 0; b < 7; b++)
            acc += spt[(ly + a) * 22 + lx + b] * sw[a * 7 + b];
    g_dwo[ch * SPP + oy * PP + ox] = acc;
}

__global__ void __launch_bounds__(256) k_pw(const float* __restrict__ W) {
    __shared__ float swT[64 * 68];
    __shared__ float sin_[4096];
    __shared__ float sr[2][8];
    const int p0 = blockIdx.x * 64;
    for (int t = threadIdx.x; t < 4096; t += 256) {
        int co = t >> 6, ci = t & 63;
        swT[ci * 68 + co] = W[t];
    }
    for (int t = threadIdx.x; t < 4096; t += 256) {
        int ci = t >> 6, p = t & 63; int gp = p0 + p;
        sin_[t] = (gp < SPP) ? g_dwo[ci * SPP + gp] : 0.f;
    }
    __syncthreads();
    const int ocg = threadIdx.x >> 4, pg = threadIdx.x & 15;
    float acc[4][4] = {};
#pragma unroll 4
    for (int ci = 0; ci < 64; ci++) {
        float4 w4 = *(const float4*)&swT[ci * 68 + ocg * 4];
        float4 i4 = *(const float4*)&sin_[ci * 64 + pg * 4];
        acc[0][0] += w4.x * i4.x; acc[0][1] += w4.x * i4.y; acc[0][2] += w4.x * i4.z; acc[0][3] += w4.x * i4.w;
        acc[1][0] += w4.y * i4.x; acc[1][1] += w4.y * i4.y; acc[1][2] += w4.y * i4.z; acc[1][3] += w4.y * i4.w;
        acc[2][0] += w4.z * i4.x; acc[2][1] += w4.z * i4.y; acc[2][2] += w4.z * i4.z; acc[2][3] += w4.z * i4.w;
        acc[3][0] += w4.w * i4.x; acc[3][1] += w4.w * i4.y; acc[3][2] += w4.w * i4.z; acc[3][3] += w4.w * i4.w;
    }
    float ls = 0.f, ls2 = 0.f;
#pragma unroll
    for (int o = 0; o < 4; o++) {
        int oc = ocg * 4 + o;
#pragma unroll
        for (int p = 0; p < 4; p++) {
            int gp = p0 + pg * 4 + p;
            if (gp < SPP) {
                float v = acc[o][p];
                g_pwo[oc * SPP + gp] = v;
                ls += v; ls2 += v * v;
            }
        }
    }
    for (int off = 16; off; off >>= 1) {
        ls += __shfl_down_sync(0xffffffffu, ls, off);
        ls2 += __shfl_down_sync(0xffffffffu, ls2, off);
    }
    if ((threadIdx.x & 31) == 0) { sr[0][threadIdx.x >> 5] = ls; sr[1][threadIdx.x >> 5] = ls2; }
    __syncthreads();
    if (threadIdx.x == 0) {
        float a = 0.f, b = 0.f;
        for (int w2 = 0; w2 < 8; w2++) { a += sr[0][w2]; b += sr[1][w2]; }
        atomicAdd(&g_red[0], a); atomicAdd(&g_red[1], b);
    }
}

// ---------------- l1 via bf16 mma m16n8k16, synchronous staged weights ----------------
// block: 128 oc x (16y x 8x); 8 warps: warp = 32 oc x (8y x 8x). grid (12,6,2).
#define L1_WBUF 14336                        // u32 per weight buffer (one icg group)
#define L1_IN   1408                         // u32: even[4][22][8] + odd[4][22][8]
#define L1_SMEMB ((L1_WBUF + L1_IN) * 4)     // 62976 bytes

__global__ void __launch_bounds__(256) k_l1mma(int blk, const float* __restrict__ l1b) {
    extern __shared__ uint32_t sm[];
    uint32_t* s_in = sm + L1_WBUF;
    const int tid = threadIdx.x;
    const int tx = blockIdx.x * 8, ty = blockIdx.y * 16;
    const int ochalf = blockIdx.z;
    const int wid = tid >> 5, lane = tid & 31;
    const int ocg = wid >> 1, pxg = wid & 1;
    const int g = lane >> 2, j4 = lane & 3;

    const float m = g_red[0] * (1.0f / (float)NLN);
    const float inv = rsqrtf(g_red[1] * (1.0f / (float)NLN) - m * m + 1e-5f);

    for (int t = tid; t < L1_IN; t += 256) s_in[t] = 0u;

    float c[2][8][4] = {};
    unsigned short* s_ine = (unsigned short*)s_in;          // even copy: [ic][22][16] u16
    unsigned short* s_ino = (unsigned short*)(s_in + 704);  // odd copy

    for (int icg = 0; icg < 16; icg++) {
        __syncthreads();
        // stage weights (synchronous float4 copy; source is L2-hot, 57 KB)
        {
            size_t chunk = ((size_t)(blk * 16 + icg) * 2 + ochalf) * L1_WBUF;
            const uint4* src = (const uint4*)(g_l1w_bf + chunk);
            uint4* dstw = (uint4*)sm;
#pragma unroll
            for (int i = 0; i < 14; i++)
                dstw[tid + i * 256] = src[tid + i * 256];
        }
        // stage inputs (normalized, bf16, dual-parity)
        for (int t = tid; t < 1232; t += 256) {
            int ic = t / 308, r2 = t % 308;
            int r = r2 / 14, cx = r2 % 14;
            float v = (g_pwo[(icg * 4 + ic) * SPP + (ty + r) * PP + (tx + cx)] - m) * inv;
            unsigned short hb = __bfloat16_as_ushort(__float2bfloat16(v));
            int rowb = (ic * 22 + r) * 16;
            s_ine[rowb + cx] = hb;
            if (cx >= 1) s_ino[rowb + cx - 1] = hb;
        }
        __syncthreads();

        const uint32_t* wb = sm;
        const int r0 = ocg * 32 + g;
        const uint32_t* pbase = s_in + (g & 1) * 704 + ((g >> 1) + j4);
#pragma unroll
        for (int pair = 0; pair < 2; pair++) {
#pragma unroll
            for (int a = 0; a < 7; a++) {
                const uint32_t* ws = wb + (pair * 7 + a) * 1024 + 2 * j4;
                u64t A0lo = *(const u64t*)(ws + r0 * 8);
                u64t A0hi = *(const u64t*)(ws + (r0 + 8) * 8);
                u64t A1lo = *(const u64t*)(ws + (r0 + 16) * 8);
                u64t A1hi = *(const u64t*)(ws + (r0 + 24) * 8);
                uint32_t a00 = (uint32_t)A0lo, a02 = (uint32_t)(A0lo >> 32);
                uint32_t a01 = (uint32_t)A0hi, a03 = (uint32_t)(A0hi >> 32);
                uint32_t a10 = (uint32_t)A1lo, a12 = (uint32_t)(A1lo >> 32);
                uint32_t a11 = (uint32_t)A1hi, a13 = (uint32_t)(A1hi >> 32);
                const uint32_t* p0 = pbase + (pair * 2) * 176 + (pxg * 8 + a) * 8;
                const uint32_t* p1 = p0 + 176;
#pragma unroll
                for (int j = 0; j < 8; j++) {
                    uint32_t b0 = p0[j * 8], b1 = p1[j * 8];
                    mma_bf16(c[0][j], a00, a01, a02, a03, b0, b1);
                    mma_bf16(c[1][j], a10, a11, a12, a13, b0, b1);
                }
            }
        }
    }

    // epilogue: bias + exact gelu
#pragma unroll
    for (int mm = 0; mm < 2; mm++) {
        int ocb = ochalf * 128 + ocg * 32 + mm * 16 + g;
        float b_lo = l1b[ocb], b_hi = l1b[ocb + 8];
#pragma unroll
        for (int j = 0; j < 8; j++) {
            int y = ty + pxg * 8 + j;
            int xb = tx + 2 * j4;
            float* o_lo = &g_l1o[ocb * SP + y * 96 + xb];
            float* o_hi = &g_l1o[(ocb + 8) * SP + y * 96 + xb];
            o_lo[0] = gelu(c[mm][j][0] + b_lo);
            o_lo[1] = gelu(c[mm][j][1] + b_lo);
            o_hi[0] = gelu(c[mm][j][2] + b_hi);
            o_hi[1] = gelu(c[mm][j][3] + b_hi);
        }
    }
}

__global__ void __launch_bounds__(256) k_l2(const float* __restrict__ W, const float* __restrict__ bias,
                                            int r1, int r2, int dst) {
    __shared__ float swT[64 * 68];
    __shared__ float sin_[4096];
    const int p0 = blockIdx.x * 64;
    const int ocg = threadIdx.x >> 4, pg = threadIdx.x & 15;
    float acc[4][4] = {};
    for (int c0 = 0; c0 < 256; c0 += 64) {
        __syncthreads();
        for (int t = threadIdx.x; t < 4096; t += 256) {
            int co = t >> 6, ci = t & 63;
            swT[ci * 68 + co] = W[co * 256 + c0 + ci];
        }
        for (int t = threadIdx.x; t < 4096; t += 256) {
            int ci = t >> 6, p = t & 63;
            sin_[t] = g_l1o[(c0 + ci) * SP + p0 + p];
        }
        __syncthreads();
#pragma unroll 4
        for (int ci = 0; ci < 64; ci++) {
            float4 w4 = *(const float4*)&swT[ci * 68 + ocg * 4];
            float4 i4 = *(const float4*)&sin_[ci * 64 + pg * 4];
            acc[0][0] += w4.x * i4.x; acc[0][1] += w4.x * i4.y; acc[0][2] += w4.x * i4.z; acc[0][3] += w4.x * i4.w;
            acc[1][0] += w4.y * i4.x; acc[1][1] += w4.y * i4.y; acc[1][2] += w4.y * i4.z; acc[1][3] += w4.y * i4.w;
            acc[2][0] += w4.z * i4.x; acc[2][1] += w4.z * i4.y; acc[2][2] += w4.z * i4.z; acc[2][3] += w4.z * i4.w;
            acc[3][0] += w4.w * i4.x; acc[3][1] += w4.w * i4.y; acc[3][2] += w4.w * i4.z; acc[3][3] += w4.w * i4.w;
        }
    }
    float* dstp = g_feat[dst];
    const float* rp1 = g_feat[r1];
    const float* rp2 = (r2 >= 0) ? g_feat[r2] : 0;
#pragma unroll
    for (int o = 0; o < 4; o++) {
        int oc = ocg * 4 + o;
        float bi = bias[oc];
#pragma unroll
        for (int p = 0; p < 4; p++) {
            int idx = oc * SP + p0 + pg * 4 + p;
            float v = acc[o][p] + bi + rp1[idx];
            if (rp2) v += rp2[idx];
            dstp[idx] = v;
        }
    }
}

__global__ void __launch_bounds__(256) k_xg(int fi) {
    __shared__ float sf[1024];
    const float* f = g_feat[fi];
    const int ag = threadIdx.x >> 4, bg = threadIdx.x & 15;
    float acc[4][4] = {};
    float sacc[4] = {};
    const int tok0 = blockIdx.x * 144;
    for (int tb = 0; tb < 144; tb += 16) {
        __syncthreads();
        for (int t2 = threadIdx.x; t2 < 1024; t2 += 256) sf[t2] = f[(tok0 + tb) * 64 + t2];
        __syncthreads();
#pragma unroll
        for (int tk = 0; tk < 16; tk++) {
            float4 fa = *(const float4*)&sf[tk * 64 + ag * 4];
            float4 fb = *(const float4*)&sf[tk * 64 + bg * 4];
            acc[0][0] += fa.x * fb.x; acc[0][1] += fa.x * fb.y; acc[0][2] += fa.x * fb.z; acc[0][3] += fa.x * fb.w;
            acc[1][0] += fa.y * fb.x; acc[1][1] += fa.y * fb.y; acc[1][2] += fa.y * fb.z; acc[1][3] += fa.y * fb.w;
            acc[2][0] += fa.z * fb.x; acc[2][1] += fa.z * fb.y; acc[2][2] += fa.z * fb.z; acc[2][3] += fa.z * fb.w;
            acc[3][0] += fa.w * fb.x; acc[3][1] += fa.w * fb.y; acc[3][2] += fa.w * fb.z; acc[3][3] += fa.w * fb.w;
            if (ag == 0) { sacc[0] += fb.x; sacc[1] += fb.y; sacc[2] += fb.z; sacc[3] += fb.w; }
        }
    }
    for (int i2 = 0; i2 < 4; i2++)
        for (int j2 = 0; j2 < 4; j2++)
            atomicAdd(&g_G[(ag * 4 + i2) * 64 + bg * 4 + j2], acc[i2][j2]);
    if (ag == 0)
        for (int j2 = 0; j2 < 4; j2++) atomicAdd(&g_s[bg * 4 + j2], sacc[j2]);
}

__global__ void __launch_bounds__(256) k_xatt(const float* __restrict__ Qw, const float* __restrict__ Qb,
                                              const float* __restrict__ Kw, const float* __restrict__ Kb,
                                              const float* __restrict__ Vw, const float* __restrict__ Vb,
                                              float scale) {
    __shared__ float sA[4096];
    __shared__ float sGK[4096];
    __shared__ float ss[64], sQs[64], sKs[64];
    const int t = threadIdx.x;
    for (int i = t; i < 4096; i += 256) sA[i] = g_G[i];
    if (t < 64) ss[t] = g_s[t];
    __syncthreads();
    if (t < 64) {
        float q = 0.f;
        for (int a2 = 0; a2 < 64; a2++) q += Qw[t * 64 + a2] * ss[a2];
        sQs[t] = q;
    } else if (t < 128) {
        int d = t - 64; float q = 0.f;
        for (int b2 = 0; b2 < 64; b2++) q += Kw[d * 64 + b2] * ss[b2];
        sKs[d] = q;
    }
    for (int i = t; i < 4096; i += 256) {
        int a2 = i >> 6, d = i & 63;
        float s2 = 0.f;
        for (int b2 = 0; b2 < 64; b2++) s2 += sA[a2 * 64 + b2] * Kw[d * 64 + b2];
        sGK[i] = s2;
    }
    __syncthreads();
    // zero g_G / g_s for the next xblock (contents already captured in sA/sGK)
    for (int i = t; i < 4096; i += 256) g_G[i] = 0.f;
    if (t < 64) g_s[t] = 0.f;
    for (int i = t; i < 4096; i += 256) {
        int c = i >> 6, d = i & 63;
        float s2 = Qb[c] * sKs[d] + sQs[c] * Kb[d] + 9216.0f * Qb[c] * Kb[d];
        for (int a2 = 0; a2 < 64; a2++) s2 += Qw[c * 64 + a2] * sGK[a2 * 64 + d];
        sA[i] = s2 * scale;
    }
    __syncthreads();
    if (t < 64) {
        float mx = -1e30f;
        for (int d = 0; d < 64; d++) mx = fmaxf(mx, sA[t * 64 + d]);
        float sm = 0.f;
        for (int d = 0; d < 64; d++) { float e = expf(sA[t * 64 + d] - mx); sA[t * 64 + d] = e; sm += e; }
        float r = 1.0f / sm;
        for (int d = 0; d < 64; d++) sA[t * 64 + d] *= r;
    }
    __syncthreads();
    for (int i = t; i < 4096; i += 256) {
        int a2 = i >> 6, d = i & 63;
        float s2 = 0.f;
        for (int c = 0; c < 64; c++) s2 += Vw[c * 64 + a2] * sA[c * 64 + d];
        g_M[i] = s2;
    }
    if (t < 64) {
        float s2 = 0.f;
        for (int c = 0; c < 64; c++) s2 += Vb[c] * sA[c * 64 + t];
        g_bias[t] = s2;
    }
}

__global__ void __launch_bounds__(256) k_xapply(int fi, int dst) {
    __shared__ float sM[4096];
    __shared__ float sb[64];
    __shared__ float sf[2048];
    for (int t = threadIdx.x; t < 4096; t += 256) sM[t] = g_M[t];
    if (threadIdx.x < 64) sb[threadIdx.x] = g_bias[threadIdx.x];
    const int tok0 = blockIdx.x * 32;
    const float* f = g_feat[fi];
    for (int t = threadIdx.x; t < 2048; t += 256) sf[t] = f[tok0 * 64 + t];
    __syncthreads();
    const int tk = threadIdx.x >> 3, dg = threadIdx.x & 7;
    float acc[8] = {};
#pragma unroll 8
    for (int a2 = 0; a2 < 64; a2++) {
        float fa = sf[tk * 64 + a2];
        float4 m0 = *(const float4*)&sM[a2 * 64 + dg * 8];
        float4 m1 = *(const float4*)&sM[a2 * 64 + dg * 8 + 4];
        acc[0] += fa * m0.x; acc[1] += fa * m0.y; acc[2] += fa * m0.z; acc[3] += fa * m0.w;
        acc[4] += fa * m1.x; acc[5] += fa * m1.y; acc[6] += fa * m1.z; acc[7] += fa * m1.w;
    }
    float* dp = g_feat[dst];
    const int base = (tok0 + tk) * 64 + dg * 8;
#pragma unroll
    for (int d2 = 0; d2 < 8; d2++) dp[base + d2] = sf[tk * 64 + dg * 8 + d2] + acc[d2] + sb[dg * 8 + d2];
}

__global__ void __launch_bounds__(256) k_op(int fi, int oi, const float* __restrict__ w,
                                            const float* __restrict__ bb) {
    __shared__ float sw[576];
    for (int t = threadIdx.x; t < 576; t += 256) {
        int ch = t / 9, k2 = t % 9; int a = k2 / 3, b2 = k2 % 3;
        sw[t] = w[ch * 9 + (2 - a) * 3 + (2 - b2)];
    }
    __syncthreads();
    int idx = blockIdx.x * 256 + threadIdx.x;
    if (idx >= SP) return;
    int u = idx / 96, v = idx % 96;
    const float* x = g_feat[fi];
    float acc = bb[0];
    for (int ch = 0; ch < 64; ch++) {
#pragma unroll
        for (int a = 0; a < 3; a++) {
            int y = u + a - 1; if ((unsigned)y >= 96u) continue;
#pragma unroll
            for (int b2 = 0; b2 < 3; b2++) {
                int xx = v + b2 - 1; if ((unsigned)xx >= 96u) continue;
                acc += x[ch * SP + y * 96 + xx] * sw[ch * 9 + a * 3 + b2];
            }
        }
    }
    g_opout[oi][v * 96 + u] = acc;
}

__global__ void __launch_bounds__(256) k_idwt(const float* __restrict__ img, float* __restrict__ out) {
    int idx = blockIdx.x * 256 + threadIdx.x;
    if (idx >= SP) return;
    int i = idx / 96, j = idx % 96;
    float a = g_opout[0][idx], b = g_opout[1][idx], c = g_opout[2][idx], d = g_opout[3][idx];
    int r0 = (2 * i) * 192 + 2 * j;
    int r1 = (2 * i + 1) * 192 + 2 * j;
    out[r0]     = 0.5f * (a + b + c + d) + img[r0];
    out[r0 + 1] = 0.5f * (a - b + c - d) + img[r0 + 1];
    out[r1]     = 0.5f * (a + b - c - d) + img[r1];
    out[r1 + 1] = 0.5f * (a - b - c + d) + img[r1 + 1];
}

extern "C" void kernel_launch(void* const* d_in, const int* in_sizes, int n_in,
                              void* d_out, int out_size) {
    (void)in_sizes; (void)n_in; (void)out_size;
    const float* images = (const float*)d_in[0];
    const float* ip_w  = (const float*)d_in[1];
    const float* ip_b  = (const float*)d_in[2];
    const float* op_w  = (const float*)d_in[3];
    const float* op_b  = (const float*)d_in[4];
    const float* cb_dw = (const float*)d_in[5];
    const float* cb_pw = (const float*)d_in[6];
    const float* cb_l1w = (const float*)d_in[7];
    const float* cb_l1b = (const float*)d_in[8];
    const float* cb_l2w = (const float*)d_in[9];
    const float* cb_l2b = (const float*)d_in[10];
    const float* xqw = (const float*)d_in[11];
    const float* xqb = (const float*)d_in[12];
    const float* xkw = (const float*)d_in[13];
    const float* xkb = (const float*)d_in[14];
    const float* xvw = (const float*)d_in[15];
    const float* xvb = (const float*)d_in[16];
    float* out = (float*)d_out;

    cudaFuncSetAttribute(k_l1mma, cudaFuncAttributeMaxDynamicSharedMemorySize, L1_SMEMB);

    k_dwt<<<36, 256>>>(images);
    k_l1wtb<<<(6 * 16 * 2 * 14 * 128 * 8 + 255) / 256, 256>>>(cb_l1w);

    auto cb = [&](int blk, int src, int r2, int dst) {
        k_dw7<<<dim3(7, 7, 64), 256>>>(src, cb_dw + blk * 3136);
        k_pw<<<163, 256>>>(cb_pw + blk * 4096);
        k_l1mma<<<dim3(12, 6, 2), 256, L1_SMEMB>>>(blk, cb_l1b + blk * 256);
        k_l2<<<144, 256>>>(cb_l2w + blk * 16384, cb_l2b + blk * 64, src, r2, dst);
    };
    auto xb = [&](int i, int src, int dst, float scale) {
        k_xg<<<64, 256>>>(src);
        k_xatt<<<1, 256>>>(xqw + i * 4096, xqb + i * 64, xkw + i * 4096, xkb + i * 64,
                           xvw + i * 4096, xvb + i * 64, scale);
        k_xapply<<<288, 256>>>(src, dst);
    };

    k_ip<<<2304, 256>>>(0, 0, ip_w, ip_b);
    cb(0, 0, -1, 1);
    cb(1, 1, 1, 2);
    xb(0, 1, 3, 0.44721359549995793f);
    cb(2, 3, 2, 4);
    cb(3, 4, 1, 5);
    k_op<<<36, 256>>>(5, 0, op_w, op_b);

    for (int bi = 1; bi <= 3; bi++) {
        k_ip<<<2304, 256>>>(bi, 6, ip_w, ip_b);
        cb(4, 6, -1, 7);
        xb(1, 7, 3, 0.70710678118654752f);
        cb(5, 3, 7, 4);
        k_op<<<36, 256>>>(4, bi, op_w, op_b);
    }
    k_idwt<<<36, 256>>>(images, out);
}

// round 9
// speedup vs baseline: 3.8809x; 1.2570x over previous
#include <cuda_runtime.h>
#include <cuda_bf16.h>
#include <math.h>
#include <stdint.h>

#define CC 64
#define SP 9216
#define PP 102
#define SPP 10404
#define NLN 665856
#define CSPP (CC * SPP)
#define L1OSZ (4 * CC * SP)

typedef unsigned long long u64t;

// ---------------- scratch ----------------
__device__ float g_band[4][SP];
__device__ float g_opout[4][SP];
__device__ float g_feat[8][CC * SP];
__device__ float g_dwo[3 * CSPP];
__device__ float g_pwo[3 * CSPP];
__device__ float g_l1o[3 * L1OSZ];
// bf16-packed l1 weights: [blk][icg 16][ochalf 2][seg 14 (pair*7+a)][oc 128][q 8] u32
__device__ __align__(16) uint32_t g_l1w_bf[6 * 16 * 2 * 14 * 128 * 8];
__device__ float g_red[6];          // per-band (sum, sumsq)
__device__ float g_G[3 * 4096];
__device__ float g_s[3 * 64];
__device__ float g_M[3 * 4096];
__device__ float g_bias[3 * 64];

__device__ __forceinline__ float gelu(float x) {
    return 0.5f * x * (1.0f + erff(x * 0.70710678118654752f));
}
__device__ __forceinline__ void mma_bf16(float* c, uint32_t a0, uint32_t a1, uint32_t a2,
                                         uint32_t a3, uint32_t b0, uint32_t b1) {
    asm volatile(
        "mma.sync.aligned.m16n8k16.row.col.f32.bf16.bf16.f32 "
        "{%0,%1,%2,%3}, {%4,%5,%6,%7}, {%8,%9}, {%0,%1,%2,%3};"
        : "+f"(c[0]), "+f"(c[1]), "+f"(c[2]), "+f"(c[3])
        : "r"(a0), "r"(a1), "r"(a2), "r"(a3), "r"(b0), "r"(b1));
}

// ---------------- DWT (+ zero attention accumulators) ----------------
__global__ void __launch_bounds__(256) k_dwt(const float* __restrict__ img) {
    if (blockIdx.x == 0) {
        for (int t = threadIdx.x; t < 3 * 4096; t += 256) g_G[t] = 0.f;
        for (int t = threadIdx.x; t < 192; t += 256) g_s[t] = 0.f;
    }
    int idx = blockIdx.x * 256 + threadIdx.x;
    if (idx >= SP) return;
    int i = idx / 96, j = idx % 96;
    float a = img[(2 * i) * 192 + 2 * j];
    float b = img[(2 * i + 1) * 192 + 2 * j];
    float c = img[(2 * i) * 192 + 2 * j + 1];
    float d = img[(2 * i + 1) * 192 + 2 * j + 1];
    g_band[0][idx] = (a + b + c + d) * 0.5f;
    g_band[1][idx] = (a + b - c - d) * 0.5f;
    g_band[2][idx] = (a - b + c - d) * 0.5f;
    g_band[3][idx] = (a - b - c + d) * 0.5f;
}

// ---------------- l1 weight prepack to bf16 ----------------
__global__ void __launch_bounds__(256) k_l1wtb(const float* __restrict__ w) {
    int idx = blockIdx.x * 256 + threadIdx.x;
    const int total = 6 * 16 * 2 * 14 * 128 * 8;
    if (idx >= total) return;
    int q = idx & 7;
    int j4 = q >> 1, h = q & 1;
    int t = idx >> 3;
    int oc_l = t & 127; t >>= 7;
    int seg = t % 14; t /= 14;
    int ochalf = t & 1; t >>= 1;
    int icg = t & 15;
    int blk = t >> 4;
    int pair = seg / 7, a = seg % 7;
    int ic = icg * 4 + pair * 2 + h;
    int oc = ochalf * 128 + oc_l;
    int b0t = 2 * j4, b1t = 2 * j4 + 1;
    const float* wb = w + ((size_t)(blk * 256 + oc) * 64 + ic) * 49 + a * 7;
    float w0 = wb[b0t];
    float w1 = (b1t < 7) ? wb[b1t] : 0.f;
    uint32_t lo = __bfloat16_as_ushort(__float2bfloat16(w0));
    uint32_t hi = __bfloat16_as_ushort(__float2bfloat16(w1));
    g_l1w_bf[idx] = lo | (hi << 16);
}

// ---------------- ip: band -> feat, batched over gridDim.y bands ----------------
__global__ void __launch_bounds__(256) k_ip(int bi0, int fi0, const float* __restrict__ w,
                                            const float* __restrict__ bb) {
    __shared__ float sw[576];
    __shared__ float sb2[64];
    const int band = blockIdx.y;
    for (int t = threadIdx.x; t < 576; t += 256) sw[t] = w[t];
    if (threadIdx.x < 64) sb2[threadIdx.x] = bb[threadIdx.x];
    __syncthreads();
    int idx = blockIdx.x * 256 + threadIdx.x;
    if (idx >= CC * SP) return;
    int v = idx % 96; int u = (idx / 96) % 96; int ch = idx / SP;
    const float* src = g_band[bi0 + band];
    float acc = sb2[ch];
#pragma unroll
    for (int a = 0; a < 3; a++) {
        int x0 = u + a - 1;
        if ((unsigned)x0 < 96u) {
#pragma unroll
            for (int b2 = 0; b2 < 3; b2++) {
                int y0 = v + b2 - 1;
                if ((unsigned)y0 < 96u) acc += src[y0 * 96 + x0] * sw[ch * 9 + a * 3 + b2];
            }
        }
    }
    g_feat[fi0 + band * 2][idx] = acc;
}

// ---------------- depthwise 7x7 (+ zero LN reduction), batched (z = band*64+ch) ---------
__global__ void __launch_bounds__(256) k_dw7(int fi0, int fstep, const float* __restrict__ dww) {
    __shared__ float sw[49];
    __shared__ float spt[484];
    const int band = blockIdx.z >> 6;
    const int ch = blockIdx.z & 63;
    if (blockIdx.x == 0 && blockIdx.y == 0 && ch == 0 && threadIdx.x < 2)
        g_red[band * 2 + threadIdx.x] = 0.f;
    const int ty0 = blockIdx.y * 16, tx0 = blockIdx.x * 16;
    if (threadIdx.x < 49) sw[threadIdx.x] = dww[ch * 49 + threadIdx.x];
    const float* src = g_feat[fi0 + band * fstep] + ch * SP;
    for (int t = threadIdx.x; t < 484; t += 256) {
        int r = t / 22, c2 = t % 22;
        int gy = ty0 - 6 + r, gx = tx0 - 6 + c2;
        spt[t] = (gy >= 0 && gy < 96 && gx >= 0 && gx < 96) ? src[gy * 96 + gx] : 0.f;
    }
    __syncthreads();
    int ly = threadIdx.x / 16, lx = threadIdx.x % 16;
    int oy = ty0 + ly, ox = tx0 + lx;
    if (oy >= PP || ox >= PP) return;
    float acc = 0.f;
#pragma unroll
    for (int a = 0; a < 7; a++)
#pragma unroll
        for (int b = 0; b < 7; b++)
            acc += spt[(ly + a) * 22 + lx + b] * sw[a * 7 + b];
    g_dwo[band * CSPP + ch * SPP + oy * PP + ox] = acc;
}

// ---------------- pointwise 64->64 + per-band LN reduction, batched ----------------
__global__ void __launch_bounds__(256) k_pw(const float* __restrict__ W) {
    __shared__ float swT[64 * 68];
    __shared__ float sin_[4096];
    __shared__ float sr[2][8];
    const int band = blockIdx.y;
    const float* dwo = g_dwo + band * CSPP;
    float* pwo = g_pwo + band * CSPP;
    const int p0 = blockIdx.x * 64;
    for (int t = threadIdx.x; t < 4096; t += 256) {
        int co = t >> 6, ci = t & 63;
        swT[ci * 68 + co] = W[t];
    }
    for (int t = threadIdx.x; t < 4096; t += 256) {
        int ci = t >> 6, p = t & 63; int gp = p0 + p;
        sin_[t] = (gp < SPP) ? dwo[ci * SPP + gp] : 0.f;
    }
    __syncthreads();
    const int ocg = threadIdx.x >> 4, pg = threadIdx.x & 15;
    float acc[4][4] = {};
#pragma unroll 4
    for (int ci = 0; ci < 64; ci++) {
        float4 w4 = *(const float4*)&swT[ci * 68 + ocg * 4];
        float4 i4 = *(const float4*)&sin_[ci * 64 + pg * 4];
        acc[0][0] += w4.x * i4.x; acc[0][1] += w4.x * i4.y; acc[0][2] += w4.x * i4.z; acc[0][3] += w4.x * i4.w;
        acc[1][0] += w4.y * i4.x; acc[1][1] += w4.y * i4.y; acc[1][2] += w4.y * i4.z; acc[1][3] += w4.y * i4.w;
        acc[2][0] += w4.z * i4.x; acc[2][1] += w4.z * i4.y; acc[2][2] += w4.z * i4.z; acc[2][3] += w4.z * i4.w;
        acc[3][0] += w4.w * i4.x; acc[3][1] += w4.w * i4.y; acc[3][2] += w4.w * i4.z; acc[3][3] += w4.w * i4.w;
    }
    float ls = 0.f, ls2 = 0.f;
#pragma unroll
    for (int o = 0; o < 4; o++) {
        int oc = ocg * 4 + o;
#pragma unroll
        for (int p = 0; p < 4; p++) {
            int gp = p0 + pg * 4 + p;
            if (gp < SPP) {
                float v = acc[o][p];
                pwo[oc * SPP + gp] = v;
                ls += v; ls2 += v * v;
            }
        }
    }
    for (int off = 16; off; off >>= 1) {
        ls += __shfl_down_sync(0xffffffffu, ls, off);
        ls2 += __shfl_down_sync(0xffffffffu, ls2, off);
    }
    if ((threadIdx.x & 31) == 0) { sr[0][threadIdx.x >> 5] = ls; sr[1][threadIdx.x >> 5] = ls2; }
    __syncthreads();
    if (threadIdx.x == 0) {
        float a = 0.f, b = 0.f;
        for (int w2 = 0; w2 < 8; w2++) { a += sr[0][w2]; b += sr[1][w2]; }
        atomicAdd(&g_red[band * 2], a); atomicAdd(&g_red[band * 2 + 1], b);
    }
}

// ---------------- l1 via bf16 mma, batched (z = band*2 + ochalf) ----------------
#define L1_WBUF 14336
#define L1_IN   1408
#define L1_SMEMB ((L1_WBUF + L1_IN) * 4)

__global__ void __launch_bounds__(256) k_l1mma(int blk, const float* __restrict__ l1b) {
    extern __shared__ uint32_t sm[];
    uint32_t* s_in = sm + L1_WBUF;
    const int tid = threadIdx.x;
    const int tx = blockIdx.x * 8, ty = blockIdx.y * 16;
    const int band = blockIdx.z >> 1;
    const int ochalf = blockIdx.z & 1;
    const int wid = tid >> 5, lane = tid & 31;
    const int ocg = wid >> 1, pxg = wid & 1;
    const int g = lane >> 2, j4 = lane & 3;

    const float m = g_red[band * 2] * (1.0f / (float)NLN);
    const float inv = rsqrtf(g_red[band * 2 + 1] * (1.0f / (float)NLN) - m * m + 1e-5f);
    const float* pwo = g_pwo + band * CSPP;
    float* l1o = g_l1o + band * L1OSZ;

    for (int t = tid; t < L1_IN; t += 256) s_in[t] = 0u;

    float c[2][8][4] = {};
    unsigned short* s_ine = (unsigned short*)s_in;
    unsigned short* s_ino = (unsigned short*)(s_in + 704);

    for (int icg = 0; icg < 16; icg++) {
        __syncthreads();
        {
            size_t chunk = ((size_t)(blk * 16 + icg) * 2 + ochalf) * L1_WBUF;
            const uint4* src = (const uint4*)(g_l1w_bf + chunk);
            uint4* dstw = (uint4*)sm;
#pragma unroll
            for (int i = 0; i < 14; i++)
                dstw[tid + i * 256] = src[tid + i * 256];
        }
        for (int t = tid; t < 1232; t += 256) {
            int ic = t / 308, r2 = t % 308;
            int r = r2 / 14, cx = r2 % 14;
            float v = (pwo[(icg * 4 + ic) * SPP + (ty + r) * PP + (tx + cx)] - m) * inv;
            unsigned short hb = __bfloat16_as_ushort(__float2bfloat16(v));
            int rowb = (ic * 22 + r) * 16;
            s_ine[rowb + cx] = hb;
            if (cx >= 1) s_ino[rowb + cx - 1] = hb;
        }
        __syncthreads();

        const uint32_t* wb = sm;
        const int r0 = ocg * 32 + g;
        const uint32_t* pbase = s_in + (g & 1) * 704 + ((g >> 1) + j4);
#pragma unroll
        for (int pair = 0; pair < 2; pair++) {
#pragma unroll
            for (int a = 0; a < 7; a++) {
                const uint32_t* ws = wb + (pair * 7 + a) * 1024 + 2 * j4;
                u64t A0lo = *(const u64t*)(ws + r0 * 8);
                u64t A0hi = *(const u64t*)(ws + (r0 + 8) * 8);
                u64t A1lo = *(const u64t*)(ws + (r0 + 16) * 8);
                u64t A1hi = *(const u64t*)(ws + (r0 + 24) * 8);
                uint32_t a00 = (uint32_t)A0lo, a02 = (uint32_t)(A0lo >> 32);
                uint32_t a01 = (uint32_t)A0hi, a03 = (uint32_t)(A0hi >> 32);
                uint32_t a10 = (uint32_t)A1lo, a12 = (uint32_t)(A1lo >> 32);
                uint32_t a11 = (uint32_t)A1hi, a13 = (uint32_t)(A1hi >> 32);
                const uint32_t* p0 = pbase + (pair * 2) * 176 + (pxg * 8 + a) * 8;
                const uint32_t* p1 = p0 + 176;
#pragma unroll
                for (int j = 0; j < 8; j++) {
                    uint32_t b0 = p0[j * 8], b1 = p1[j * 8];
                    mma_bf16(c[0][j], a00, a01, a02, a03, b0, b1);
                    mma_bf16(c[1][j], a10, a11, a12, a13, b0, b1);
                }
            }
        }
    }

#pragma unroll
    for (int mm = 0; mm < 2; mm++) {
        int ocb = ochalf * 128 + ocg * 32 + mm * 16 + g;
        float b_lo = l1b[ocb], b_hi = l1b[ocb + 8];
#pragma unroll
        for (int j = 0; j < 8; j++) {
            int y = ty + pxg * 8 + j;
            int xb = tx + 2 * j4;
            float* o_lo = &l1o[ocb * SP + y * 96 + xb];
            float* o_hi = &l1o[(ocb + 8) * SP + y * 96 + xb];
            o_lo[0] = gelu(c[mm][j][0] + b_lo);
            o_lo[1] = gelu(c[mm][j][1] + b_lo);
            o_hi[0] = gelu(c[mm][j][2] + b_hi);
            o_hi[1] = gelu(c[mm][j][3] + b_hi);
        }
    }
}

// ---------------- l2: 1x1 256->64 + bias + residual(s), batched ----------------
__global__ void __launch_bounds__(256) k_l2(const float* __restrict__ W, const float* __restrict__ bias,
                                            int r1_0, int r2_0, int d0, int fstep) {
    __shared__ float swT[64 * 68];
    __shared__ float sin_[4096];
    const int band = blockIdx.y;
    const float* l1o = g_l1o + band * L1OSZ;
    const int p0 = blockIdx.x * 64;
    const int ocg = threadIdx.x >> 4, pg = threadIdx.x & 15;
    float acc[4][4] = {};
    for (int c0 = 0; c0 < 256; c0 += 64) {
        __syncthreads();
        for (int t = threadIdx.x; t < 4096; t += 256) {
            int co = t >> 6, ci = t & 63;
            swT[ci * 68 + co] = W[co * 256 + c0 + ci];
        }
        for (int t = threadIdx.x; t < 4096; t += 256) {
            int ci = t >> 6, p = t & 63;
            sin_[t] = l1o[(c0 + ci) * SP + p0 + p];
        }
        __syncthreads();
#pragma unroll 4
        for (int ci = 0; ci < 64; ci++) {
            float4 w4 = *(const float4*)&swT[ci * 68 + ocg * 4];
            float4 i4 = *(const float4*)&sin_[ci * 64 + pg * 4];
            acc[0][0] += w4.x * i4.x; acc[0][1] += w4.x * i4.y; acc[0][2] += w4.x * i4.z; acc[0][3] += w4.x * i4.w;
            acc[1][0] += w4.y * i4.x; acc[1][1] += w4.y * i4.y; acc[1][2] += w4.y * i4.z; acc[1][3] += w4.y * i4.w;
            acc[2][0] += w4.z * i4.x; acc[2][1] += w4.z * i4.y; acc[2][2] += w4.z * i4.z; acc[2][3] += w4.z * i4.w;
            acc[3][0] += w4.w * i4.x; acc[3][1] += w4.w * i4.y; acc[3][2] += w4.w * i4.z; acc[3][3] += w4.w * i4.w;
        }
    }
    float* dstp = g_feat[d0 + band * fstep];
    const float* rp1 = g_feat[r1_0 + band * fstep];
    const float* rp2 = (r2_0 >= 0) ? g_feat[r2_0 + band * fstep] : 0;
#pragma unroll
    for (int o = 0; o < 4; o++) {
        int oc = ocg * 4 + o;
        float bi = bias[oc];
#pragma unroll
        for (int p = 0; p < 4; p++) {
            int idx = oc * SP + p0 + pg * 4 + p;
            float v = acc[o][p] + bi + rp1[idx];
            if (rp2) v += rp2[idx];
            dstp[idx] = v;
        }
    }
}

// ---------------- xblock Gram + row-sum, batched ----------------
__global__ void __launch_bounds__(256) k_xg(int f0, int fstep) {
    __shared__ float sf[1024];
    const int band = blockIdx.y;
    const float* f = g_feat[f0 + band * fstep];
    float* Gp = g_G + band * 4096;
    float* sp = g_s + band * 64;
    const int ag = threadIdx.x >> 4, bg = threadIdx.x & 15;
    float acc[4][4] = {};
    float sacc[4] = {};
    const int tok0 = blockIdx.x * 144;
    for (int tb = 0; tb < 144; tb += 16) {
        __syncthreads();
        for (int t2 = threadIdx.x; t2 < 1024; t2 += 256) sf[t2] = f[(tok0 + tb) * 64 + t2];
        __syncthreads();
#pragma unroll
        for (int tk = 0; tk < 16; tk++) {
            float4 fa = *(const float4*)&sf[tk * 64 + ag * 4];
            float4 fb = *(const float4*)&sf[tk * 64 + bg * 4];
            acc[0][0] += fa.x * fb.x; acc[0][1] += fa.x * fb.y; acc[0][2] += fa.x * fb.z; acc[0][3] += fa.x * fb.w;
            acc[1][0] += fa.y * fb.x; acc[1][1] += fa.y * fb.y; acc[1][2] += fa.y * fb.z; acc[1][3] += fa.y * fb.w;
            acc[2][0] += fa.z * fb.x; acc[2][1] += fa.z * fb.y; acc[2][2] += fa.z * fb.z; acc[2][3] += fa.z * fb.w;
            acc[3][0] += fa.w * fb.x; acc[3][1] += fa.w * fb.y; acc[3][2] += fa.w * fb.z; acc[3][3] += fa.w * fb.w;
            if (ag == 0) { sacc[0] += fb.x; sacc[1] += fb.y; sacc[2] += fb.z; sacc[3] += fb.w; }
        }
    }
    for (int i2 = 0; i2 < 4; i2++)
        for (int j2 = 0; j2 < 4; j2++)
            atomicAdd(&Gp[(ag * 4 + i2) * 64 + bg * 4 + j2], acc[i2][j2]);
    if (ag == 0)
        for (int j2 = 0; j2 < 4; j2++) atomicAdd(&sp[bg * 4 + j2], sacc[j2]);
}

// ---------------- attention core, batched (blockIdx.x = band) ----------------
__global__ void __launch_bounds__(256) k_xatt(const float* __restrict__ Qw, const float* __restrict__ Qb,
                                              const float* __restrict__ Kw, const float* __restrict__ Kb,
                                              const float* __restrict__ Vw, const float* __restrict__ Vb,
                                              float scale) {
    __shared__ float sA[4096];
    __shared__ float sGK[4096];
    __shared__ float ss[64], sQs[64], sKs[64];
    const int band = blockIdx.x;
    float* Gp = g_G + band * 4096;
    float* sp = g_s + band * 64;
    const int t = threadIdx.x;
    for (int i = t; i < 4096; i += 256) sA[i] = Gp[i];
    if (t < 64) ss[t] = sp[t];
    __syncthreads();
    if (t < 64) {
        float q = 0.f;
        for (int a2 = 0; a2 < 64; a2++) q += Qw[t * 64 + a2] * ss[a2];
        sQs[t] = q;
    } else if (t < 128) {
        int d = t - 64; float q = 0.f;
        for (int b2 = 0; b2 < 64; b2++) q += Kw[d * 64 + b2] * ss[b2];
        sKs[d] = q;
    }
    for (int i = t; i < 4096; i += 256) {
        int a2 = i >> 6, d = i & 63;
        float s2 = 0.f;
        for (int b2 = 0; b2 < 64; b2++) s2 += sA[a2 * 64 + b2] * Kw[d * 64 + b2];
        sGK[i] = s2;
    }
    __syncthreads();
    // zero this band's G/s for the next use (contents captured in sA/sGK)
    for (int i = t; i < 4096; i += 256) Gp[i] = 0.f;
    if (t < 64) sp[t] = 0.f;
    for (int i = t; i < 4096; i += 256) {
        int c = i >> 6, d = i & 63;
        float s2 = Qb[c] * sKs[d] + sQs[c] * Kb[d] + 9216.0f * Qb[c] * Kb[d];
        for (int a2 = 0; a2 < 64; a2++) s2 += Qw[c * 64 + a2] * sGK[a2 * 64 + d];
        sA[i] = s2 * scale;
    }
    __syncthreads();
    if (t < 64) {
        float mx = -1e30f;
        for (int d = 0; d < 64; d++) mx = fmaxf(mx, sA[t * 64 + d]);
        float sm = 0.f;
        for (int d = 0; d < 64; d++) { float e = expf(sA[t * 64 + d] - mx); sA[t * 64 + d] = e; sm += e; }
        float r = 1.0f / sm;
        for (int d = 0; d < 64; d++) sA[t * 64 + d] *= r;
    }
    __syncthreads();
    for (int i = t; i < 4096; i += 256) {
        int a2 = i >> 6, d = i & 63;
        float s2 = 0.f;
        for (int c = 0; c < 64; c++) s2 += Vw[c * 64 + a2] * sA[c * 64 + d];
        g_M[band * 4096 + i] = s2;
    }
    if (t < 64) {
        float s2 = 0.f;
        for (int c = 0; c < 64; c++) s2 += Vb[c] * sA[c * 64 + t];
        g_bias[band * 64 + t] = s2;
    }
}

// ---------------- xblock apply, batched ----------------
__global__ void __launch_bounds__(256) k_xapply(int f0, int fstep, int d0) {
    __shared__ float sM[4096];
    __shared__ float sb[64];
    __shared__ float sf[2048];
    const int band = blockIdx.y;
    for (int t = threadIdx.x; t < 4096; t += 256) sM[t] = g_M[band * 4096 + t];
    if (threadIdx.x < 64) sb[threadIdx.x] = g_bias[band * 64 + threadIdx.x];
    const int tok0 = blockIdx.x * 32;
    const float* f = g_feat[f0 + band * fstep];
    for (int t = threadIdx.x; t < 2048; t += 256) sf[t] = f[tok0 * 64 + t];
    __syncthreads();
    const int tk = threadIdx.x >> 3, dg = threadIdx.x & 7;
    float acc[8] = {};
#pragma unroll 8
    for (int a2 = 0; a2 < 64; a2++) {
        float fa = sf[tk * 64 + a2];
        float4 m0 = *(const float4*)&sM[a2 * 64 + dg * 8];
        float4 m1 = *(const float4*)&sM[a2 * 64 + dg * 8 + 4];
        acc[0] += fa * m0.x; acc[1] += fa * m0.y; acc[2] += fa * m0.z; acc[3] += fa * m0.w;
        acc[4] += fa * m1.x; acc[5] += fa * m1.y; acc[6] += fa * m1.z; acc[7] += fa * m1.w;
    }
    float* dp = g_feat[d0 + band * fstep];
    const int base = (tok0 + tk) * 64 + dg * 8;
#pragma unroll
    for (int d2 = 0; d2 < 8; d2++) dp[base + d2] = sf[tk * 64 + dg * 8 + d2] + acc[d2] + sb[dg * 8 + d2];
}

// ---------------- op, batched ----------------
__global__ void __launch_bounds__(256) k_op(int f0, int fstep, int oi0, const float* __restrict__ w,
                                            const float* __restrict__ bb) {
    __shared__ float sw[576];
    const int band = blockIdx.y;
    for (int t = threadIdx.x; t < 576; t += 256) {
        int ch = t / 9, k2 = t % 9; int a = k2 / 3, b2 = k2 % 3;
        sw[t] = w[ch * 9 + (2 - a) * 3 + (2 - b2)];
    }
    __syncthreads();
    int idx = blockIdx.x * 256 + threadIdx.x;
    if (idx >= SP) return;
    int u = idx / 96, v = idx % 96;
    const float* x = g_feat[f0 + band * fstep];
    float acc = bb[0];
    for (int ch = 0; ch < 64; ch++) {
#pragma unroll
        for (int a = 0; a < 3; a++) {
            int y = u + a - 1; if ((unsigned)y >= 96u) continue;
#pragma unroll
            for (int b2 = 0; b2 < 3; b2++) {
                int xx = v + b2 - 1; if ((unsigned)xx >= 96u) continue;
                acc += x[ch * SP + y * 96 + xx] * sw[ch * 9 + a * 3 + b2];
            }
        }
    }
    g_opout[oi0 + band][v * 96 + u] = acc;
}

__global__ void __launch_bounds__(256) k_idwt(const float* __restrict__ img, float* __restrict__ out) {
    int idx = blockIdx.x * 256 + threadIdx.x;
    if (idx >= SP) return;
    int i = idx / 96, j = idx % 96;
    float a = g_opout[0][idx], b = g_opout[1][idx], c = g_opout[2][idx], d = g_opout[3][idx];
    int r0 = (2 * i) * 192 + 2 * j;
    int r1 = (2 * i + 1) * 192 + 2 * j;
    out[r0]     = 0.5f * (a + b + c + d) + img[r0];
    out[r0 + 1] = 0.5f * (a - b + c - d) + img[r0 + 1];
    out[r1]     = 0.5f * (a + b - c - d) + img[r1];
    out[r1 + 1] = 0.5f * (a - b - c + d) + img[r1 + 1];
}

extern "C" void kernel_launch(void* const* d_in, const int* in_sizes, int n_in,
                              void* d_out, int out_size) {
    (void)in_sizes; (void)n_in; (void)out_size;
    const float* images = (const float*)d_in[0];
    const float* ip_w  = (const float*)d_in[1];
    const float* ip_b  = (const float*)d_in[2];
    const float* op_w  = (const float*)d_in[3];
    const float* op_b  = (const float*)d_in[4];
    const float* cb_dw = (const float*)d_in[5];
    const float* cb_pw = (const float*)d_in[6];
    const float* cb_l1w = (const float*)d_in[7];
    const float* cb_l1b = (const float*)d_in[8];
    const float* cb_l2w = (const float*)d_in[9];
    const float* cb_l2b = (const float*)d_in[10];
    const float* xqw = (const float*)d_in[11];
    const float* xqb = (const float*)d_in[12];
    const float* xkw = (const float*)d_in[13];
    const float* xkb = (const float*)d_in[14];
    const float* xvw = (const float*)d_in[15];
    const float* xvb = (const float*)d_in[16];
    float* out = (float*)d_out;

    cudaFuncSetAttribute(k_l1mma, cudaFuncAttributeMaxDynamicSharedMemorySize, L1_SMEMB);

    k_dwt<<<36, 256>>>(images);
    k_l1wtb<<<(6 * 16 * 2 * 14 * 128 * 8 + 255) / 256, 256>>>(cb_l1w);

    // cb over nb bands: src/r2/dst are slot indices for band 0; stride fstep per band
    auto cb = [&](int blk, int nb, int src, int r2, int dst, int fstep) {
        k_dw7<<<dim3(7, 7, 64 * nb), 256>>>(src, fstep, cb_dw + blk * 3136);
        k_pw<<<dim3(163, nb), 256>>>(cb_pw + blk * 4096);
        k_l1mma<<<dim3(12, 6, 2 * nb), 256, L1_SMEMB>>>(blk, cb_l1b + blk * 256);
        k_l2<<<dim3(144, nb), 256>>>(cb_l2w + blk * 16384, cb_l2b + blk * 64, src, r2, dst, fstep);
    };
    auto xb = [&](int i, int nb, int src, int dst, int fstep, float scale) {
        k_xg<<<dim3(64, nb), 256>>>(src, fstep);
        k_xatt<<<nb, 256>>>(xqw + i * 4096, xqb + i * 64, xkw + i * 4096, xkb + i * 64,
                            xvw + i * 4096, xvb + i * 64, scale);
        k_xapply<<<dim3(288, nb), 256>>>(src, fstep, dst);
    };

    // ---- low-frequency chain (nb=1, slots 0..5) ----
    k_ip<<<dim3(2304, 1), 256>>>(0, 0, ip_w, ip_b);
    cb(0, 1, 0, -1, 1, 0);
    cb(1, 1, 1, 1, 2, 0);
    xb(0, 1, 1, 3, 0, 0.44721359549995793f);
    cb(2, 1, 3, 2, 4, 0);
    cb(3, 1, 4, 1, 5, 0);
    k_op<<<dim3(36, 1), 256>>>(5, 0, 0, op_w, op_b);

    // ---- high-frequency bands, batched nb=3 (band b: A=2b, B=2b+1) ----
    k_ip<<<dim3(2304, 3), 256>>>(1, 0, ip_w, ip_b);          // A_b = ip(band b+1)
    cb(4, 3, 0, -1, 1, 2);                                   // B_b = cb4(A_b)
    xb(1, 3, 1, 0, 2, 0.70710678118654752f);                 // A_b = xb(B_b)
    cb(5, 3, 0, 1, 1, 2);                                    // B_b = cb5(A_b) + B_b
    k_op<<<dim3(36, 3), 256>>>(1, 2, 1, op_w, op_b);         // opout[1+b]
    k_idwt<<<36, 256>>>(images, out);
}

// round 10
// speedup vs baseline: 4.6668x; 1.2025x over previous
#include <cuda_runtime.h>
#include <cuda_bf16.h>
#include <math.h>
#include <stdint.h>

#define CC 64
#define SP 9216
#define PP 102
#define SPP 10404
#define NLN 665856
#define CSPP (CC * SPP)
#define L1OSZ (4 * CC * SP)

typedef unsigned long long u64t;

__device__ __forceinline__ int m4(int4 v, int i) { return ((const int*)&v)[i]; }

// ---------------- scratch ----------------
__device__ float g_band[4][SP];
__device__ float g_opout[4][SP];
__device__ float g_feat[12][CC * SP];
__device__ float g_dwo[4 * CSPP];
__device__ float g_pwo[4 * CSPP];
__device__ float g_l1o[4 * L1OSZ];
__device__ __align__(16) uint32_t g_l1w_bf[6 * 16 * 2 * 14 * 128 * 8];
__device__ float g_red[8];
__device__ float g_G[4 * 4096];
__device__ float g_s[4 * 64];
__device__ float g_M[4 * 4096];
__device__ float g_bias[4 * 64];

__device__ __forceinline__ float gelu(float x) {
    return 0.5f * x * (1.0f + erff(x * 0.70710678118654752f));
}
__device__ __forceinline__ void mma_bf16(float* c, uint32_t a0, uint32_t a1, uint32_t a2,
                                         uint32_t a3, uint32_t b0, uint32_t b1) {
    asm volatile(
        "mma.sync.aligned.m16n8k16.row.col.f32.bf16.bf16.f32 "
        "{%0,%1,%2,%3}, {%4,%5,%6,%7}, {%8,%9}, {%0,%1,%2,%3};"
        : "+f"(c[0]), "+f"(c[1]), "+f"(c[2]), "+f"(c[3])
        : "r"(a0), "r"(a1), "r"(a2), "r"(a3), "r"(b0), "r"(b1));
}

// ---------------- DWT (+ zero attention accumulators) ----------------
__global__ void __launch_bounds__(256) k_dwt(const float* __restrict__ img) {
    if (blockIdx.x == 0) {
        for (int t = threadIdx.x; t < 4 * 4096; t += 256) g_G[t] = 0.f;
        if (threadIdx.x < 256) { if (threadIdx.x < 4 * 64) g_s[threadIdx.x] = 0.f; }
    }
    int idx = blockIdx.x * 256 + threadIdx.x;
    if (idx >= SP) return;
    int i = idx / 96, j = idx % 96;
    float a = img[(2 * i) * 192 + 2 * j];
    float b = img[(2 * i + 1) * 192 + 2 * j];
    float c = img[(2 * i) * 192 + 2 * j + 1];
    float d = img[(2 * i + 1) * 192 + 2 * j + 1];
    g_band[0][idx] = (a + b + c + d) * 0.5f;
    g_band[1][idx] = (a + b - c - d) * 0.5f;
    g_band[2][idx] = (a - b + c - d) * 0.5f;
    g_band[3][idx] = (a - b - c + d) * 0.5f;
}

// ---------------- l1 weight prepack to bf16 ----------------
__global__ void __launch_bounds__(256) k_l1wtb(const float* __restrict__ w) {
    int idx = blockIdx.x * 256 + threadIdx.x;
    const int total = 6 * 16 * 2 * 14 * 128 * 8;
    if (idx >= total) return;
    int q = idx & 7;
    int j4 = q >> 1, h = q & 1;
    int t = idx >> 3;
    int oc_l = t & 127; t >>= 7;
    int seg = t % 14; t /= 14;
    int ochalf = t & 1; t >>= 1;
    int icg = t & 15;
    int blk = t >> 4;
    int pair = seg / 7, a = seg % 7;
    int ic = icg * 4 + pair * 2 + h;
    int oc = ochalf * 128 + oc_l;
    int b0t = 2 * j4, b1t = 2 * j4 + 1;
    const float* wb = w + ((size_t)(blk * 256 + oc) * 64 + ic) * 49 + a * 7;
    float w0 = wb[b0t];
    float w1 = (b1t < 7) ? wb[b1t] : 0.f;
    uint32_t lo = __bfloat16_as_ushort(__float2bfloat16(w0));
    uint32_t hi = __bfloat16_as_ushort(__float2bfloat16(w1));
    g_l1w_bf[idx] = lo | (hi << 16);
}

// ---------------- ip: band -> feat slot, maps ----------------
__global__ void __launch_bounds__(256) k_ip(int4 bim, int4 outm, const float* __restrict__ w,
                                            const float* __restrict__ bb) {
    __shared__ float sw[576];
    __shared__ float sb2[64];
    const int band = blockIdx.y;
    for (int t = threadIdx.x; t < 576; t += 256) sw[t] = w[t];
    if (threadIdx.x < 64) sb2[threadIdx.x] = bb[threadIdx.x];
    __syncthreads();
    int idx = blockIdx.x * 256 + threadIdx.x;
    if (idx >= CC * SP) return;
    int v = idx % 96; int u = (idx / 96) % 96; int ch = idx / SP;
    const float* src = g_band[m4(bim, band)];
    float acc = sb2[ch];
#pragma unroll
    for (int a = 0; a < 3; a++) {
        int x0 = u + a - 1;
        if ((unsigned)x0 < 96u) {
#pragma unroll
            for (int b2 = 0; b2 < 3; b2++) {
                int y0 = v + b2 - 1;
                if ((unsigned)y0 < 96u) acc += src[y0 * 96 + x0] * sw[ch * 9 + a * 3 + b2];
            }
        }
    }
    g_feat[m4(outm, band)][idx] = acc;
}

// ---------------- depthwise 7x7 (+ zero LN reduction) ----------------
__global__ void __launch_bounds__(256) k_dw7(int4 srcm, int4 bbm, int4 blkm,
                                             const float* __restrict__ dwwb) {
    __shared__ float sw[49];
    __shared__ float spt[484];
    const int band = blockIdx.z >> 6;
    const int ch = blockIdx.z & 63;
    const int bb = m4(bbm, band);
    if (blockIdx.x == 0 && blockIdx.y == 0 && ch == 0 && threadIdx.x < 2)
        g_red[bb * 2 + threadIdx.x] = 0.f;
    const float* dww = dwwb + m4(blkm, band) * 3136;
    const int ty0 = blockIdx.y * 16, tx0 = blockIdx.x * 16;
    if (threadIdx.x < 49) sw[threadIdx.x] = dww[ch * 49 + threadIdx.x];
    const float* src = g_feat[m4(srcm, band)] + ch * SP;
    for (int t = threadIdx.x; t < 484; t += 256) {
        int r = t / 22, c2 = t % 22;
        int gy = ty0 - 6 + r, gx = tx0 - 6 + c2;
        spt[t] = (gy >= 0 && gy < 96 && gx >= 0 && gx < 96) ? src[gy * 96 + gx] : 0.f;
    }
    __syncthreads();
    int ly = threadIdx.x / 16, lx = threadIdx.x % 16;
    int oy = ty0 + ly, ox = tx0 + lx;
    if (oy >= PP || ox >= PP) return;
    float acc = 0.f;
#pragma unroll
    for (int a = 0; a < 7; a++)
#pragma unroll
        for (int b = 0; b < 7; b++)
            acc += spt[(ly + a) * 22 + lx + b] * sw[a * 7 + b];
    g_dwo[bb * CSPP + ch * SPP + oy * PP + ox] = acc;
}

// ---------------- pointwise + per-band LN reduction ----------------
__global__ void __launch_bounds__(256) k_pw(int4 bbm, int4 blkm, const float* __restrict__ Wb) {
    __shared__ float swT[64 * 68];
    __shared__ float sin_[4096];
    __shared__ float sr[2][8];
    const int band = blockIdx.y;
    const int bb = m4(bbm, band);
    const float* W = Wb + m4(blkm, band) * 4096;
    const float* dwo = g_dwo + bb * CSPP;
    float* pwo = g_pwo + bb * CSPP;
    const int p0 = blockIdx.x * 64;
    for (int t = threadIdx.x; t < 4096; t += 256) {
        int co = t >> 6, ci = t & 63;
        swT[ci * 68 + co] = W[t];
    }
    for (int t = threadIdx.x; t < 4096; t += 256) {
        int ci = t >> 6, p = t & 63; int gp = p0 + p;
        sin_[t] = (gp < SPP) ? dwo[ci * SPP + gp] : 0.f;
    }
    __syncthreads();
    const int ocg = threadIdx.x >> 4, pg = threadIdx.x & 15;
    float acc[4][4] = {};
#pragma unroll 4
    for (int ci = 0; ci < 64; ci++) {
        float4 w4 = *(const float4*)&swT[ci * 68 + ocg * 4];
        float4 i4 = *(const float4*)&sin_[ci * 64 + pg * 4];
        acc[0][0] += w4.x * i4.x; acc[0][1] += w4.x * i4.y; acc[0][2] += w4.x * i4.z; acc[0][3] += w4.x * i4.w;
        acc[1][0] += w4.y * i4.x; acc[1][1] += w4.y * i4.y; acc[1][2] += w4.y * i4.z; acc[1][3] += w4.y * i4.w;
        acc[2][0] += w4.z * i4.x; acc[2][1] += w4.z * i4.y; acc[2][2] += w4.z * i4.z; acc[2][3] += w4.z * i4.w;
        acc[3][0] += w4.w * i4.x; acc[3][1] += w4.w * i4.y; acc[3][2] += w4.w * i4.z; acc[3][3] += w4.w * i4.w;
    }
    float ls = 0.f, ls2 = 0.f;
#pragma unroll
    for (int o = 0; o < 4; o++) {
        int oc = ocg * 4 + o;
#pragma unroll
        for (int p = 0; p < 4; p++) {
            int gp = p0 + pg * 4 + p;
            if (gp < SPP) {
                float v = acc[o][p];
                pwo[oc * SPP + gp] = v;
                ls += v; ls2 += v * v;
            }
        }
    }
    for (int off = 16; off; off >>= 1) {
        ls += __shfl_down_sync(0xffffffffu, ls, off);
        ls2 += __shfl_down_sync(0xffffffffu, ls2, off);
    }
    if ((threadIdx.x & 31) == 0) { sr[0][threadIdx.x >> 5] = ls; sr[1][threadIdx.x >> 5] = ls2; }
    __syncthreads();
    if (threadIdx.x == 0) {
        float a = 0.f, b = 0.f;
        for (int w2 = 0; w2 < 8; w2++) { a += sr[0][w2]; b += sr[1][w2]; }
        atomicAdd(&g_red[bb * 2], a); atomicAdd(&g_red[bb * 2 + 1], b);
    }
}

// ---------------- l1 via bf16 mma (z = band*2 + ochalf) ----------------
#define L1_WBUF 14336
#define L1_IN   1408
#define L1_SMEMB ((L1_WBUF + L1_IN) * 4)

__global__ void __launch_bounds__(256) k_l1mma(int4 bbm, int4 blkm, const float* __restrict__ l1bb) {
    extern __shared__ uint32_t sm[];
    uint32_t* s_in = sm + L1_WBUF;
    const int tid = threadIdx.x;
    const int tx = blockIdx.x * 8, ty = blockIdx.y * 16;
    const int band = blockIdx.z >> 1;
    const int ochalf = blockIdx.z & 1;
    const int bb = m4(bbm, band);
    const int blk = m4(blkm, band);
    const float* l1b = l1bb + blk * 256;
    const int wid = tid >> 5, lane = tid & 31;
    const int ocg = wid >> 1, pxg = wid & 1;
    const int g = lane >> 2, j4 = lane & 3;

    const float m = g_red[bb * 2] * (1.0f / (float)NLN);
    const float inv = rsqrtf(g_red[bb * 2 + 1] * (1.0f / (float)NLN) - m * m + 1e-5f);
    const float* pwo = g_pwo + bb * CSPP;
    float* l1o = g_l1o + bb * L1OSZ;

    for (int t = tid; t < L1_IN; t += 256) s_in[t] = 0u;

    float c[2][8][4] = {};
    unsigned short* s_ine = (unsigned short*)s_in;
    unsigned short* s_ino = (unsigned short*)(s_in + 704);

    for (int icg = 0; icg < 16; icg++) {
        __syncthreads();
        {
            size_t chunk = ((size_t)(blk * 16 + icg) * 2 + ochalf) * L1_WBUF;
            const uint4* src = (const uint4*)(g_l1w_bf + chunk);
            uint4* dstw = (uint4*)sm;
#pragma unroll
            for (int i = 0; i < 14; i++)
                dstw[tid + i * 256] = src[tid + i * 256];
        }
        for (int t = tid; t < 1232; t += 256) {
            int ic = t / 308, r2 = t % 308;
            int r = r2 / 14, cx = r2 % 14;
            float v = (pwo[(icg * 4 + ic) * SPP + (ty + r) * PP + (tx + cx)] - m) * inv;
            unsigned short hb = __bfloat16_as_ushort(__float2bfloat16(v));
            int rowb = (ic * 22 + r) * 16;
            s_ine[rowb + cx] = hb;
            if (cx >= 1) s_ino[rowb + cx - 1] = hb;
        }
        __syncthreads();

        const uint32_t* wb = sm;
        const int r0 = ocg * 32 + g;
        const uint32_t* pbase = s_in + (g & 1) * 704 + ((g >> 1) + j4);
#pragma unroll
        for (int pair = 0; pair < 2; pair++) {
#pragma unroll
            for (int a = 0; a < 7; a++) {
                const uint32_t* ws = wb + (pair * 7 + a) * 1024 + 2 * j4;
                u64t A0lo = *(const u64t*)(ws + r0 * 8);
                u64t A0hi = *(const u64t*)(ws + (r0 + 8) * 8);
                u64t A1lo = *(const u64t*)(ws + (r0 + 16) * 8);
                u64t A1hi = *(const u64t*)(ws + (r0 + 24) * 8);
                uint32_t a00 = (uint32_t)A0lo, a02 = (uint32_t)(A0lo >> 32);
                uint32_t a01 = (uint32_t)A0hi, a03 = (uint32_t)(A0hi >> 32);
                uint32_t a10 = (uint32_t)A1lo, a12 = (uint32_t)(A1lo >> 32);
                uint32_t a11 = (uint32_t)A1hi, a13 = (uint32_t)(A1hi >> 32);
                const uint32_t* p0 = pbase + (pair * 2) * 176 + (pxg * 8 + a) * 8;
                const uint32_t* p1 = p0 + 176;
#pragma unroll
                for (int j = 0; j < 8; j++) {
                    uint32_t b0 = p0[j * 8], b1 = p1[j * 8];
                    mma_bf16(c[0][j], a00, a01, a02, a03, b0, b1);
                    mma_bf16(c[1][j], a10, a11, a12, a13, b0, b1);
                }
            }
        }
    }

#pragma unroll
    for (int mm = 0; mm < 2; mm++) {
        int ocb = ochalf * 128 + ocg * 32 + mm * 16 + g;
        float b_lo = l1b[ocb], b_hi = l1b[ocb + 8];
#pragma unroll
        for (int j = 0; j < 8; j++) {
            int y = ty + pxg * 8 + j;
            int xb = tx + 2 * j4;
            float* o_lo = &l1o[ocb * SP + y * 96 + xb];
            float* o_hi = &l1o[(ocb + 8) * SP + y * 96 + xb];
            o_lo[0] = gelu(c[mm][j][0] + b_lo);
            o_lo[1] = gelu(c[mm][j][1] + b_lo);
            o_hi[0] = gelu(c[mm][j][2] + b_hi);
            o_hi[1] = gelu(c[mm][j][3] + b_hi);
        }
    }
}

// ---------------- l2: 1x1 256->64 + bias + residual(s) ----------------
__global__ void __launch_bounds__(256) k_l2(int4 bbm, int4 blkm, int4 srcm, int4 r2m, int4 dstm,
                                            const float* __restrict__ Wb, const float* __restrict__ biasb) {
    __shared__ float swT[64 * 68];
    __shared__ float sin_[4096];
    const int band = blockIdx.y;
    const int bb = m4(bbm, band);
    const int blk = m4(blkm, band);
    const float* W = Wb + blk * 16384;
    const float* bias = biasb + blk * 64;
    const float* l1o = g_l1o + bb * L1OSZ;
    const int p0 = blockIdx.x * 64;
    const int ocg = threadIdx.x >> 4, pg = threadIdx.x & 15;
    float acc[4][4] = {};
    for (int c0 = 0; c0 < 256; c0 += 64) {
        __syncthreads();
        for (int t = threadIdx.x; t < 4096; t += 256) {
            int co = t >> 6, ci = t & 63;
            swT[ci * 68 + co] = W[co * 256 + c0 + ci];
        }
        for (int t = threadIdx.x; t < 4096; t += 256) {
            int ci = t >> 6, p = t & 63;
            sin_[t] = l1o[(c0 + ci) * SP + p0 + p];
        }
        __syncthreads();
#pragma unroll 4
        for (int ci = 0; ci < 64; ci++) {
            float4 w4 = *(const float4*)&swT[ci * 68 + ocg * 4];
            float4 i4 = *(const float4*)&sin_[ci * 64 + pg * 4];
            acc[0][0] += w4.x * i4.x; acc[0][1] += w4.x * i4.y; acc[0][2] += w4.x * i4.z; acc[0][3] += w4.x * i4.w;
            acc[1][0] += w4.y * i4.x; acc[1][1] += w4.y * i4.y; acc[1][2] += w4.y * i4.z; acc[1][3] += w4.y * i4.w;
            acc[2][0] += w4.z * i4.x; acc[2][1] += w4.z * i4.y; acc[2][2] += w4.z * i4.z; acc[2][3] += w4.z * i4.w;
            acc[3][0] += w4.w * i4.x; acc[3][1] += w4.w * i4.y; acc[3][2] += w4.w * i4.z; acc[3][3] += w4.w * i4.w;
        }
    }
    float* dstp = g_feat[m4(dstm, band)];
    const float* rp1 = g_feat[m4(srcm, band)];
    const int r2 = m4(r2m, band);
    const float* rp2 = (r2 >= 0) ? g_feat[r2] : 0;
#pragma unroll
    for (int o = 0; o < 4; o++) {
        int oc = ocg * 4 + o;
        float bi = bias[oc];
#pragma unroll
        for (int p = 0; p < 4; p++) {
            int idx = oc * SP + p0 + pg * 4 + p;
            float v = acc[o][p] + bi + rp1[idx];
            if (rp2) v += rp2[idx];
            dstp[idx] = v;
        }
    }
}

// ---------------- xblock Gram + row-sum ----------------
__global__ void __launch_bounds__(256) k_xg(int4 srcm) {
    __shared__ float sf[1024];
    const int band = blockIdx.y;
    const float* f = g_feat[m4(srcm, band)];
    float* Gp = g_G + band * 4096;
    float* sp = g_s + band * 64;
    const int ag = threadIdx.x >> 4, bg = threadIdx.x & 15;
    float acc[4][4] = {};
    float sacc[4] = {};
    const int tok0 = blockIdx.x * 144;
    for (int tb = 0; tb < 144; tb += 16) {
        __syncthreads();
        for (int t2 = threadIdx.x; t2 < 1024; t2 += 256) sf[t2] = f[(tok0 + tb) * 64 + t2];
        __syncthreads();
#pragma unroll
        for (int tk = 0; tk < 16; tk++) {
            float4 fa = *(const float4*)&sf[tk * 64 + ag * 4];
            float4 fb = *(const float4*)&sf[tk * 64 + bg * 4];
            acc[0][0] += fa.x * fb.x; acc[0][1] += fa.x * fb.y; acc[0][2] += fa.x * fb.z; acc[0][3] += fa.x * fb.w;
            acc[1][0] += fa.y * fb.x; acc[1][1] += fa.y * fb.y; acc[1][2] += fa.y * fb.z; acc[1][3] += fa.y * fb.w;
            acc[2][0] += fa.z * fb.x; acc[2][1] += fa.z * fb.y; acc[2][2] += fa.z * fb.z; acc[2][3] += fa.z * fb.w;
            acc[3][0] += fa.w * fb.x; acc[3][1] += fa.w * fb.y; acc[3][2] += fa.w * fb.z; acc[3][3] += fa.w * fb.w;
            if (ag == 0) { sacc[0] += fb.x; sacc[1] += fb.y; sacc[2] += fb.z; sacc[3] += fb.w; }
        }
    }
    for (int i2 = 0; i2 < 4; i2++)
        for (int j2 = 0; j2 < 4; j2++)
            atomicAdd(&Gp[(ag * 4 + i2) * 64 + bg * 4 + j2], acc[i2][j2]);
    if (ag == 0)
        for (int j2 = 0; j2 < 4; j2++) atomicAdd(&sp[bg * 4 + j2], sacc[j2]);
}

// ---------------- attention core (blockIdx.x = band; per-band weight set) ----------------
__global__ void __launch_bounds__(256) k_xatt(const float* __restrict__ xqw, const float* __restrict__ xqb,
                                              const float* __restrict__ xkw, const float* __restrict__ xkb,
                                              const float* __restrict__ xvw, const float* __restrict__ xvb,
                                              int4 imap) {
    __shared__ float sA[4096];
    __shared__ float sGK[4096];
    __shared__ float ss[64], sQs[64], sKs[64];
    const int band = blockIdx.x;
    const int iw = m4(imap, band);
    const float* Qw = xqw + iw * 4096; const float* Qb = xqb + iw * 64;
    const float* Kw = xkw + iw * 4096; const float* Kb = xkb + iw * 64;
    const float* Vw = xvw + iw * 4096; const float* Vb = xvb + iw * 64;
    const float scale = (iw == 0) ? 0.44721359549995793f : 0.70710678118654752f;
    float* Gp = g_G + band * 4096;
    float* sp = g_s + band * 64;
    const int t = threadIdx.x;
    for (int i = t; i < 4096; i += 256) sA[i] = Gp[i];
    if (t < 64) ss[t] = sp[t];
    __syncthreads();
    if (t < 64) {
        float q = 0.f;
        for (int a2 = 0; a2 < 64; a2++) q += Qw[t * 64 + a2] * ss[a2];
        sQs[t] = q;
    } else if (t < 128) {
        int d = t - 64; float q = 0.f;
        for (int b2 = 0; b2 < 64; b2++) q += Kw[d * 64 + b2] * ss[b2];
        sKs[d] = q;
    }
    for (int i = t; i < 4096; i += 256) {
        int a2 = i >> 6, d = i & 63;
        float s2 = 0.f;
        for (int b2 = 0; b2 < 64; b2++) s2 += sA[a2 * 64 + b2] * Kw[d * 64 + b2];
        sGK[i] = s2;
    }
    __syncthreads();
    for (int i = t; i < 4096; i += 256) Gp[i] = 0.f;
    if (t < 64) sp[t] = 0.f;
    for (int i = t; i < 4096; i += 256) {
        int c = i >> 6, d = i & 63;
        float s2 = Qb[c] * sKs[d] + sQs[c] * Kb[d] + 9216.0f * Qb[c] * Kb[d];
        for (int a2 = 0; a2 < 64; a2++) s2 += Qw[c * 64 + a2] * sGK[a2 * 64 + d];
        sA[i] = s2 * scale;
    }
    __syncthreads();
    if (t < 64) {
        float mx = -1e30f;
        for (int d = 0; d < 64; d++) mx = fmaxf(mx, sA[t * 64 + d]);
        float sm = 0.f;
        for (int d = 0; d < 64; d++) { float e = expf(sA[t * 64 + d] - mx); sA[t * 64 + d] = e; sm += e; }
        float r = 1.0f / sm;
        for (int d = 0; d < 64; d++) sA[t * 64 + d] *= r;
    }
    __syncthreads();
    for (int i = t; i < 4096; i += 256) {
        int a2 = i >> 6, d = i & 63;
        float s2 = 0.f;
        for (int c = 0; c < 64; c++) s2 += Vw[c * 64 + a2] * sA[c * 64 + d];
        g_M[band * 4096 + i] = s2;
    }
    if (t < 64) {
        float s2 = 0.f;
        for (int c = 0; c < 64; c++) s2 += Vb[c] * sA[c * 64 + t];
        g_bias[band * 64 + t] = s2;
    }
}

// ---------------- xblock apply ----------------
__global__ void __launch_bounds__(256) k_xapply(int4 srcm, int4 dstm) {
    __shared__ float sM[4096];
    __shared__ float sb[64];
    __shared__ float sf[2048];
    const int band = blockIdx.y;
    for (int t = threadIdx.x; t < 4096; t += 256) sM[t] = g_M[band * 4096 + t];
    if (threadIdx.x < 64) sb[threadIdx.x] = g_bias[band * 64 + threadIdx.x];
    const int tok0 = blockIdx.x * 32;
    const float* f = g_feat[m4(srcm, band)];
    for (int t = threadIdx.x; t < 2048; t += 256) sf[t] = f[tok0 * 64 + t];
    __syncthreads();
    const int tk = threadIdx.x >> 3, dg = threadIdx.x & 7;
    float acc[8] = {};
#pragma unroll 8
    for (int a2 = 0; a2 < 64; a2++) {
        float fa = sf[tk * 64 + a2];
        float4 m0 = *(const float4*)&sM[a2 * 64 + dg * 8];
        float4 m1 = *(const float4*)&sM[a2 * 64 + dg * 8 + 4];
        acc[0] += fa * m0.x; acc[1] += fa * m0.y; acc[2] += fa * m0.z; acc[3] += fa * m0.w;
        acc[4] += fa * m1.x; acc[5] += fa * m1.y; acc[6] += fa * m1.z; acc[7] += fa * m1.w;
    }
    float* dp = g_feat[m4(dstm, band)];
    const int base = (tok0 + tk) * 64 + dg * 8;
#pragma unroll
    for (int d2 = 0; d2 < 8; d2++) dp[base + d2] = sf[tk * 64 + dg * 8 + d2] + acc[d2] + sb[dg * 8 + d2];
}

// ---------------- op ----------------
__global__ void __launch_bounds__(256) k_op(int4 srcm, int4 outm, const float* __restrict__ w,
                                            const float* __restrict__ bb) {
    __shared__ float sw[576];
    const int band = blockIdx.y;
    for (int t = threadIdx.x; t < 576; t += 256) {
        int ch = t / 9, k2 = t % 9; int a = k2 / 3, b2 = k2 % 3;
        sw[t] = w[ch * 9 + (2 - a) * 3 + (2 - b2)];
    }
    __syncthreads();
    int idx = blockIdx.x * 256 + threadIdx.x;
    if (idx >= SP) return;
    int u = idx / 96, v = idx % 96;
    const float* x = g_feat[m4(srcm, band)];
    float acc = bb[0];
    for (int ch = 0; ch < 64; ch++) {
#pragma unroll
        for (int a = 0; a < 3; a++) {
            int y = u + a - 1; if ((unsigned)y >= 96u) continue;
#pragma unroll
            for (int b2 = 0; b2 < 3; b2++) {
                int xx = v + b2 - 1; if ((unsigned)xx >= 96u) continue;
                acc += x[ch * SP + y * 96 + xx] * sw[ch * 9 + a * 3 + b2];
            }
        }
    }
    g_opout[m4(outm, band)][v * 96 + u] = acc;
}

__global__ void __launch_bounds__(256) k_idwt(const float* __restrict__ img, float* __restrict__ out) {
    int idx = blockIdx.x * 256 + threadIdx.x;
    if (idx >= SP) return;
    int i = idx / 96, j = idx % 96;
    float a = g_opout[0][idx], b = g_opout[1][idx], c = g_opout[2][idx], d = g_opout[3][idx];
    int r0 = (2 * i) * 192 + 2 * j;
    int r1 = (2 * i + 1) * 192 + 2 * j;
    out[r0]     = 0.5f * (a + b + c + d) + img[r0];
    out[r0 + 1] = 0.5f * (a - b + c - d) + img[r0 + 1];
    out[r1]     = 0.5f * (a + b - c - d) + img[r1];
    out[r1 + 1] = 0.5f * (a - b - c + d) + img[r1 + 1];
}

extern "C" void kernel_launch(void* const* d_in, const int* in_sizes, int n_in,
                              void* d_out, int out_size) {
    (void)in_sizes; (void)n_in; (void)out_size;
    const float* images = (const float*)d_in[0];
    const float* ip_w  = (const float*)d_in[1];
    const float* ip_b  = (const float*)d_in[2];
    const float* op_w  = (const float*)d_in[3];
    const float* op_b  = (const float*)d_in[4];
    const float* cb_dw = (const float*)d_in[5];
    const float* cb_pw = (const float*)d_in[6];
    const float* cb_l1w = (const float*)d_in[7];
    const float* cb_l1b = (const float*)d_in[8];
    const float* cb_l2w = (const float*)d_in[9];
    const float* cb_l2b = (const float*)d_in[10];
    const float* xqw = (const float*)d_in[11];
    const float* xqb = (const float*)d_in[12];
    const float* xkw = (const float*)d_in[13];
    const float* xkb = (const float*)d_in[14];
    const float* xvw = (const float*)d_in[15];
    const float* xvb = (const float*)d_in[16];
    float* out = (float*)d_out;

    cudaFuncSetAttribute(k_l1mma, cudaFuncAttributeMaxDynamicSharedMemorySize, L1_SMEMB);

    k_dwt<<<36, 256>>>(images);
    k_l1wtb<<<(6 * 16 * 2 * 14 * 128 * 8 + 255) / 256, 256>>>(cb_l1w);

    auto cb = [&](int nb, int4 bbm, int4 blkm, int4 srcm, int4 r2m, int4 dstm) {
        k_dw7<<<dim3(7, 7, 64 * nb), 256>>>(srcm, bbm, blkm, cb_dw);
        k_pw<<<dim3(163, nb), 256>>>(bbm, blkm, cb_pw);
        k_l1mma<<<dim3(12, 6, 2 * nb), 256, L1_SMEMB>>>(bbm, blkm, cb_l1b);
        k_l2<<<dim3(144, nb), 256>>>(bbm, blkm, srcm, r2m, dstm, cb_l2w, cb_l2b);
    };

    // slots: HF band b (b=0..2): A=2b, B=2b+1 ; LF: lf=6, c1=7, c2=8, xlow=9, c3=10, c4=11
    // buffer band: HF b -> b ; LF -> 3
    const int4 bb4   = make_int4(0, 1, 2, 3);
    const int4 bbLF  = make_int4(3, 3, 3, 3);

    // Stage A: ip all 4 bands (HF uses g_band[1..3], LF g_band[0])
    k_ip<<<dim3(2304, 4), 256>>>(make_int4(1, 2, 3, 0), make_int4(0, 2, 4, 6), ip_w, ip_b);

    // Stage B: CB-I  (HF blk4: A->B ; LF blk0: lf->c1)
    cb(4, bb4, make_int4(4, 4, 4, 0), make_int4(0, 2, 4, 6),
       make_int4(-1, -1, -1, -1), make_int4(1, 3, 5, 7));

    // Stage C: cb1 LF-only (c2 = cb1(c1) + c1)
    cb(1, bbLF, make_int4(1, 1, 1, 1), make_int4(7, 7, 7, 7),
       make_int4(7, 7, 7, 7), make_int4(8, 8, 8, 8));

    // Stage D: XB all 4 bands (HF i=1 on B -> A ; LF i=0 on c1 -> xlow)
    {
        int4 srcm = make_int4(1, 3, 5, 7);
        int4 dstm = make_int4(0, 2, 4, 9);
        k_xg<<<dim3(64, 4), 256>>>(srcm);
        k_xatt<<<4, 256>>>(xqw, xqb, xkw, xkb, xvw, xvb, make_int4(1, 1, 1, 0));
        k_xapply<<<dim3(288, 4), 256>>>(srcm, dstm);
    }

    // Stage E: CB-II (HF blk5: h2 = cb5(hx)+h1 -> B ; LF blk2: c3 = cb2(xlow)+c2)
    cb(4, bb4, make_int4(5, 5, 5, 2), make_int4(0, 2, 4, 9),
       make_int4(1, 3, 5, 8), make_int4(1, 3, 5, 10));

    // Stage F: cb3 LF-only (c4 = cb3(c3) + c1)
    cb(1, bbLF, make_int4(3, 3, 3, 3), make_int4(10, 10, 10, 10),
       make_int4(7, 7, 7, 7), make_int4(11, 11, 11, 11));

    // Stage G: op all 4 bands (HF h2 -> opout[1+b] ; LF c4 -> opout[0])
    k_op<<<dim3(36, 4), 256>>>(make_int4(1, 3, 5, 11), make_int4(1, 2, 3, 0), op_w, op_b);

    k_idwt<<<36, 256>>>(images, out);
}

// round 12
// speedup vs baseline: 5.0332x; 1.0785x over previous
#include <cuda_runtime.h>
#include <cuda_bf16.h>
#include <math.h>
#include <stdint.h>

#define CC 64
#define SP 9216
#define PP 102
#define SPP 10404
#define NLN 665856
#define CSPP (CC * SPP)
#define L1OSZ (4 * CC * SP)

typedef unsigned long long u64t;

__device__ __forceinline__ int m4(int4 v, int i) { return ((const int*)&v)[i]; }

// ---------------- scratch ----------------
__device__ float g_band[4][SP];
__device__ float g_opout[4][SP];
__device__ float g_feat[12][CC * SP];
__device__ float g_dwo[4 * CSPP];
__device__ float g_pwo[4 * CSPP];
__device__ float g_l1o[4 * L1OSZ];
__device__ __align__(16) uint32_t g_l1w_bf[6 * 16 * 2 * 14 * 128 * 8];
__device__ float g_red[8];
__device__ float g_G[4 * 4096];
__device__ float g_s[4 * 64];
__device__ float g_M[4 * 4096];
__device__ float g_bias[4 * 64];

__device__ __forceinline__ float gelu(float x) {
    return 0.5f * x * (1.0f + erff(x * 0.70710678118654752f));
}
__device__ __forceinline__ void mma_bf16(float* c, uint32_t a0, uint32_t a1, uint32_t a2,
                                         uint32_t a3, uint32_t b0, uint32_t b1) {
    asm volatile(
        "mma.sync.aligned.m16n8k16.row.col.f32.bf16.bf16.f32 "
        "{%0,%1,%2,%3}, {%4,%5,%6,%7}, {%8,%9}, {%0,%1,%2,%3};"
        : "+f"(c[0]), "+f"(c[1]), "+f"(c[2]), "+f"(c[3])
        : "r"(a0), "r"(a1), "r"(a2), "r"(a3), "r"(b0), "r"(b1));
}

// ---------------- DWT (+ zero attention accumulators) ----------------
__global__ void __launch_bounds__(256) k_dwt(const float* __restrict__ img) {
    if (blockIdx.x == 0) {
        for (int t = threadIdx.x; t < 4 * 4096; t += 256) g_G[t] = 0.f;
        if (threadIdx.x < 4 * 64) g_s[threadIdx.x] = 0.f;
    }
    int idx = blockIdx.x * 256 + threadIdx.x;
    if (idx >= SP) return;
    int i = idx / 96, j = idx % 96;
    float a = img[(2 * i) * 192 + 2 * j];
    float b = img[(2 * i + 1) * 192 + 2 * j];
    float c = img[(2 * i) * 192 + 2 * j + 1];
    float d = img[(2 * i + 1) * 192 + 2 * j + 1];
    g_band[0][idx] = (a + b + c + d) * 0.5f;
    g_band[1][idx] = (a + b - c - d) * 0.5f;
    g_band[2][idx] = (a - b + c - d) * 0.5f;
    g_band[3][idx] = (a - b - c + d) * 0.5f;
}

// ---------------- l1 weight prepack to bf16 ----------------
__global__ void __launch_bounds__(256) k_l1wtb(const float* __restrict__ w) {
    int idx = blockIdx.x * 256 + threadIdx.x;
    const int total = 6 * 16 * 2 * 14 * 128 * 8;
    if (idx >= total) return;
    int q = idx & 7;
    int j4 = q >> 1, h = q & 1;
    int t = idx >> 3;
    int oc_l = t & 127; t >>= 7;
    int seg = t % 14; t /= 14;
    int ochalf = t & 1; t >>= 1;
    int icg = t & 15;
    int blk = t >> 4;
    int pair = seg / 7, a = seg % 7;
    int ic = icg * 4 + pair * 2 + h;
    int oc = ochalf * 128 + oc_l;
    int b0t = 2 * j4, b1t = 2 * j4 + 1;
    const float* wb = w + ((size_t)(blk * 256 + oc) * 64 + ic) * 49 + a * 7;
    float w0 = wb[b0t];
    float w1 = (b1t < 7) ? wb[b1t] : 0.f;
    uint32_t lo = __bfloat16_as_ushort(__float2bfloat16(w0));
    uint32_t hi = __bfloat16_as_ushort(__float2bfloat16(w1));
    g_l1w_bf[idx] = lo | (hi << 16);
}

// ---------------- ip ----------------
__global__ void __launch_bounds__(256) k_ip(int4 bim, int4 outm, const float* __restrict__ w,
                                            const float* __restrict__ bb) {
    __shared__ float sw[576];
    __shared__ float sb2[64];
    const int band = blockIdx.y;
    for (int t = threadIdx.x; t < 576; t += 256) sw[t] = w[t];
    if (threadIdx.x < 64) sb2[threadIdx.x] = bb[threadIdx.x];
    __syncthreads();
    int idx = blockIdx.x * 256 + threadIdx.x;
    if (idx >= CC * SP) return;
    int v = idx % 96; int u = (idx / 96) % 96; int ch = idx / SP;
    const float* src = g_band[m4(bim, band)];
    float acc = sb2[ch];
#pragma unroll
    for (int a = 0; a < 3; a++) {
        int x0 = u + a - 1;
        if ((unsigned)x0 < 96u) {
#pragma unroll
            for (int b2 = 0; b2 < 3; b2++) {
                int y0 = v + b2 - 1;
                if ((unsigned)y0 < 96u) acc += src[y0 * 96 + x0] * sw[ch * 9 + a * 3 + b2];
            }
        }
    }
    g_feat[m4(outm, band)][idx] = acc;
}

// ---------------- depthwise 7x7, register-blocked 4px/thread (32x32 tile) ----------------
__global__ void __launch_bounds__(256) k_dw7(int4 srcm, int4 bbm, int4 blkm,
                                             const float* __restrict__ dwwb) {
    __shared__ __align__(16) float sw[64];          // padded to 256 B for spt alignment
    __shared__ __align__(16) float spt[38 * 40];    // 40-float rows = 160 B (16B multiple)
    const int band = blockIdx.z >> 6;
    const int ch = blockIdx.z & 63;
    const int bb = m4(bbm, band);
    if (blockIdx.x == 0 && blockIdx.y == 0 && ch == 0 && threadIdx.x < 2)
        g_red[bb * 2 + threadIdx.x] = 0.f;
    const float* dww = dwwb + m4(blkm, band) * 3136;
    const int ty0 = blockIdx.y * 32, tx0 = blockIdx.x * 32;
    if (threadIdx.x < 49) sw[threadIdx.x] = dww[ch * 49 + threadIdx.x];
    const float* src = g_feat[m4(srcm, band)] + ch * SP;
    for (int t = threadIdx.x; t < 1520; t += 256) {
        int r = t / 40, c = t % 40;
        int gy = ty0 - 6 + r, gx = tx0 - 6 + c;
        spt[t] = (c < 38 && gy >= 0 && gy < 96 && gx >= 0 && gx < 96) ? src[gy * 96 + gx] : 0.f;
    }
    __syncthreads();
    const int ly = threadIdx.x >> 3, lx0 = (threadIdx.x & 7) * 4;
    const int oy = ty0 + ly;
    if (oy >= PP) return;
    float acc[4] = {0.f, 0.f, 0.f, 0.f};
#pragma unroll
    for (int a = 0; a < 7; a++) {
        const float* row = &spt[(ly + a) * 40 + lx0];
        float4 r0 = *(const float4*)row;
        float4 r1 = *(const float4*)(row + 4);
        float2 r2 = *(const float2*)(row + 8);
        float rr[10] = {r0.x, r0.y, r0.z, r0.w, r1.x, r1.y, r1.z, r1.w, r2.x, r2.y};
#pragma unroll
        for (int b = 0; b < 7; b++) {
            float wv = sw[a * 7 + b];
            acc[0] += rr[b] * wv;
            acc[1] += rr[b + 1] * wv;
            acc[2] += rr[b + 2] * wv;
            acc[3] += rr[b + 3] * wv;
        }
    }
    float* dst = g_dwo + bb * CSPP + ch * SPP + oy * PP;
#pragma unroll
    for (int k = 0; k < 4; k++) {
        int ox = tx0 + lx0 + k;
        if (ox < PP) dst[ox] = acc[k];
    }
}

// ---------------- pointwise + per-band LN reduction ----------------
__global__ void __launch_bounds__(256) k_pw(int4 bbm, int4 blkm, const float* __restrict__ Wb) {
    __shared__ float swT[64 * 68];
    __shared__ float sin_[4096];
    __shared__ float sr[2][8];
    const int band = blockIdx.y;
    const int bb = m4(bbm, band);
    const float* W = Wb + m4(blkm, band) * 4096;
    const float* dwo = g_dwo + bb * CSPP;
    float* pwo = g_pwo + bb * CSPP;
    const int p0 = blockIdx.x * 64;
    for (int t = threadIdx.x; t < 4096; t += 256) {
        int co = t >> 6, ci = t & 63;
        swT[ci * 68 + co] = W[t];
    }
    for (int t = threadIdx.x; t < 4096; t += 256) {
        int ci = t >> 6, p = t & 63; int gp = p0 + p;
        sin_[t] = (gp < SPP) ? dwo[ci * SPP + gp] : 0.f;
    }
    __syncthreads();
    const int ocg = threadIdx.x >> 4, pg = threadIdx.x & 15;
    float acc[4][4] = {};
#pragma unroll 4
    for (int ci = 0; ci < 64; ci++) {
        float4 w4 = *(const float4*)&swT[ci * 68 + ocg * 4];
        float4 i4 = *(const float4*)&sin_[ci * 64 + pg * 4];
        acc[0][0] += w4.x * i4.x; acc[0][1] += w4.x * i4.y; acc[0][2] += w4.x * i4.z; acc[0][3] += w4.x * i4.w;
        acc[1][0] += w4.y * i4.x; acc[1][1] += w4.y * i4.y; acc[1][2] += w4.y * i4.z; acc[1][3] += w4.y * i4.w;
        acc[2][0] += w4.z * i4.x; acc[2][1] += w4.z * i4.y; acc[2][2] += w4.z * i4.z; acc[2][3] += w4.z * i4.w;
        acc[3][0] += w4.w * i4.x; acc[3][1] += w4.w * i4.y; acc[3][2] += w4.w * i4.z; acc[3][3] += w4.w * i4.w;
    }
    float ls = 0.f, ls2 = 0.f;
#pragma unroll
    for (int o = 0; o < 4; o++) {
        int oc = ocg * 4 + o;
#pragma unroll
        for (int p = 0; p < 4; p++) {
            int gp = p0 + pg * 4 + p;
            if (gp < SPP) {
                float v = acc[o][p];
                pwo[oc * SPP + gp] = v;
                ls += v; ls2 += v * v;
            }
        }
    }
    for (int off = 16; off; off >>= 1) {
        ls += __shfl_down_sync(0xffffffffu, ls, off);
        ls2 += __shfl_down_sync(0xffffffffu, ls2, off);
    }
    if ((threadIdx.x & 31) == 0) { sr[0][threadIdx.x >> 5] = ls; sr[1][threadIdx.x >> 5] = ls2; }
    __syncthreads();
    if (threadIdx.x == 0) {
        float a = 0.f, b = 0.f;
        for (int w2 = 0; w2 < 8; w2++) { a += sr[0][w2]; b += sr[1][w2]; }
        atomicAdd(&g_red[bb * 2], a); atomicAdd(&g_red[bb * 2 + 1], b);
    }
}

// ---------------- l1 via bf16 mma (z = band*2 + ochalf) ----------------
#define L1_WBUF 14336
#define L1_IN   1408
#define L1_SMEMB ((L1_WBUF + L1_IN) * 4)

__global__ void __launch_bounds__(256) k_l1mma(int4 bbm, int4 blkm, const float* __restrict__ l1bb) {
    extern __shared__ uint32_t sm[];
    uint32_t* s_in = sm + L1_WBUF;
    const int tid = threadIdx.x;
    const int tx = blockIdx.x * 8, ty = blockIdx.y * 16;
    const int band = blockIdx.z >> 1;
    const int ochalf = blockIdx.z & 1;
    const int bb = m4(bbm, band);
    const int blk = m4(blkm, band);
    const float* l1b = l1bb + blk * 256;
    const int wid = tid >> 5, lane = tid & 31;
    const int ocg = wid >> 1, pxg = wid & 1;
    const int g = lane >> 2, j4 = lane & 3;

    const float m = g_red[bb * 2] * (1.0f / (float)NLN);
    const float inv = rsqrtf(g_red[bb * 2 + 1] * (1.0f / (float)NLN) - m * m + 1e-5f);
    const float* pwo = g_pwo + bb * CSPP;
    float* l1o = g_l1o + bb * L1OSZ;

    for (int t = tid; t < L1_IN; t += 256) s_in[t] = 0u;

    float c[2][8][4] = {};
    unsigned short* s_ine = (unsigned short*)s_in;
    unsigned short* s_ino = (unsigned short*)(s_in + 704);

    for (int icg = 0; icg < 16; icg++) {
        __syncthreads();
        {
            size_t chunk = ((size_t)(blk * 16 + icg) * 2 + ochalf) * L1_WBUF;
            const uint4* src = (const uint4*)(g_l1w_bf + chunk);
            uint4* dstw = (uint4*)sm;
#pragma unroll
            for (int i = 0; i < 14; i++)
                dstw[tid + i * 256] = src[tid + i * 256];
        }
        for (int t = tid; t < 1232; t += 256) {
            int ic = t / 308, r2 = t % 308;
            int r = r2 / 14, cx = r2 % 14;
            float v = (pwo[(icg * 4 + ic) * SPP + (ty + r) * PP + (tx + cx)] - m) * inv;
            unsigned short hb = __bfloat16_as_ushort(__float2bfloat16(v));
            int rowb = (ic * 22 + r) * 16;
            s_ine[rowb + cx] = hb;
            if (cx >= 1) s_ino[rowb + cx - 1] = hb;
        }
        __syncthreads();

        const uint32_t* wb = sm;
        const int r0 = ocg * 32 + g;
        const uint32_t* pbase = s_in + (g & 1) * 704 + ((g >> 1) + j4);
#pragma unroll
        for (int pair = 0; pair < 2; pair++) {
#pragma unroll
            for (int a = 0; a < 7; a++) {
                const uint32_t* ws = wb + (pair * 7 + a) * 1024 + 2 * j4;
                u64t A0lo = *(const u64t*)(ws + r0 * 8);
                u64t A0hi = *(const u64t*)(ws + (r0 + 8) * 8);
                u64t A1lo = *(const u64t*)(ws + (r0 + 16) * 8);
                u64t A1hi = *(const u64t*)(ws + (r0 + 24) * 8);
                uint32_t a00 = (uint32_t)A0lo, a02 = (uint32_t)(A0lo >> 32);
                uint32_t a01 = (uint32_t)A0hi, a03 = (uint32_t)(A0hi >> 32);
                uint32_t a10 = (uint32_t)A1lo, a12 = (uint32_t)(A1lo >> 32);
                uint32_t a11 = (uint32_t)A1hi, a13 = (uint32_t)(A1hi >> 32);
                const uint32_t* p0 = pbase + (pair * 2) * 176 + (pxg * 8 + a) * 8;
                const uint32_t* p1 = p0 + 176;
#pragma unroll
                for (int j = 0; j < 8; j++) {
                    uint32_t b0 = p0[j * 8], b1 = p1[j * 8];
                    mma_bf16(c[0][j], a00, a01, a02, a03, b0, b1);
                    mma_bf16(c[1][j], a10, a11, a12, a13, b0, b1);
                }
            }
        }
    }

#pragma unroll
    for (int mm = 0; mm < 2; mm++) {
        int ocb = ochalf * 128 + ocg * 32 + mm * 16 + g;
        float b_lo = l1b[ocb], b_hi = l1b[ocb + 8];
#pragma unroll
        for (int j = 0; j < 8; j++) {
            int y = ty + pxg * 8 + j;
            int xb = tx + 2 * j4;
            float* o_lo = &l1o[ocb * SP + y * 96 + xb];
            float* o_hi = &l1o[(ocb + 8) * SP + y * 96 + xb];
            o_lo[0] = gelu(c[mm][j][0] + b_lo);
            o_lo[1] = gelu(c[mm][j][1] + b_lo);
            o_hi[0] = gelu(c[mm][j][2] + b_hi);
            o_hi[1] = gelu(c[mm][j][3] + b_hi);
        }
    }
}

// ---------------- l2 ----------------
__global__ void __launch_bounds__(256) k_l2(int4 bbm, int4 blkm, int4 srcm, int4 r2m, int4 dstm,
                                            const float* __restrict__ Wb, const float* __restrict__ biasb) {
    __shared__ float swT[64 * 68];
    __shared__ float sin_[4096];
    const int band = blockIdx.y;
    const int bb = m4(bbm, band);
    const int blk = m4(blkm, band);
    const float* W = Wb + blk * 16384;
    const float* bias = biasb + blk * 64;
    const float* l1o = g_l1o + bb * L1OSZ;
    const int p0 = blockIdx.x * 64;
    const int ocg = threadIdx.x >> 4, pg = threadIdx.x & 15;
    float acc[4][4] = {};
    for (int c0 = 0; c0 < 256; c0 += 64) {
        __syncthreads();
        for (int t = threadIdx.x; t < 4096; t += 256) {
            int co = t >> 6, ci = t & 63;
            swT[ci * 68 + co] = W[co * 256 + c0 + ci];
        }
        for (int t = threadIdx.x; t < 4096; t += 256) {
            int ci = t >> 6, p = t & 63;
            sin_[t] = l1o[(c0 + ci) * SP + p0 + p];
        }
        __syncthreads();
#pragma unroll 4
        for (int ci = 0; ci < 64; ci++) {
            float4 w4 = *(const float4*)&swT[ci * 68 + ocg * 4];
            float4 i4 = *(const float4*)&sin_[ci * 64 + pg * 4];
            acc[0][0] += w4.x * i4.x; acc[0][1] += w4.x * i4.y; acc[0][2] += w4.x * i4.z; acc[0][3] += w4.x * i4.w;
            acc[1][0] += w4.y * i4.x; acc[1][1] += w4.y * i4.y; acc[1][2] += w4.y * i4.z; acc[1][3] += w4.y * i4.w;
            acc[2][0] += w4.z * i4.x; acc[2][1] += w4.z * i4.y; acc[2][2] += w4.z * i4.z; acc[2][3] += w4.z * i4.w;
            acc[3][0] += w4.w * i4.x; acc[3][1] += w4.w * i4.y; acc[3][2] += w4.w * i4.z; acc[3][3] += w4.w * i4.w;
        }
    }
    float* dstp = g_feat[m4(dstm, band)];
    const float* rp1 = g_feat[m4(srcm, band)];
    const int r2 = m4(r2m, band);
    const float* rp2 = (r2 >= 0) ? g_feat[r2] : 0;
#pragma unroll
    for (int o = 0; o < 4; o++) {
        int oc = ocg * 4 + o;
        float bi = bias[oc];
#pragma unroll
        for (int p = 0; p < 4; p++) {
            int idx = oc * SP + p0 + pg * 4 + p;
            float v = acc[o][p] + bi + rp1[idx];
            if (rp2) v += rp2[idx];
            dstp[idx] = v;
        }
    }
}

// ---------------- xblock Gram + row-sum ----------------
__global__ void __launch_bounds__(256) k_xg(int4 srcm) {
    __shared__ float sf[1024];
    const int band = blockIdx.y;
    const float* f = g_feat[m4(srcm, band)];
    float* Gp = g_G + band * 4096;
    float* sp = g_s + band * 64;
    const int ag = threadIdx.x >> 4, bg = threadIdx.x & 15;
    float acc[4][4] = {};
    float sacc[4] = {};
    const int tok0 = blockIdx.x * 144;
    for (int tb = 0; tb < 144; tb += 16) {
        __syncthreads();
        for (int t2 = threadIdx.x; t2 < 1024; t2 += 256) sf[t2] = f[(tok0 + tb) * 64 + t2];
        __syncthreads();
#pragma unroll
        for (int tk = 0; tk < 16; tk++) {
            float4 fa = *(const float4*)&sf[tk * 64 + ag * 4];
            float4 fb = *(const float4*)&sf[tk * 64 + bg * 4];
            acc[0][0] += fa.x * fb.x; acc[0][1] += fa.x * fb.y; acc[0][2] += fa.x * fb.z; acc[0][3] += fa.x * fb.w;
            acc[1][0] += fa.y * fb.x; acc[1][1] += fa.y * fb.y; acc[1][2] += fa.y * fb.z; acc[1][3] += fa.y * fb.w;
            acc[2][0] += fa.z * fb.x; acc[2][1] += fa.z * fb.y; acc[2][2] += fa.z * fb.z; acc[2][3] += fa.z * fb.w;
            acc[3][0] += fa.w * fb.x; acc[3][1] += fa.w * fb.y; acc[3][2] += fa.w * fb.z; acc[3][3] += fa.w * fb.w;
            if (ag == 0) { sacc[0] += fb.x; sacc[1] += fb.y; sacc[2] += fb.z; sacc[3] += fb.w; }
        }
    }
    for (int i2 = 0; i2 < 4; i2++)
        for (int j2 = 0; j2 < 4; j2++)
            atomicAdd(&Gp[(ag * 4 + i2) * 64 + bg * 4 + j2], acc[i2][j2]);
    if (ag == 0)
        for (int j2 = 0; j2 < 4; j2++) atomicAdd(&sp[bg * 4 + j2], sacc[j2]);
}

// ---------------- attention core ----------------
__global__ void __launch_bounds__(256) k_xatt(const float* __restrict__ xqw, const float* __restrict__ xqb,
                                              const float* __restrict__ xkw, const float* __restrict__ xkb,
                                              const float* __restrict__ xvw, const float* __restrict__ xvb,
                                              int4 imap) {
    __shared__ float sA[4096];
    __shared__ float sGK[4096];
    __shared__ float ss[64], sQs[64], sKs[64];
    const int band = blockIdx.x;
    const int iw = m4(imap, band);
    const float* Qw = xqw + iw * 4096; const float* Qb = xqb + iw * 64;
    const float* Kw = xkw + iw * 4096; const float* Kb = xkb + iw * 64;
    const float* Vw = xvw + iw * 4096; const float* Vb = xvb + iw * 64;
    const float scale = (iw == 0) ? 0.44721359549995793f : 0.70710678118654752f;
    float* Gp = g_G + band * 4096;
    float* sp = g_s + band * 64;
    const int t = threadIdx.x;
    for (int i = t; i < 4096; i += 256) sA[i] = Gp[i];
    if (t < 64) ss[t] = sp[t];
    __syncthreads();
    if (t < 64) {
        float q = 0.f;
        for (int a2 = 0; a2 < 64; a2++) q += Qw[t * 64 + a2] * ss[a2];
        sQs[t] = q;
    } else if (t < 128) {
        int d = t - 64; float q = 0.f;
        for (int b2 = 0; b2 < 64; b2++) q += Kw[d * 64 + b2] * ss[b2];
        sKs[d] = q;
    }
    for (int i = t; i < 4096; i += 256) {
        int a2 = i >> 6, d = i & 63;
        float s2 = 0.f;
        for (int b2 = 0; b2 < 64; b2++) s2 += sA[a2 * 64 + b2] * Kw[d * 64 + b2];
        sGK[i] = s2;
    }
    __syncthreads();
    for (int i = t; i < 4096; i += 256) Gp[i] = 0.f;
    if (t < 64) sp[t] = 0.f;
    for (int i = t; i < 4096; i += 256) {
        int c = i >> 6, d = i & 63;
        float s2 = Qb[c] * sKs[d] + sQs[c] * Kb[d] + 9216.0f * Qb[c] * Kb[d];
        for (int a2 = 0; a2 < 64; a2++) s2 += Qw[c * 64 + a2] * sGK[a2 * 64 + d];
        sA[i] = s2 * scale;
    }
    __syncthreads();
    if (t < 64) {
        float mx = -1e30f;
        for (int d = 0; d < 64; d++) mx = fmaxf(mx, sA[t * 64 + d]);
        float sm = 0.f;
        for (int d = 0; d < 64; d++) { float e = expf(sA[t * 64 + d] - mx); sA[t * 64 + d] = e; sm += e; }
        float r = 1.0f / sm;
        for (int d = 0; d < 64; d++) sA[t * 64 + d] *= r;
    }
    __syncthreads();
    for (int i = t; i < 4096; i += 256) {
        int a2 = i >> 6, d = i & 63;
        float s2 = 0.f;
        for (int c = 0; c < 64; c++) s2 += Vw[c * 64 + a2] * sA[c * 64 + d];
        g_M[band * 4096 + i] = s2;
    }
    if (t < 64) {
        float s2 = 0.f;
        for (int c = 0; c < 64; c++) s2 += Vb[c] * sA[c * 64 + t];
        g_bias[band * 64 + t] = s2;
    }
}

// ---------------- xblock apply ----------------
__global__ void __launch_bounds__(256) k_xapply(int4 srcm, int4 dstm) {
    __shared__ float sM[4096];
    __shared__ float sb[64];
    __shared__ float sf[2048];
    const int band = blockIdx.y;
    for (int t = threadIdx.x; t < 4096; t += 256) sM[t] = g_M[band * 4096 + t];
    if (threadIdx.x < 64) sb[threadIdx.x] = g_bias[band * 64 + threadIdx.x];
    const int tok0 = blockIdx.x * 32;
    const float* f = g_feat[m4(srcm, band)];
    for (int t = threadIdx.x; t < 2048; t += 256) sf[t] = f[tok0 * 64 + t];
    __syncthreads();
    const int tk = threadIdx.x >> 3, dg = threadIdx.x & 7;
    float acc[8] = {};
#pragma unroll 8
    for (int a2 = 0; a2 < 64; a2++) {
        float fa = sf[tk * 64 + a2];
        float4 m0 = *(const float4*)&sM[a2 * 64 + dg * 8];
        float4 m1 = *(const float4*)&sM[a2 * 64 + dg * 8 + 4];
        acc[0] += fa * m0.x; acc[1] += fa * m0.y; acc[2] += fa * m0.z; acc[3] += fa * m0.w;
        acc[4] += fa * m1.x; acc[5] += fa * m1.y; acc[6] += fa * m1.z; acc[7] += fa * m1.w;
    }
    float* dp = g_feat[m4(dstm, band)];
    const int base = (tok0 + tk) * 64 + dg * 8;
#pragma unroll
    for (int d2 = 0; d2 < 8; d2++) dp[base + d2] = sf[tk * 64 + dg * 8 + d2] + acc[d2] + sb[dg * 8 + d2];
}

// ---------------- op: smem-tiled 16x16 px, 8-channel chunks ----------------
__global__ void __launch_bounds__(256) k_op(int4 srcm, int4 outm, const float* __restrict__ w,
                                            const float* __restrict__ bb) {
    __shared__ float sw[576];
    __shared__ float sx[8 * 324];
    const int band = blockIdx.y;
    const int bx = blockIdx.x;
    const int u0 = (bx / 6) * 16, v0 = (bx % 6) * 16;
    for (int t = threadIdx.x; t < 576; t += 256) {
        int ch = t / 9, k2 = t % 9; int a = k2 / 3, b2 = k2 % 3;
        sw[t] = w[ch * 9 + (2 - a) * 3 + (2 - b2)];
    }
    const float* x = g_feat[m4(srcm, band)];
    const int tu = threadIdx.x / 16, tv = threadIdx.x % 16;
    float acc = bb[0];
    for (int cg = 0; cg < 8; cg++) {
        __syncthreads();
        for (int t = threadIdx.x; t < 2592; t += 256) {
            int c = t / 324, rr = (t % 324) / 18, cc = t % 18;
            int gy = u0 - 1 + rr, gx = v0 - 1 + cc;
            sx[t] = (gy >= 0 && gy < 96 && gx >= 0 && gx < 96) ? x[(cg * 8 + c) * SP + gy * 96 + gx] : 0.f;
        }
        __syncthreads();
#pragma unroll
        for (int c = 0; c < 8; c++) {
            int ch = cg * 8 + c;
#pragma unroll
            for (int a = 0; a < 3; a++)
#pragma unroll
                for (int b2 = 0; b2 < 3; b2++)
                    acc += sx[c * 324 + (tu + a) * 18 + (tv + b2)] * sw[ch * 9 + a * 3 + b2];
        }
    }
    int u = u0 + tu, v = v0 + tv;
    g_opout[m4(outm, band)][v * 96 + u] = acc;
}

__global__ void __launch_bounds__(256) k_idwt(const float* __restrict__ img, float* __restrict__ out) {
    int idx = blockIdx.x * 256 + threadIdx.x;
    if (idx >= SP) return;
    int i = idx / 96, j = idx % 96;
    float a = g_opout[0][idx], b = g_opout[1][idx], c = g_opout[2][idx], d = g_opout[3][idx];
    int r0 = (2 * i) * 192 + 2 * j;
    int r1 = (2 * i + 1) * 192 + 2 * j;
    out[r0]     = 0.5f * (a + b + c + d) + img[r0];
    out[r0 + 1] = 0.5f * (a - b + c - d) + img[r0 + 1];
    out[r1]     = 0.5f * (a + b - c - d) + img[r1];
    out[r1 + 1] = 0.5f * (a - b - c + d) + img[r1 + 1];
}

extern "C" void kernel_launch(void* const* d_in, const int* in_sizes, int n_in,
                              void* d_out, int out_size) {
    (void)in_sizes; (void)n_in; (void)out_size;
    const float* images = (const float*)d_in[0];
    const float* ip_w  = (const float*)d_in[1];
    const float* ip_b  = (const float*)d_in[2];
    const float* op_w  = (const float*)d_in[3];
    const float* op_b  = (const float*)d_in[4];
    const float* cb_dw = (const float*)d_in[5];
    const float* cb_pw = (const float*)d_in[6];
    const float* cb_l1w = (const float*)d_in[7];
    const float* cb_l1b = (const float*)d_in[8];
    const float* cb_l2w = (const float*)d_in[9];
    const float* cb_l2b = (const float*)d_in[10];
    const float* xqw = (const float*)d_in[11];
    const float* xqb = (const float*)d_in[12];
    const float* xkw = (const float*)d_in[13];
    const float* xkb = (const float*)d_in[14];
    const float* xvw = (const float*)d_in[15];
    const float* xvb = (const float*)d_in[16];
    float* out = (float*)d_out;

    cudaFuncSetAttribute(k_l1mma, cudaFuncAttributeMaxDynamicSharedMemorySize, L1_SMEMB);

    k_dwt<<<36, 256>>>(images);
    k_l1wtb<<<(6 * 16 * 2 * 14 * 128 * 8 + 255) / 256, 256>>>(cb_l1w);

    auto cb = [&](int nb, int4 bbm, int4 blkm, int4 srcm, int4 r2m, int4 dstm) {
        k_dw7<<<dim3(4, 4, 64 * nb), 256>>>(srcm, bbm, blkm, cb_dw);
        k_pw<<<dim3(163, nb), 256>>>(bbm, blkm, cb_pw);
        k_l1mma<<<dim3(12, 6, 2 * nb), 256, L1_SMEMB>>>(bbm, blkm, cb_l1b);
        k_l2<<<dim3(144, nb), 256>>>(bbm, blkm, srcm, r2m, dstm, cb_l2w, cb_l2b);
    };

    // slots: HF band b (b=0..2): A=2b, B=2b+1 ; LF: lf=6, c1=7, c2=8, xlow=9, c3=10, c4=11
    const int4 bb4   = make_int4(0, 1, 2, 3);
    const int4 bbLF  = make_int4(3, 3, 3, 3);

    // Stage A: ip all 4 bands
    k_ip<<<dim3(2304, 4), 256>>>(make_int4(1, 2, 3, 0), make_int4(0, 2, 4, 6), ip_w, ip_b);

    // Stage B: CB-I (HF blk4: A->B ; LF blk0: lf->c1)
    cb(4, bb4, make_int4(4, 4, 4, 0), make_int4(0, 2, 4, 6),
       make_int4(-1, -1, -1, -1), make_int4(1, 3, 5, 7));

    // Stage C: cb1 LF-only (c2 = cb1(c1) + c1)
    cb(1, bbLF, make_int4(1, 1, 1, 1), make_int4(7, 7, 7, 7),
       make_int4(7, 7, 7, 7), make_int4(8, 8, 8, 8));

    // Stage D: XB all 4 bands
    {
        int4 srcm = make_int4(1, 3, 5, 7);
        int4 dstm = make_int4(0, 2, 4, 9);
        k_xg<<<dim3(64, 4), 256>>>(srcm);
        k_xatt<<<4, 256>>>(xqw, xqb, xkw, xkb, xvw, xvb, make_int4(1, 1, 1, 0));
        k_xapply<<<dim3(288, 4), 256>>>(srcm, dstm);
    }

    // Stage E: CB-II (HF blk5: h2 = cb5(hx)+h1 ; LF blk2: c3 = cb2(xlow)+c2)
    cb(4, bb4, make_int4(5, 5, 5, 2), make_int4(0, 2, 4, 9),
       make_int4(1, 3, 5, 8), make_int4(1, 3, 5, 10));

    // Stage F: cb3 LF-only (c4 = cb3(c3) + c1)
    cb(1, bbLF, make_int4(3, 3, 3, 3), make_int4(10, 10, 10, 10),
       make_int4(7, 7, 7, 7), make_int4(11, 11, 11, 11));

    // Stage G: op all 4 bands
    k_op<<<dim3(36, 4), 256>>>(make_int4(1, 3, 5, 11), make_int4(1, 2, 3, 0), op_w, op_b);

    k_idwt<<<36, 256>>>(images, out);
}

// round 13
// speedup vs baseline: 5.2393x; 1.0409x over previous
#include <cuda_runtime.h>
#include <cuda_bf16.h>
#include <math.h>
#include <stdint.h>

#define CC 64
#define SP 9216
#define PP 102
#define SPP 10404
#define NLN 665856
#define CSPP (CC * SPP)
#define L1OSZ (4 * CC * SP)

typedef unsigned long long u64t;

__device__ __forceinline__ int m4(int4 v, int i) { return ((const int*)&v)[i]; }

// ---------------- scratch ----------------
__device__ float g_band[4][SP];
__device__ float g_opout[4][SP];
__device__ float g_feat[12][CC * SP];
__device__ float g_dwo[4 * CSPP];
__device__ float g_pwo[4 * CSPP];
__device__ float g_l1o[4 * L1OSZ];
__device__ __align__(16) uint32_t g_l1w_bf[6 * 16 * 2 * 14 * 128 * 8];
__device__ __align__(16) float g_l2wT[6 * 32 * 64 * 8];   // [blk][k8 32][oc 64][j4*2+e], tf32
__device__ float g_red[8];
__device__ float g_G[4 * 4096];
__device__ float g_s[4 * 64];
__device__ float g_M[4 * 4096];
__device__ float g_bias[4 * 64];

__device__ __forceinline__ float gelu(float x) {
    return 0.5f * x * (1.0f + erff(x * 0.70710678118654752f));
}
__device__ __forceinline__ void mma_bf16(float* c, uint32_t a0, uint32_t a1, uint32_t a2,
                                         uint32_t a3, uint32_t b0, uint32_t b1) {
    asm volatile(
        "mma.sync.aligned.m16n8k16.row.col.f32.bf16.bf16.f32 "
        "{%0,%1,%2,%3}, {%4,%5,%6,%7}, {%8,%9}, {%0,%1,%2,%3};"
        : "+f"(c[0]), "+f"(c[1]), "+f"(c[2]), "+f"(c[3])
        : "r"(a0), "r"(a1), "r"(a2), "r"(a3), "r"(b0), "r"(b1));
}
__device__ __forceinline__ void mma_tf32(float* c, uint32_t a0, uint32_t a1, uint32_t a2,
                                         uint32_t a3, uint32_t b0, uint32_t b1) {
    asm volatile(
        "mma.sync.aligned.m16n8k8.row.col.f32.tf32.tf32.f32 "
        "{%0,%1,%2,%3}, {%4,%5,%6,%7}, {%8,%9}, {%0,%1,%2,%3};"
        : "+f"(c[0]), "+f"(c[1]), "+f"(c[2]), "+f"(c[3])
        : "r"(a0), "r"(a1), "r"(a2), "r"(a3), "r"(b0), "r"(b1));
}
__device__ __forceinline__ uint32_t f2tf32(float x) {
    uint32_t r;
    asm("cvt.rna.tf32.f32 %0, %1;" : "=r"(r) : "f"(x));
    return r;
}

// ---------------- DWT (+ zero attention accumulators) ----------------
__global__ void __launch_bounds__(256) k_dwt(const float* __restrict__ img) {
    if (blockIdx.x == 0) {
        for (int t = threadIdx.x; t < 4 * 4096; t += 256) g_G[t] = 0.f;
        if (threadIdx.x < 4 * 64) g_s[threadIdx.x] = 0.f;
    }
    int idx = blockIdx.x * 256 + threadIdx.x;
    if (idx >= SP) return;
    int i = idx / 96, j = idx % 96;
    float a = img[(2 * i) * 192 + 2 * j];
    float b = img[(2 * i + 1) * 192 + 2 * j];
    float c = img[(2 * i) * 192 + 2 * j + 1];
    float d = img[(2 * i + 1) * 192 + 2 * j + 1];
    g_band[0][idx] = (a + b + c + d) * 0.5f;
    g_band[1][idx] = (a + b - c - d) * 0.5f;
    g_band[2][idx] = (a - b + c - d) * 0.5f;
    g_band[3][idx] = (a - b - c + d) * 0.5f;
}

// ---------------- l1 weight prepack to bf16 ----------------
__global__ void __launch_bounds__(256) k_l1wtb(const float* __restrict__ w) {
    int idx = blockIdx.x * 256 + threadIdx.x;
    const int total = 6 * 16 * 2 * 14 * 128 * 8;
    if (idx >= total) return;
    int q = idx & 7;
    int j4 = q >> 1, h = q & 1;
    int t = idx >> 3;
    int oc_l = t & 127; t >>= 7;
    int seg = t % 14; t /= 14;
    int ochalf = t & 1; t >>= 1;
    int icg = t & 15;
    int blk = t >> 4;
    int pair = seg / 7, a = seg % 7;
    int ic = icg * 4 + pair * 2 + h;
    int oc = ochalf * 128 + oc_l;
    int b0t = 2 * j4, b1t = 2 * j4 + 1;
    const float* wb = w + ((size_t)(blk * 256 + oc) * 64 + ic) * 49 + a * 7;
    float w0 = wb[b0t];
    float w1 = (b1t < 7) ? wb[b1t] : 0.f;
    uint32_t lo = __bfloat16_as_ushort(__float2bfloat16(w0));
    uint32_t hi = __bfloat16_as_ushort(__float2bfloat16(w1));
    g_l1w_bf[idx] = lo | (hi << 16);
}

// ---------------- l2 weight prepack to tf32 ----------------
__global__ void __launch_bounds__(256) k_l2wt(const float* __restrict__ w) {
    int idx = blockIdx.x * 256 + threadIdx.x;
    const int total = 6 * 32 * 64 * 8;
    if (idx >= total) return;
    int e = idx & 1;
    int j4 = (idx >> 1) & 3;
    int oc = (idx >> 3) & 63;
    int k8 = (idx >> 9) & 31;
    int blk = idx >> 14;
    float v = w[(size_t)(blk * 64 + oc) * 256 + k8 * 8 + j4 + 4 * e];
    g_l2wT[idx] = __uint_as_float(f2tf32(v));
}

// ---------------- ip ----------------
__global__ void __launch_bounds__(256) k_ip(int4 bim, int4 outm, const float* __restrict__ w,
                                            const float* __restrict__ bb) {
    __shared__ float sw[576];
    __shared__ float sb2[64];
    const int band = blockIdx.y;
    for (int t = threadIdx.x; t < 576; t += 256) sw[t] = w[t];
    if (threadIdx.x < 64) sb2[threadIdx.x] = bb[threadIdx.x];
    __syncthreads();
    int idx = blockIdx.x * 256 + threadIdx.x;
    if (idx >= CC * SP) return;
    int v = idx % 96; int u = (idx / 96) % 96; int ch = idx / SP;
    const float* src = g_band[m4(bim, band)];
    float acc = sb2[ch];
#pragma unroll
    for (int a = 0; a < 3; a++) {
        int x0 = u + a - 1;
        if ((unsigned)x0 < 96u) {
#pragma unroll
            for (int b2 = 0; b2 < 3; b2++) {
                int y0 = v + b2 - 1;
                if ((unsigned)y0 < 96u) acc += src[y0 * 96 + x0] * sw[ch * 9 + a * 3 + b2];
            }
        }
    }
    g_feat[m4(outm, band)][idx] = acc;
}

// ---------------- depthwise 7x7, register-blocked 4px/thread ----------------
__global__ void __launch_bounds__(256) k_dw7(int4 srcm, int4 bbm, int4 blkm,
                                             const float* __restrict__ dwwb) {
    __shared__ __align__(16) float sw[64];
    __shared__ __align__(16) float spt[38 * 40];
    const int band = blockIdx.z >> 6;
    const int ch = blockIdx.z & 63;
    const int bb = m4(bbm, band);
    if (blockIdx.x == 0 && blockIdx.y == 0 && ch == 0 && threadIdx.x < 2)
        g_red[bb * 2 + threadIdx.x] = 0.f;
    const float* dww = dwwb + m4(blkm, band) * 3136;
    const int ty0 = blockIdx.y * 32, tx0 = blockIdx.x * 32;
    if (threadIdx.x < 49) sw[threadIdx.x] = dww[ch * 49 + threadIdx.x];
    const float* src = g_feat[m4(srcm, band)] + ch * SP;
    for (int t = threadIdx.x; t < 1520; t += 256) {
        int r = t / 40, c = t % 40;
        int gy = ty0 - 6 + r, gx = tx0 - 6 + c;
        spt[t] = (c < 38 && gy >= 0 && gy < 96 && gx >= 0 && gx < 96) ? src[gy * 96 + gx] : 0.f;
    }
    __syncthreads();
    const int ly = threadIdx.x >> 3, lx0 = (threadIdx.x & 7) * 4;
    const int oy = ty0 + ly;
    if (oy >= PP) return;
    float acc[4] = {0.f, 0.f, 0.f, 0.f};
#pragma unroll
    for (int a = 0; a < 7; a++) {
        const float* row = &spt[(ly + a) * 40 + lx0];
        float4 r0 = *(const float4*)row;
        float4 r1 = *(const float4*)(row + 4);
        float2 r2 = *(const float2*)(row + 8);
        float rr[10] = {r0.x, r0.y, r0.z, r0.w, r1.x, r1.y, r1.z, r1.w, r2.x, r2.y};
#pragma unroll
        for (int b = 0; b < 7; b++) {
            float wv = sw[a * 7 + b];
            acc[0] += rr[b] * wv;
            acc[1] += rr[b + 1] * wv;
            acc[2] += rr[b + 2] * wv;
            acc[3] += rr[b + 3] * wv;
        }
    }
    float* dst = g_dwo + bb * CSPP + ch * SPP + oy * PP;
#pragma unroll
    for (int k = 0; k < 4; k++) {
        int ox = tx0 + lx0 + k;
        if (ox < PP) dst[ox] = acc[k];
    }
}

// ---------------- pointwise + per-band LN reduction ----------------
__global__ void __launch_bounds__(256) k_pw(int4 bbm, int4 blkm, const float* __restrict__ Wb) {
    __shared__ float swT[64 * 68];
    __shared__ float sin_[4096];
    __shared__ float sr[2][8];
    const int band = blockIdx.y;
    const int bb = m4(bbm, band);
    const float* W = Wb + m4(blkm, band) * 4096;
    const float* dwo = g_dwo + bb * CSPP;
    float* pwo = g_pwo + bb * CSPP;
    const int p0 = blockIdx.x * 64;
    for (int t = threadIdx.x; t < 4096; t += 256) {
        int co = t >> 6, ci = t & 63;
        swT[ci * 68 + co] = W[t];
    }
    for (int t = threadIdx.x; t < 4096; t += 256) {
        int ci = t >> 6, p = t & 63; int gp = p0 + p;
        sin_[t] = (gp < SPP) ? dwo[ci * SPP + gp] : 0.f;
    }
    __syncthreads();
    const int ocg = threadIdx.x >> 4, pg = threadIdx.x & 15;
    float acc[4][4] = {};
#pragma unroll 4
    for (int ci = 0; ci < 64; ci++) {
        float4 w4 = *(const float4*)&swT[ci * 68 + ocg * 4];
        float4 i4 = *(const float4*)&sin_[ci * 64 + pg * 4];
        acc[0][0] += w4.x * i4.x; acc[0][1] += w4.x * i4.y; acc[0][2] += w4.x * i4.z; acc[0][3] += w4.x * i4.w;
        acc[1][0] += w4.y * i4.x; acc[1][1] += w4.y * i4.y; acc[1][2] += w4.y * i4.z; acc[1][3] += w4.y * i4.w;
        acc[2][0] += w4.z * i4.x; acc[2][1] += w4.z * i4.y; acc[2][2] += w4.z * i4.z; acc[2][3] += w4.z * i4.w;
        acc[3][0] += w4.w * i4.x; acc[3][1] += w4.w * i4.y; acc[3][2] += w4.w * i4.z; acc[3][3] += w4.w * i4.w;
    }
    float ls = 0.f, ls2 = 0.f;
#pragma unroll
    for (int o = 0; o < 4; o++) {
        int oc = ocg * 4 + o;
#pragma unroll
        for (int p = 0; p < 4; p++) {
            int gp = p0 + pg * 4 + p;
            if (gp < SPP) {
                float v = acc[o][p];
                pwo[oc * SPP + gp] = v;
                ls += v; ls2 += v * v;
            }
        }
    }
    for (int off = 16; off; off >>= 1) {
        ls += __shfl_down_sync(0xffffffffu, ls, off);
        ls2 += __shfl_down_sync(0xffffffffu, ls2, off);
    }
    if ((threadIdx.x & 31) == 0) { sr[0][threadIdx.x >> 5] = ls; sr[1][threadIdx.x >> 5] = ls2; }
    __syncthreads();
    if (threadIdx.x == 0) {
        float a = 0.f, b = 0.f;
        for (int w2 = 0; w2 < 8; w2++) { a += sr[0][w2]; b += sr[1][w2]; }
        atomicAdd(&g_red[bb * 2], a); atomicAdd(&g_red[bb * 2 + 1], b);
    }
}

// ---------------- l1 via bf16 mma (z = band*2 + ochalf) ----------------
#define L1_WBUF 14336
#define L1_IN   1408
#define L1_SMEMB ((L1_WBUF + L1_IN) * 4)

__global__ void __launch_bounds__(256) k_l1mma(int4 bbm, int4 blkm, const float* __restrict__ l1bb) {
    extern __shared__ uint32_t sm[];
    uint32_t* s_in = sm + L1_WBUF;
    const int tid = threadIdx.x;
    const int tx = blockIdx.x * 8, ty = blockIdx.y * 16;
    const int band = blockIdx.z >> 1;
    const int ochalf = blockIdx.z & 1;
    const int bb = m4(bbm, band);
    const int blk = m4(blkm, band);
    const float* l1b = l1bb + blk * 256;
    const int wid = tid >> 5, lane = tid & 31;
    const int ocg = wid >> 1, pxg = wid & 1;
    const int g = lane >> 2, j4 = lane & 3;

    const float m = g_red[bb * 2] * (1.0f / (float)NLN);
    const float inv = rsqrtf(g_red[bb * 2 + 1] * (1.0f / (float)NLN) - m * m + 1e-5f);
    const float* pwo = g_pwo + bb * CSPP;
    float* l1o = g_l1o + bb * L1OSZ;

    for (int t = tid; t < L1_IN; t += 256) s_in[t] = 0u;

    float c[2][8][4] = {};
    unsigned short* s_ine = (unsigned short*)s_in;
    unsigned short* s_ino = (unsigned short*)(s_in + 704);

    for (int icg = 0; icg < 16; icg++) {
        __syncthreads();
        {
            size_t chunk = ((size_t)(blk * 16 + icg) * 2 + ochalf) * L1_WBUF;
            const uint4* src = (const uint4*)(g_l1w_bf + chunk);
            uint4* dstw = (uint4*)sm;
#pragma unroll
            for (int i = 0; i < 14; i++)
                dstw[tid + i * 256] = src[tid + i * 256];
        }
        for (int t = tid; t < 1232; t += 256) {
            int ic = t / 308, r2 = t % 308;
            int r = r2 / 14, cx = r2 % 14;
            float v = (pwo[(icg * 4 + ic) * SPP + (ty + r) * PP + (tx + cx)] - m) * inv;
            unsigned short hb = __bfloat16_as_ushort(__float2bfloat16(v));
            int rowb = (ic * 22 + r) * 16;
            s_ine[rowb + cx] = hb;
            if (cx >= 1) s_ino[rowb + cx - 1] = hb;
        }
        __syncthreads();

        const uint32_t* wb = sm;
        const int r0 = ocg * 32 + g;
        const uint32_t* pbase = s_in + (g & 1) * 704 + ((g >> 1) + j4);
#pragma unroll
        for (int pair = 0; pair < 2; pair++) {
#pragma unroll
            for (int a = 0; a < 7; a++) {
                const uint32_t* ws = wb + (pair * 7 + a) * 1024 + 2 * j4;
                u64t A0lo = *(const u64t*)(ws + r0 * 8);
                u64t A0hi = *(const u64t*)(ws + (r0 + 8) * 8);
                u64t A1lo = *(const u64t*)(ws + (r0 + 16) * 8);
                u64t A1hi = *(const u64t*)(ws + (r0 + 24) * 8);
                uint32_t a00 = (uint32_t)A0lo, a02 = (uint32_t)(A0lo >> 32);
                uint32_t a01 = (uint32_t)A0hi, a03 = (uint32_t)(A0hi >> 32);
                uint32_t a10 = (uint32_t)A1lo, a12 = (uint32_t)(A1lo >> 32);
                uint32_t a11 = (uint32_t)A1hi, a13 = (uint32_t)(A1hi >> 32);
                const uint32_t* p0 = pbase + (pair * 2) * 176 + (pxg * 8 + a) * 8;
                const uint32_t* p1 = p0 + 176;
#pragma unroll
                for (int j = 0; j < 8; j++) {
                    uint32_t b0 = p0[j * 8], b1 = p1[j * 8];
                    mma_bf16(c[0][j], a00, a01, a02, a03, b0, b1);
                    mma_bf16(c[1][j], a10, a11, a12, a13, b0, b1);
                }
            }
        }
    }

#pragma unroll
    for (int mm = 0; mm < 2; mm++) {
        int ocb = ochalf * 128 + ocg * 32 + mm * 16 + g;
        float b_lo = l1b[ocb], b_hi = l1b[ocb + 8];
#pragma unroll
        for (int j = 0; j < 8; j++) {
            int y = ty + pxg * 8 + j;
            int xb = tx + 2 * j4;
            float* o_lo = &l1o[ocb * SP + y * 96 + xb];
            float* o_hi = &l1o[(ocb + 8) * SP + y * 96 + xb];
            o_lo[0] = gelu(c[mm][j][0] + b_lo);
            o_lo[1] = gelu(c[mm][j][1] + b_lo);
            o_hi[0] = gelu(c[mm][j][2] + b_hi);
            o_hi[1] = gelu(c[mm][j][3] + b_hi);
        }
    }
}

// ---------------- l2 via tf32 mma: 64oc x 128px blocks, K=256 ----------------
__global__ void __launch_bounds__(256) k_l2(int4 bbm, int4 blkm, int4 srcm, int4 r2m, int4 dstm,
                                            const float* __restrict__ biasb) {
    __shared__ __align__(16) float swt[4096];   // [k8 8][oc 64][8]
    __shared__ __align__(16) float sin_[8192];  // [k 64][px 128], tf32-rounded
    const int band = blockIdx.y;
    const int bb = m4(bbm, band);
    const int blk = m4(blkm, band);
    const float* bias = biasb + blk * 64;
    const float* l1o = g_l1o + bb * L1OSZ;
    const int p0 = blockIdx.x * 128;
    const int tid = threadIdx.x;
    const int wid = tid >> 5, lane = tid & 31;
    const int ocg = wid >> 1, pxg = wid & 1;
    const int g = lane >> 2, j4 = lane & 3;

    float c[8][4] = {};

    for (int c0 = 0; c0 < 4; c0++) {
        __syncthreads();
        {
            const float4* src = (const float4*)(g_l2wT + ((size_t)blk * 32 + c0 * 8) * 512);
            float4* dstw = (float4*)swt;
#pragma unroll
            for (int i = 0; i < 4; i++)
                dstw[tid + i * 256] = src[tid + i * 256];
        }
        for (int t = tid; t < 8192; t += 256) {
            int ch = t >> 7, px = t & 127;
            sin_[t] = __uint_as_float(f2tf32(l1o[(c0 * 64 + ch) * SP + p0 + px]));
        }
        __syncthreads();
#pragma unroll
        for (int k8 = 0; k8 < 8; k8++) {
            const float* wsrc = swt + (k8 * 64 + ocg * 16) * 8 + j4 * 2;
            float2 lo = *(const float2*)(wsrc + g * 8);
            float2 hi = *(const float2*)(wsrc + (g + 8) * 8);
            uint32_t a0 = __float_as_uint(lo.x), a2 = __float_as_uint(lo.y);
            uint32_t a1 = __float_as_uint(hi.x), a3 = __float_as_uint(hi.y);
            const float* brow0 = sin_ + (k8 * 8 + j4) * 128 + pxg * 64 + g;
            const float* brow1 = brow0 + 4 * 128;
#pragma unroll
            for (int nt = 0; nt < 8; nt++) {
                uint32_t b0 = __float_as_uint(brow0[nt * 8]);
                uint32_t b1 = __float_as_uint(brow1[nt * 8]);
                mma_tf32(c[nt], a0, a1, a2, a3, b0, b1);
            }
        }
    }

    float* dstp = g_feat[m4(dstm, band)];
    const float* rp1 = g_feat[m4(srcm, band)];
    const int r2 = m4(r2m, band);
    const float* rp2 = (r2 >= 0) ? g_feat[r2] : 0;
    const int oc_lo = ocg * 16 + g, oc_hi = oc_lo + 8;
    const float bi_lo = bias[oc_lo], bi_hi = bias[oc_hi];
#pragma unroll
    for (int nt = 0; nt < 8; nt++) {
        int px = p0 + pxg * 64 + nt * 8 + 2 * j4;
        int i_lo = oc_lo * SP + px;
        int i_hi = oc_hi * SP + px;
        float v0 = c[nt][0] + bi_lo + rp1[i_lo];
        float v1 = c[nt][1] + bi_lo + rp1[i_lo + 1];
        float v2 = c[nt][2] + bi_hi + rp1[i_hi];
        float v3 = c[nt][3] + bi_hi + rp1[i_hi + 1];
        if (rp2) { v0 += rp2[i_lo]; v1 += rp2[i_lo + 1]; v2 += rp2[i_hi]; v3 += rp2[i_hi + 1]; }
        dstp[i_lo] = v0; dstp[i_lo + 1] = v1;
        dstp[i_hi] = v2; dstp[i_hi + 1] = v3;
    }
}

// ---------------- xblock Gram + row-sum ----------------
__global__ void __launch_bounds__(256) k_xg(int4 srcm) {
    __shared__ float sf[1024];
    const int band = blockIdx.y;
    const float* f = g_feat[m4(srcm, band)];
    float* Gp = g_G + band * 4096;
    float* sp = g_s + band * 64;
    const int ag = threadIdx.x >> 4, bg = threadIdx.x & 15;
    float acc[4][4] = {};
    float sacc[4] = {};
    const int tok0 = blockIdx.x * 144;
    for (int tb = 0; tb < 144; tb += 16) {
        __syncthreads();
        for (int t2 = threadIdx.x; t2 < 1024; t2 += 256) sf[t2] = f[(tok0 + tb) * 64 + t2];
        __syncthreads();
#pragma unroll
        for (int tk = 0; tk < 16; tk++) {
            float4 fa = *(const float4*)&sf[tk * 64 + ag * 4];
            float4 fb = *(const float4*)&sf[tk * 64 + bg * 4];
            acc[0][0] += fa.x * fb.x; acc[0][1] += fa.x * fb.y; acc[0][2] += fa.x * fb.z; acc[0][3] += fa.x * fb.w;
            acc[1][0] += fa.y * fb.x; acc[1][1] += fa.y * fb.y; acc[1][2] += fa.y * fb.z; acc[1][3] += fa.y * fb.w;
            acc[2][0] += fa.z * fb.x; acc[2][1] += fa.z * fb.y; acc[2][2] += fa.z * fb.z; acc[2][3] += fa.z * fb.w;
            acc[3][0] += fa.w * fb.x; acc[3][1] += fa.w * fb.y; acc[3][2] += fa.w * fb.z; acc[3][3] += fa.w * fb.w;
            if (ag == 0) { sacc[0] += fb.x; sacc[1] += fb.y; sacc[2] += fb.z; sacc[3] += fb.w; }
        }
    }
    for (int i2 = 0; i2 < 4; i2++)
        for (int j2 = 0; j2 < 4; j2++)
            atomicAdd(&Gp[(ag * 4 + i2) * 64 + bg * 4 + j2], acc[i2][j2]);
    if (ag == 0)
        for (int j2 = 0; j2 < 4; j2++) atomicAdd(&sp[bg * 4 + j2], sacc[j2]);
}

// ---------------- attention core ----------------
__global__ void __launch_bounds__(256) k_xatt(const float* __restrict__ xqw, const float* __restrict__ xqb,
                                              const float* __restrict__ xkw, const float* __restrict__ xkb,
                                              const float* __restrict__ xvw, const float* __restrict__ xvb,
                                              int4 imap) {
    __shared__ float sA[4096];
    __shared__ float sGK[4096];
    __shared__ float ss[64], sQs[64], sKs[64];
    const int band = blockIdx.x;
    const int iw = m4(imap, band);
    const float* Qw = xqw + iw * 4096; const float* Qb = xqb + iw * 64;
    const float* Kw = xkw + iw * 4096; const float* Kb = xkb + iw * 64;
    const float* Vw = xvw + iw * 4096; const float* Vb = xvb + iw * 64;
    const float scale = (iw == 0) ? 0.44721359549995793f : 0.70710678118654752f;
    float* Gp = g_G + band * 4096;
    float* sp = g_s + band * 64;
    const int t = threadIdx.x;
    for (int i = t; i < 4096; i += 256) sA[i] = Gp[i];
    if (t < 64) ss[t] = sp[t];
    __syncthreads();
    if (t < 64) {
        float q = 0.f;
        for (int a2 = 0; a2 < 64; a2++) q += Qw[t * 64 + a2] * ss[a2];
        sQs[t] = q;
    } else if (t < 128) {
        int d = t - 64; float q = 0.f;
        for (int b2 = 0; b2 < 64; b2++) q += Kw[d * 64 + b2] * ss[b2];
        sKs[d] = q;
    }
    for (int i = t; i < 4096; i += 256) {
        int a2 = i >> 6, d = i & 63;
        float s2 = 0.f;
        for (int b2 = 0; b2 < 64; b2++) s2 += sA[a2 * 64 + b2] * Kw[d * 64 + b2];
        sGK[i] = s2;
    }
    __syncthreads();
    for (int i = t; i < 4096; i += 256) Gp[i] = 0.f;
    if (t < 64) sp[t] = 0.f;
    for (int i = t; i < 4096; i += 256) {
        int c = i >> 6, d = i & 63;
        float s2 = Qb[c] * sKs[d] + sQs[c] * Kb[d] + 9216.0f * Qb[c] * Kb[d];
        for (int a2 = 0; a2 < 64; a2++) s2 += Qw[c * 64 + a2] * sGK[a2 * 64 + d];
        sA[i] = s2 * scale;
    }
    __syncthreads();
    if (t < 64) {
        float mx = -1e30f;
        for (int d = 0; d < 64; d++) mx = fmaxf(mx, sA[t * 64 + d]);
        float sm = 0.f;
        for (int d = 0; d < 64; d++) { float e = expf(sA[t * 64 + d] - mx); sA[t * 64 + d] = e; sm += e; }
        float r = 1.0f / sm;
        for (int d = 0; d < 64; d++) sA[t * 64 + d] *= r;
    }
    __syncthreads();
    for (int i = t; i < 4096; i += 256) {
        int a2 = i >> 6, d = i & 63;
        float s2 = 0.f;
        for (int c = 0; c < 64; c++) s2 += Vw[c * 64 + a2] * sA[c * 64 + d];
        g_M[band * 4096 + i] = s2;
    }
    if (t < 64) {
        float s2 = 0.f;
        for (int c = 0; c < 64; c++) s2 += Vb[c] * sA[c * 64 + t];
        g_bias[band * 64 + t] = s2;
    }
}

// ---------------- xblock apply ----------------
__global__ void __launch_bounds__(256) k_xapply(int4 srcm, int4 dstm) {
    __shared__ float sM[4096];
    __shared__ float sb[64];
    __shared__ float sf[2048];
    const int band = blockIdx.y;
    for (int t = threadIdx.x; t < 4096; t += 256) sM[t] = g_M[band * 4096 + t];
    if (threadIdx.x < 64) sb[threadIdx.x] = g_bias[band * 64 + threadIdx.x];
    const int tok0 = blockIdx.x * 32;
    const float* f = g_feat[m4(srcm, band)];
    for (int t = threadIdx.x; t < 2048; t += 256) sf[t] = f[tok0 * 64 + t];
    __syncthreads();
    const int tk = threadIdx.x >> 3, dg = threadIdx.x & 7;
    float acc[8] = {};
#pragma unroll 8
    for (int a2 = 0; a2 < 64; a2++) {
        float fa = sf[tk * 64 + a2];
        float4 m0 = *(const float4*)&sM[a2 * 64 + dg * 8];
        float4 m1 = *(const float4*)&sM[a2 * 64 + dg * 8 + 4];
        acc[0] += fa * m0.x; acc[1] += fa * m0.y; acc[2] += fa * m0.z; acc[3] += fa * m0.w;
        acc[4] += fa * m1.x; acc[5] += fa * m1.y; acc[6] += fa * m1.z; acc[7] += fa * m1.w;
    }
    float* dp = g_feat[m4(dstm, band)];
    const int base = (tok0 + tk) * 64 + dg * 8;
#pragma unroll
    for (int d2 = 0; d2 < 8; d2++) dp[base + d2] = sf[tk * 64 + dg * 8 + d2] + acc[d2] + sb[dg * 8 + d2];
}

// ---------------- op: smem-tiled 16x16 px, 8-channel chunks ----------------
__global__ void __launch_bounds__(256) k_op(int4 srcm, int4 outm, const float* __restrict__ w,
                                            const float* __restrict__ bb) {
    __shared__ float sw[576];
    __shared__ float sx[8 * 324];
    const int band = blockIdx.y;
    const int bx = blockIdx.x;
    const int u0 = (bx / 6) * 16, v0 = (bx % 6) * 16;
    for (int t = threadIdx.x; t < 576; t += 256) {
        int ch = t / 9, k2 = t % 9; int a = k2 / 3, b2 = k2 % 3;
        sw[t] = w[ch * 9 + (2 - a) * 3 + (2 - b2)];
    }
    const float* x = g_feat[m4(srcm, band)];
    const int tu = threadIdx.x / 16, tv = threadIdx.x % 16;
    float acc = bb[0];
    for (int cg = 0; cg < 8; cg++) {
        __syncthreads();
        for (int t = threadIdx.x; t < 2592; t += 256) {
            int c = t / 324, rr = (t % 324) / 18, cc = t % 18;
            int gy = u0 - 1 + rr, gx = v0 - 1 + cc;
            sx[t] = (gy >= 0 && gy < 96 && gx >= 0 && gx < 96) ? x[(cg * 8 + c) * SP + gy * 96 + gx] : 0.f;
        }
        __syncthreads();
#pragma unroll
        for (int c = 0; c < 8; c++) {
            int ch = cg * 8 + c;
#pragma unroll
            for (int a = 0; a < 3; a++)
#pragma unroll
                for (int b2 = 0; b2 < 3; b2++)
                    acc += sx[c * 324 + (tu + a) * 18 + (tv + b2)] * sw[ch * 9 + a * 3 + b2];
        }
    }
    int u = u0 + tu, v = v0 + tv;
    g_opout[m4(outm, band)][v * 96 + u] = acc;
}

__global__ void __launch_bounds__(256) k_idwt(const float* __restrict__ img, float* __restrict__ out) {
    int idx = blockIdx.x * 256 + threadIdx.x;
    if (idx >= SP) return;
    int i = idx / 96, j = idx % 96;
    float a = g_opout[0][idx], b = g_opout[1][idx], c = g_opout[2][idx], d = g_opout[3][idx];
    int r0 = (2 * i) * 192 + 2 * j;
    int r1 = (2 * i + 1) * 192 + 2 * j;
    out[r0]     = 0.5f * (a + b + c + d) + img[r0];
    out[r0 + 1] = 0.5f * (a - b + c - d) + img[r0 + 1];
    out[r1]     = 0.5f * (a + b - c - d) + img[r1];
    out[r1 + 1] = 0.5f * (a - b - c + d) + img[r1 + 1];
}

extern "C" void kernel_launch(void* const* d_in, const int* in_sizes, int n_in,
                              void* d_out, int out_size) {
    (void)in_sizes; (void)n_in; (void)out_size;
    const float* images = (const float*)d_in[0];
    const float* ip_w  = (const float*)d_in[1];
    const float* ip_b  = (const float*)d_in[2];
    const float* op_w  = (const float*)d_in[3];
    const float* op_b  = (const float*)d_in[4];
    const float* cb_dw = (const float*)d_in[5];
    const float* cb_pw = (const float*)d_in[6];
    const float* cb_l1w = (const float*)d_in[7];
    const float* cb_l1b = (const float*)d_in[8];
    const float* cb_l2w = (const float*)d_in[9];
    const float* cb_l2b = (const float*)d_in[10];
    const float* xqw = (const float*)d_in[11];
    const float* xqb = (const float*)d_in[12];
    const float* xkw = (const float*)d_in[13];
    const float* xkb = (const float*)d_in[14];
    const float* xvw = (const float*)d_in[15];
    const float* xvb = (const float*)d_in[16];
    float* out = (float*)d_out;

    cudaFuncSetAttribute(k_l1mma, cudaFuncAttributeMaxDynamicSharedMemorySize, L1_SMEMB);

    k_dwt<<<36, 256>>>(images);
    k_l1wtb<<<(6 * 16 * 2 * 14 * 128 * 8 + 255) / 256, 256>>>(cb_l1w);
    k_l2wt<<<(6 * 32 * 64 * 8 + 255) / 256, 256>>>(cb_l2w);

    auto cb = [&](int nb, int4 bbm, int4 blkm, int4 srcm, int4 r2m, int4 dstm) {
        k_dw7<<<dim3(4, 4, 64 * nb), 256>>>(srcm, bbm, blkm, cb_dw);
        k_pw<<<dim3(163, nb), 256>>>(bbm, blkm, cb_pw);
        k_l1mma<<<dim3(12, 6, 2 * nb), 256, L1_SMEMB>>>(bbm, blkm, cb_l1b);
        k_l2<<<dim3(72, nb), 256>>>(bbm, blkm, srcm, r2m, dstm, cb_l2b);
    };

    // slots: HF band b (b=0..2): A=2b, B=2b+1 ; LF: lf=6, c1=7, c2=8, xlow=9, c3=10, c4=11
    const int4 bb4   = make_int4(0, 1, 2, 3);
    const int4 bbLF  = make_int4(3, 3, 3, 3);

    // Stage A: ip all 4 bands
    k_ip<<<dim3(2304, 4), 256>>>(make_int4(1, 2, 3, 0), make_int4(0, 2, 4, 6), ip_w, ip_b);

    // Stage B: CB-I (HF blk4: A->B ; LF blk0: lf->c1)
    cb(4, bb4, make_int4(4, 4, 4, 0), make_int4(0, 2, 4, 6),
       make_int4(-1, -1, -1, -1), make_int4(1, 3, 5, 7));

    // Stage C: cb1 LF-only (c2 = cb1(c1) + c1)
    cb(1, bbLF, make_int4(1, 1, 1, 1), make_int4(7, 7, 7, 7),
       make_int4(7, 7, 7, 7), make_int4(8, 8, 8, 8));

    // Stage D: XB all 4 bands
    {
        int4 srcm = make_int4(1, 3, 5, 7);
        int4 dstm = make_int4(0, 2, 4, 9);
        k_xg<<<dim3(64, 4), 256>>>(srcm);
        k_xatt<<<4, 256>>>(xqw, xqb, xkw, xkb, xvw, xvb, make_int4(1, 1, 1, 0));
        k_xapply<<<dim3(288, 4), 256>>>(srcm, dstm);
    }

    // Stage E: CB-II (HF blk5: h2 = cb5(hx)+h1 ; LF blk2: c3 = cb2(xlow)+c2)
    cb(4, bb4, make_int4(5, 5, 5, 2), make_int4(0, 2, 4, 9),
       make_int4(1, 3, 5, 8), make_int4(1, 3, 5, 10));

    // Stage F: cb3 LF-only (c4 = cb3(c3) + c1)
    cb(1, bbLF, make_int4(3, 3, 3, 3), make_int4(10, 10, 10, 10),
       make_int4(7, 7, 7, 7), make_int4(11, 11, 11, 11));

    // Stage G: op all 4 bands
    k_op<<<dim3(36, 4), 256>>>(make_int4(1, 3, 5, 11), make_int4(1, 2, 3, 0), op_w, op_b);

    k_idwt<<<36, 256>>>(images, out);
}

// round 14
// speedup vs baseline: 5.6053x; 1.0699x over previous
#include <cuda_runtime.h>
#include <cuda_bf16.h>
#include <math.h>
#include <stdint.h>

#define CC 64
#define SP 9216
#define PP 102
#define SPP 10404
#define NLN 665856
#define CSPP (CC * SPP)
#define L1OSZ (4 * CC * SP)

typedef unsigned long long u64t;

__device__ __forceinline__ int m4(int4 v, int i) { return ((const int*)&v)[i]; }

// ---------------- scratch ----------------
__device__ float g_band[4][SP];
__device__ float g_opout[4][SP];
__device__ float g_feat[12][CC * SP];
__device__ float g_dwo[4 * CSPP];
__device__ float g_pwo[4 * CSPP];
__device__ float g_l1o[4 * L1OSZ];
__device__ __align__(16) uint32_t g_l1w_bf[6 * 16 * 2 * 14 * 128 * 8];
__device__ __align__(16) float g_l2wT[6 * 32 * 64 * 8];
__device__ float g_red[8];
__device__ float g_G[4 * 4096];
__device__ float g_s[4 * 64];
__device__ float g_M[4 * 4096];
__device__ float g_bias[4 * 64];

__device__ __forceinline__ float gelu(float x) {
    return 0.5f * x * (1.0f + erff(x * 0.70710678118654752f));
}
__device__ __forceinline__ void mma_bf16(float* c, uint32_t a0, uint32_t a1, uint32_t a2,
                                         uint32_t a3, uint32_t b0, uint32_t b1) {
    asm volatile(
        "mma.sync.aligned.m16n8k16.row.col.f32.bf16.bf16.f32 "
        "{%0,%1,%2,%3}, {%4,%5,%6,%7}, {%8,%9}, {%0,%1,%2,%3};"
        : "+f"(c[0]), "+f"(c[1]), "+f"(c[2]), "+f"(c[3])
        : "r"(a0), "r"(a1), "r"(a2), "r"(a3), "r"(b0), "r"(b1));
}
__device__ __forceinline__ void mma_tf32(float* c, uint32_t a0, uint32_t a1, uint32_t a2,
                                         uint32_t a3, uint32_t b0, uint32_t b1) {
    asm volatile(
        "mma.sync.aligned.m16n8k8.row.col.f32.tf32.tf32.f32 "
        "{%0,%1,%2,%3}, {%4,%5,%6,%7}, {%8,%9}, {%0,%1,%2,%3};"
        : "+f"(c[0]), "+f"(c[1]), "+f"(c[2]), "+f"(c[3])
        : "r"(a0), "r"(a1), "r"(a2), "r"(a3), "r"(b0), "r"(b1));
}
__device__ __forceinline__ uint32_t f2tf32(float x) {
    uint32_t r;
    asm("cvt.rna.tf32.f32 %0, %1;" : "=r"(r) : "f"(x));
    return r;
}

// ---------------- DWT (+ zero attention accumulators) ----------------
__global__ void __launch_bounds__(256) k_dwt(const float* __restrict__ img) {
    if (blockIdx.x == 0) {
        for (int t = threadIdx.x; t < 4 * 4096; t += 256) g_G[t] = 0.f;
        if (threadIdx.x < 4 * 64) g_s[threadIdx.x] = 0.f;
    }
    int idx = blockIdx.x * 256 + threadIdx.x;
    if (idx >= SP) return;
    int i = idx / 96, j = idx % 96;
    float a = img[(2 * i) * 192 + 2 * j];
    float b = img[(2 * i + 1) * 192 + 2 * j];
    float c = img[(2 * i) * 192 + 2 * j + 1];
    float d = img[(2 * i + 1) * 192 + 2 * j + 1];
    g_band[0][idx] = (a + b + c + d) * 0.5f;
    g_band[1][idx] = (a + b - c - d) * 0.5f;
    g_band[2][idx] = (a - b + c - d) * 0.5f;
    g_band[3][idx] = (a - b - c + d) * 0.5f;
}

// ---------------- l1 weight prepack to bf16 ----------------
__global__ void __launch_bounds__(256) k_l1wtb(const float* __restrict__ w) {
    int idx = blockIdx.x * 256 + threadIdx.x;
    const int total = 6 * 16 * 2 * 14 * 128 * 8;
    if (idx >= total) return;
    int q = idx & 7;
    int j4 = q >> 1, h = q & 1;
    int t = idx >> 3;
    int oc_l = t & 127; t >>= 7;
    int seg = t % 14; t /= 14;
    int ochalf = t & 1; t >>= 1;
    int icg = t & 15;
    int blk = t >> 4;
    int pair = seg / 7, a = seg % 7;
    int ic = icg * 4 + pair * 2 + h;
    int oc = ochalf * 128 + oc_l;
    int b0t = 2 * j4, b1t = 2 * j4 + 1;
    const float* wb = w + ((size_t)(blk * 256 + oc) * 64 + ic) * 49 + a * 7;
    float w0 = wb[b0t];
    float w1 = (b1t < 7) ? wb[b1t] : 0.f;
    uint32_t lo = __bfloat16_as_ushort(__float2bfloat16(w0));
    uint32_t hi = __bfloat16_as_ushort(__float2bfloat16(w1));
    g_l1w_bf[idx] = lo | (hi << 16);
}

// ---------------- l2 weight prepack to tf32 ----------------
__global__ void __launch_bounds__(256) k_l2wt(const float* __restrict__ w) {
    int idx = blockIdx.x * 256 + threadIdx.x;
    const int total = 6 * 32 * 64 * 8;
    if (idx >= total) return;
    int e = idx & 1;
    int j4 = (idx >> 1) & 3;
    int oc = (idx >> 3) & 63;
    int k8 = (idx >> 9) & 31;
    int blk = idx >> 14;
    float v = w[(size_t)(blk * 64 + oc) * 256 + k8 * 8 + j4 + 4 * e];
    g_l2wT[idx] = __uint_as_float(f2tf32(v));
}

// ---------------- ip: smem-tiled 16x16 px, 16-ch groups ----------------
// grid: (36 tiles, 4 chgroups, 4 bands)
__global__ void __launch_bounds__(256) k_ip(int4 bim, int4 outm, const float* __restrict__ w,
                                            const float* __restrict__ bb) {
    __shared__ float sw[144];
    __shared__ float sb2[16];
    __shared__ float st[324];        // 18 x 18: row = v' (src row), col = u' (src col)
    const int band = blockIdx.z;
    const int cg = blockIdx.y;
    const int tile = blockIdx.x;
    const int u0 = (tile / 6) * 16, v0 = (tile % 6) * 16;
    for (int t = threadIdx.x; t < 144; t += 256) sw[t] = w[cg * 144 + t];
    if (threadIdx.x < 16) sb2[threadIdx.x] = bb[cg * 16 + threadIdx.x];
    const float* src = g_band[m4(bim, band)];
    for (int t = threadIdx.x; t < 324; t += 256) {
        int r = t / 18, c = t % 18;          // r -> src row (v'), c -> src col (u')
        int gy = v0 - 1 + r, gx = u0 - 1 + c;
        st[t] = (gy >= 0 && gy < 96 && gx >= 0 && gx < 96) ? src[gy * 96 + gx] : 0.f;
    }
    __syncthreads();
    const int tu = threadIdx.x / 16, tv = threadIdx.x & 15;
    // taps: src[(v+b2-1)*96 + (u+a-1)] = st[(tv+b2)*18 + (tu+a)]
    float rv[3][3];
#pragma unroll
    for (int a = 0; a < 3; a++)
#pragma unroll
        for (int b2 = 0; b2 < 3; b2++)
            rv[a][b2] = st[(tv + b2) * 18 + (tu + a)];
    float* dst = g_feat[m4(outm, band)];
    const int u = u0 + tu, v = v0 + tv;
#pragma unroll
    for (int ch = 0; ch < 16; ch++) {
        float acc = sb2[ch];
#pragma unroll
        for (int a = 0; a < 3; a++)
#pragma unroll
            for (int b2 = 0; b2 < 3; b2++)
                acc = fmaf(rv[a][b2], sw[ch * 9 + a * 3 + b2], acc);
        dst[(cg * 16 + ch) * SP + u * 96 + v] = acc;
    }
}

// ---------------- depthwise 7x7, register-blocked 4px/thread ----------------
__global__ void __launch_bounds__(256) k_dw7(int4 srcm, int4 bbm, int4 blkm,
                                             const float* __restrict__ dwwb) {
    __shared__ __align__(16) float sw[64];
    __shared__ __align__(16) float spt[38 * 40];
    const int band = blockIdx.z >> 6;
    const int ch = blockIdx.z & 63;
    const int bb = m4(bbm, band);
    if (blockIdx.x == 0 && blockIdx.y == 0 && ch == 0 && threadIdx.x < 2)
        g_red[bb * 2 + threadIdx.x] = 0.f;
    const float* dww = dwwb + m4(blkm, band) * 3136;
    const int ty0 = blockIdx.y * 32, tx0 = blockIdx.x * 32;
    if (threadIdx.x < 49) sw[threadIdx.x] = dww[ch * 49 + threadIdx.x];
    const float* src = g_feat[m4(srcm, band)] + ch * SP;
    for (int t = threadIdx.x; t < 1520; t += 256) {
        int r = t / 40, c = t % 40;
        int gy = ty0 - 6 + r, gx = tx0 - 6 + c;
        spt[t] = (c < 38 && gy >= 0 && gy < 96 && gx >= 0 && gx < 96) ? src[gy * 96 + gx] : 0.f;
    }
    __syncthreads();
    const int ly = threadIdx.x >> 3, lx0 = (threadIdx.x & 7) * 4;
    const int oy = ty0 + ly;
    if (oy >= PP) return;
    float acc[4] = {0.f, 0.f, 0.f, 0.f};
#pragma unroll
    for (int a = 0; a < 7; a++) {
        const float* row = &spt[(ly + a) * 40 + lx0];
        float4 r0 = *(const float4*)row;
        float4 r1 = *(const float4*)(row + 4);
        float2 r2 = *(const float2*)(row + 8);
        float rr[10] = {r0.x, r0.y, r0.z, r0.w, r1.x, r1.y, r1.z, r1.w, r2.x, r2.y};
#pragma unroll
        for (int b = 0; b < 7; b++) {
            float wv = sw[a * 7 + b];
            acc[0] += rr[b] * wv;
            acc[1] += rr[b + 1] * wv;
            acc[2] += rr[b + 2] * wv;
            acc[3] += rr[b + 3] * wv;
        }
    }
    float* dst = g_dwo + bb * CSPP + ch * SPP + oy * PP;
#pragma unroll
    for (int k = 0; k < 4; k++) {
        int ox = tx0 + lx0 + k;
        if (ox < PP) dst[ox] = acc[k];
    }
}

// ---------------- pointwise + per-band LN reduction ----------------
__global__ void __launch_bounds__(256) k_pw(int4 bbm, int4 blkm, const float* __restrict__ Wb) {
    __shared__ float swT[64 * 68];
    __shared__ float sin_[4096];
    __shared__ float sr[2][8];
    const int band = blockIdx.y;
    const int bb = m4(bbm, band);
    const float* W = Wb + m4(blkm, band) * 4096;
    const float* dwo = g_dwo + bb * CSPP;
    float* pwo = g_pwo + bb * CSPP;
    const int p0 = blockIdx.x * 64;
    for (int t = threadIdx.x; t < 4096; t += 256) {
        int co = t >> 6, ci = t & 63;
        swT[ci * 68 + co] = W[t];
    }
    for (int t = threadIdx.x; t < 4096; t += 256) {
        int ci = t >> 6, p = t & 63; int gp = p0 + p;
        sin_[t] = (gp < SPP) ? dwo[ci * SPP + gp] : 0.f;
    }
    __syncthreads();
    const int ocg = threadIdx.x >> 4, pg = threadIdx.x & 15;
    float acc[4][4] = {};
#pragma unroll 4
    for (int ci = 0; ci < 64; ci++) {
        float4 w4 = *(const float4*)&swT[ci * 68 + ocg * 4];
        float4 i4 = *(const float4*)&sin_[ci * 64 + pg * 4];
        acc[0][0] += w4.x * i4.x; acc[0][1] += w4.x * i4.y; acc[0][2] += w4.x * i4.z; acc[0][3] += w4.x * i4.w;
        acc[1][0] += w4.y * i4.x; acc[1][1] += w4.y * i4.y; acc[1][2] += w4.y * i4.z; acc[1][3] += w4.y * i4.w;
        acc[2][0] += w4.z * i4.x; acc[2][1] += w4.z * i4.y; acc[2][2] += w4.z * i4.z; acc[2][3] += w4.z * i4.w;
        acc[3][0] += w4.w * i4.x; acc[3][1] += w4.w * i4.y; acc[3][2] += w4.w * i4.z; acc[3][3] += w4.w * i4.w;
    }
    float ls = 0.f, ls2 = 0.f;
#pragma unroll
    for (int o = 0; o < 4; o++) {
        int oc = ocg * 4 + o;
#pragma unroll
        for (int p = 0; p < 4; p++) {
            int gp = p0 + pg * 4 + p;
            if (gp < SPP) {
                float v = acc[o][p];
                pwo[oc * SPP + gp] = v;
                ls += v; ls2 += v * v;
            }
        }
    }
    for (int off = 16; off; off >>= 1) {
        ls += __shfl_down_sync(0xffffffffu, ls, off);
        ls2 += __shfl_down_sync(0xffffffffu, ls2, off);
    }
    if ((threadIdx.x & 31) == 0) { sr[0][threadIdx.x >> 5] = ls; sr[1][threadIdx.x >> 5] = ls2; }
    __syncthreads();
    if (threadIdx.x == 0) {
        float a = 0.f, b = 0.f;
        for (int w2 = 0; w2 < 8; w2++) { a += sr[0][w2]; b += sr[1][w2]; }
        atomicAdd(&g_red[bb * 2], a); atomicAdd(&g_red[bb * 2 + 1], b);
    }
}

// ---------------- l1 via bf16 mma (z = band*2 + ochalf) ----------------
#define L1_WBUF 14336
#define L1_IN   1408
#define L1_SMEMB ((L1_WBUF + L1_IN) * 4)

__global__ void __launch_bounds__(256) k_l1mma(int4 bbm, int4 blkm, const float* __restrict__ l1bb) {
    extern __shared__ uint32_t sm[];
    uint32_t* s_in = sm + L1_WBUF;
    const int tid = threadIdx.x;
    const int tx = blockIdx.x * 8, ty = blockIdx.y * 16;
    const int band = blockIdx.z >> 1;
    const int ochalf = blockIdx.z & 1;
    const int bb = m4(bbm, band);
    const int blk = m4(blkm, band);
    const float* l1b = l1bb + blk * 256;
    const int wid = tid >> 5, lane = tid & 31;
    const int ocg = wid >> 1, pxg = wid & 1;
    const int g = lane >> 2, j4 = lane & 3;

    const float m = g_red[bb * 2] * (1.0f / (float)NLN);
    const float inv = rsqrtf(g_red[bb * 2 + 1] * (1.0f / (float)NLN) - m * m + 1e-5f);
    const float* pwo = g_pwo + bb * CSPP;
    float* l1o = g_l1o + bb * L1OSZ;

    for (int t = tid; t < L1_IN; t += 256) s_in[t] = 0u;

    float c[2][8][4] = {};
    unsigned short* s_ine = (unsigned short*)s_in;
    unsigned short* s_ino = (unsigned short*)(s_in + 704);

    for (int icg = 0; icg < 16; icg++) {
        __syncthreads();
        {
            size_t chunk = ((size_t)(blk * 16 + icg) * 2 + ochalf) * L1_WBUF;
            const uint4* src = (const uint4*)(g_l1w_bf + chunk);
            uint4* dstw = (uint4*)sm;
#pragma unroll
            for (int i = 0; i < 14; i++)
                dstw[tid + i * 256] = src[tid + i * 256];
        }
        for (int t = tid; t < 1232; t += 256) {
            int ic = t / 308, r2 = t % 308;
            int r = r2 / 14, cx = r2 % 14;
            float v = (pwo[(icg * 4 + ic) * SPP + (ty + r) * PP + (tx + cx)] - m) * inv;
            unsigned short hb = __bfloat16_as_ushort(__float2bfloat16(v));
            int rowb = (ic * 22 + r) * 16;
            s_ine[rowb + cx] = hb;
            if (cx >= 1) s_ino[rowb + cx - 1] = hb;
        }
        __syncthreads();

        const uint32_t* wb = sm;
        const int r0 = ocg * 32 + g;
        const uint32_t* pbase = s_in + (g & 1) * 704 + ((g >> 1) + j4);
#pragma unroll
        for (int pair = 0; pair < 2; pair++) {
#pragma unroll
            for (int a = 0; a < 7; a++) {
                const uint32_t* ws = wb + (pair * 7 + a) * 1024 + 2 * j4;
                u64t A0lo = *(const u64t*)(ws + r0 * 8);
                u64t A0hi = *(const u64t*)(ws + (r0 + 8) * 8);
                u64t A1lo = *(const u64t*)(ws + (r0 + 16) * 8);
                u64t A1hi = *(const u64t*)(ws + (r0 + 24) * 8);
                uint32_t a00 = (uint32_t)A0lo, a02 = (uint32_t)(A0lo >> 32);
                uint32_t a01 = (uint32_t)A0hi, a03 = (uint32_t)(A0hi >> 32);
                uint32_t a10 = (uint32_t)A1lo, a12 = (uint32_t)(A1lo >> 32);
                uint32_t a11 = (uint32_t)A1hi, a13 = (uint32_t)(A1hi >> 32);
                const uint32_t* p0 = pbase + (pair * 2) * 176 + (pxg * 8 + a) * 8;
                const uint32_t* p1 = p0 + 176;
#pragma unroll
                for (int j = 0; j < 8; j++) {
                    uint32_t b0 = p0[j * 8], b1 = p1[j * 8];
                    mma_bf16(c[0][j], a00, a01, a02, a03, b0, b1);
                    mma_bf16(c[1][j], a10, a11, a12, a13, b0, b1);
                }
            }
        }
    }

#pragma unroll
    for (int mm = 0; mm < 2; mm++) {
        int ocb = ochalf * 128 + ocg * 32 + mm * 16 + g;
        float b_lo = l1b[ocb], b_hi = l1b[ocb + 8];
#pragma unroll
        for (int j = 0; j < 8; j++) {
            int y = ty + pxg * 8 + j;
            int xb = tx + 2 * j4;
            float* o_lo = &l1o[ocb * SP + y * 96 + xb];
            float* o_hi = &l1o[(ocb + 8) * SP + y * 96 + xb];
            o_lo[0] = gelu(c[mm][j][0] + b_lo);
            o_lo[1] = gelu(c[mm][j][1] + b_lo);
            o_hi[0] = gelu(c[mm][j][2] + b_hi);
            o_hi[1] = gelu(c[mm][j][3] + b_hi);
        }
    }
}

// ---------------- l2 via tf32 mma ----------------
__global__ void __launch_bounds__(256) k_l2(int4 bbm, int4 blkm, int4 srcm, int4 r2m, int4 dstm,
                                            const float* __restrict__ biasb) {
    __shared__ __align__(16) float swt[4096];
    __shared__ __align__(16) float sin_[8192];
    const int band = blockIdx.y;
    const int bb = m4(bbm, band);
    const int blk = m4(blkm, band);
    const float* bias = biasb + blk * 64;
    const float* l1o = g_l1o + bb * L1OSZ;
    const int p0 = blockIdx.x * 128;
    const int tid = threadIdx.x;
    const int wid = tid >> 5, lane = tid & 31;
    const int ocg = wid >> 1, pxg = wid & 1;
    const int g = lane >> 2, j4 = lane & 3;

    float c[8][4] = {};

    for (int c0 = 0; c0 < 4; c0++) {
        __syncthreads();
        {
            const float4* src = (const float4*)(g_l2wT + ((size_t)blk * 32 + c0 * 8) * 512);
            float4* dstw = (float4*)swt;
#pragma unroll
            for (int i = 0; i < 4; i++)
                dstw[tid + i * 256] = src[tid + i * 256];
        }
        for (int t = tid; t < 8192; t += 256) {
            int ch = t >> 7, px = t & 127;
            sin_[t] = __uint_as_float(f2tf32(l1o[(c0 * 64 + ch) * SP + p0 + px]));
        }
        __syncthreads();
#pragma unroll
        for (int k8 = 0; k8 < 8; k8++) {
            const float* wsrc = swt + (k8 * 64 + ocg * 16) * 8 + j4 * 2;
            float2 lo = *(const float2*)(wsrc + g * 8);
            float2 hi = *(const float2*)(wsrc + (g + 8) * 8);
            uint32_t a0 = __float_as_uint(lo.x), a2 = __float_as_uint(lo.y);
            uint32_t a1 = __float_as_uint(hi.x), a3 = __float_as_uint(hi.y);
            const float* brow0 = sin_ + (k8 * 8 + j4) * 128 + pxg * 64 + g;
            const float* brow1 = brow0 + 4 * 128;
#pragma unroll
            for (int nt = 0; nt < 8; nt++) {
                uint32_t b0 = __float_as_uint(brow0[nt * 8]);
                uint32_t b1 = __float_as_uint(brow1[nt * 8]);
                mma_tf32(c[nt], a0, a1, a2, a3, b0, b1);
            }
        }
    }

    float* dstp = g_feat[m4(dstm, band)];
    const float* rp1 = g_feat[m4(srcm, band)];
    const int r2 = m4(r2m, band);
    const float* rp2 = (r2 >= 0) ? g_feat[r2] : 0;
    const int oc_lo = ocg * 16 + g, oc_hi = oc_lo + 8;
    const float bi_lo = bias[oc_lo], bi_hi = bias[oc_hi];
#pragma unroll
    for (int nt = 0; nt < 8; nt++) {
        int px = p0 + pxg * 64 + nt * 8 + 2 * j4;
        int i_lo = oc_lo * SP + px;
        int i_hi = oc_hi * SP + px;
        float v0 = c[nt][0] + bi_lo + rp1[i_lo];
        float v1 = c[nt][1] + bi_lo + rp1[i_lo + 1];
        float v2 = c[nt][2] + bi_hi + rp1[i_hi];
        float v3 = c[nt][3] + bi_hi + rp1[i_hi + 1];
        if (rp2) { v0 += rp2[i_lo]; v1 += rp2[i_lo + 1]; v2 += rp2[i_hi]; v3 += rp2[i_hi + 1]; }
        dstp[i_lo] = v0; dstp[i_lo + 1] = v1;
        dstp[i_hi] = v2; dstp[i_hi + 1] = v3;
    }
}

// ---------------- xblock Gram + row-sum ----------------
__global__ void __launch_bounds__(256) k_xg(int4 srcm) {
    __shared__ float sf[1024];
    const int band = blockIdx.y;
    const float* f = g_feat[m4(srcm, band)];
    float* Gp = g_G + band * 4096;
    float* sp = g_s + band * 64;
    const int ag = threadIdx.x >> 4, bg = threadIdx.x & 15;
    float acc[4][4] = {};
    float sacc[4] = {};
    const int tok0 = blockIdx.x * 144;
    for (int tb = 0; tb < 144; tb += 16) {
        __syncthreads();
        for (int t2 = threadIdx.x; t2 < 1024; t2 += 256) sf[t2] = f[(tok0 + tb) * 64 + t2];
        __syncthreads();
#pragma unroll
        for (int tk = 0; tk < 16; tk++) {
            float4 fa = *(const float4*)&sf[tk * 64 + ag * 4];
            float4 fb = *(const float4*)&sf[tk * 64 + bg * 4];
            acc[0][0] += fa.x * fb.x; acc[0][1] += fa.x * fb.y; acc[0][2] += fa.x * fb.z; acc[0][3] += fa.x * fb.w;
            acc[1][0] += fa.y * fb.x; acc[1][1] += fa.y * fb.y; acc[1][2] += fa.y * fb.z; acc[1][3] += fa.y * fb.w;
            acc[2][0] += fa.z * fb.x; acc[2][1] += fa.z * fb.y; acc[2][2] += fa.z * fb.z; acc[2][3] += fa.z * fb.w;
            acc[3][0] += fa.w * fb.x; acc[3][1] += fa.w * fb.y; acc[3][2] += fa.w * fb.z; acc[3][3] += fa.w * fb.w;
            if (ag == 0) { sacc[0] += fb.x; sacc[1] += fb.y; sacc[2] += fb.z; sacc[3] += fb.w; }
        }
    }
    for (int i2 = 0; i2 < 4; i2++)
        for (int j2 = 0; j2 < 4; j2++)
            atomicAdd(&Gp[(ag * 4 + i2) * 64 + bg * 4 + j2], acc[i2][j2]);
    if (ag == 0)
        for (int j2 = 0; j2 < 4; j2++) atomicAdd(&sp[bg * 4 + j2], sacc[j2]);
}

// ---------------- attention core ----------------
__global__ void __launch_bounds__(256) k_xatt(const float* __restrict__ xqw, const float* __restrict__ xqb,
                                              const float* __restrict__ xkw, const float* __restrict__ xkb,
                                              const float* __restrict__ xvw, const float* __restrict__ xvb,
                                              int4 imap) {
    __shared__ float sA[4096];
    __shared__ float sGK[4096];
    __shared__ float ss[64], sQs[64], sKs[64];
    const int band = blockIdx.x;
    const int iw = m4(imap, band);
    const float* Qw = xqw + iw * 4096; const float* Qb = xqb + iw * 64;
    const float* Kw = xkw + iw * 4096; const float* Kb = xkb + iw * 64;
    const float* Vw = xvw + iw * 4096; const float* Vb = xvb + iw * 64;
    const float scale = (iw == 0) ? 0.44721359549995793f : 0.70710678118654752f;
    float* Gp = g_G + band * 4096;
    float* sp = g_s + band * 64;
    const int t = threadIdx.x;
    for (int i = t; i < 4096; i += 256) sA[i] = Gp[i];
    if (t < 64) ss[t] = sp[t];
    __syncthreads();
    if (t < 64) {
        float q = 0.f;
        for (int a2 = 0; a2 < 64; a2++) q += Qw[t * 64 + a2] * ss[a2];
        sQs[t] = q;
    } else if (t < 128) {
        int d = t - 64; float q = 0.f;
        for (int b2 = 0; b2 < 64; b2++) q += Kw[d * 64 + b2] * ss[b2];
        sKs[d] = q;
    }
    for (int i = t; i < 4096; i += 256) {
        int a2 = i >> 6, d = i & 63;
        float s2 = 0.f;
        for (int b2 = 0; b2 < 64; b2++) s2 += sA[a2 * 64 + b2] * Kw[d * 64 + b2];
        sGK[i] = s2;
    }
    __syncthreads();
    for (int i = t; i < 4096; i += 256) Gp[i] = 0.f;
    if (t < 64) sp[t] = 0.f;
    for (int i = t; i < 4096; i += 256) {
        int c = i >> 6, d = i & 63;
        float s2 = Qb[c] * sKs[d] + sQs[c] * Kb[d] + 9216.0f * Qb[c] * Kb[d];
        for (int a2 = 0; a2 < 64; a2++) s2 += Qw[c * 64 + a2] * sGK[a2 * 64 + d];
        sA[i] = s2 * scale;
    }
    __syncthreads();
    if (t < 64) {
        float mx = -1e30f;
        for (int d = 0; d < 64; d++) mx = fmaxf(mx, sA[t * 64 + d]);
        float sm = 0.f;
        for (int d = 0; d < 64; d++) { float e = expf(sA[t * 64 + d] - mx); sA[t * 64 + d] = e; sm += e; }
        float r = 1.0f / sm;
        for (int d = 0; d < 64; d++) sA[t * 64 + d] *= r;
    }
    __syncthreads();
    for (int i = t; i < 4096; i += 256) {
        int a2 = i >> 6, d = i & 63;
        float s2 = 0.f;
        for (int c = 0; c < 64; c++) s2 += Vw[c * 64 + a2] * sA[c * 64 + d];
        g_M[band * 4096 + i] = s2;
    }
    if (t < 64) {
        float s2 = 0.f;
        for (int c = 0; c < 64; c++) s2 += Vb[c] * sA[c * 64 + t];
        g_bias[band * 64 + t] = s2;
    }
}

// ---------------- xblock apply ----------------
__global__ void __launch_bounds__(256) k_xapply(int4 srcm, int4 dstm) {
    __shared__ float sM[4096];
    __shared__ float sb[64];
    __shared__ float sf[2048];
    const int band = blockIdx.y;
    for (int t = threadIdx.x; t < 4096; t += 256) sM[t] = g_M[band * 4096 + t];
    if (threadIdx.x < 64) sb[threadIdx.x] = g_bias[band * 64 + threadIdx.x];
    const int tok0 = blockIdx.x * 32;
    const float* f = g_feat[m4(srcm, band)];
    for (int t = threadIdx.x; t < 2048; t += 256) sf[t] = f[tok0 * 64 + t];
    __syncthreads();
    const int tk = threadIdx.x >> 3, dg = threadIdx.x & 7;
    float acc[8] = {};
#pragma unroll 8
    for (int a2 = 0; a2 < 64; a2++) {
        float fa = sf[tk * 64 + a2];
        float4 m0 = *(const float4*)&sM[a2 * 64 + dg * 8];
        float4 m1 = *(const float4*)&sM[a2 * 64 + dg * 8 + 4];
        acc[0] += fa * m0.x; acc[1] += fa * m0.y; acc[2] += fa * m0.z; acc[3] += fa * m0.w;
        acc[4] += fa * m1.x; acc[5] += fa * m1.y; acc[6] += fa * m1.z; acc[7] += fa * m1.w;
    }
    float* dp = g_feat[m4(dstm, band)];
    const int base = (tok0 + tk) * 64 + dg * 8;
#pragma unroll
    for (int d2 = 0; d2 < 8; d2++) dp[base + d2] = sf[tk * 64 + dg * 8 + d2] + acc[d2] + sb[dg * 8 + d2];
}

// ---------------- op: smem-tiled 16x16 px, 8-channel chunks ----------------
__global__ void __launch_bounds__(256) k_op(int4 srcm, int4 outm, const float* __restrict__ w,
                                            const float* __restrict__ bb) {
    __shared__ float sw[576];
    __shared__ float sx[8 * 324];
    const int band = blockIdx.y;
    const int bx = blockIdx.x;
    const int u0 = (bx / 6) * 16, v0 = (bx % 6) * 16;
    for (int t = threadIdx.x; t < 576; t += 256) {
        int ch = t / 9, k2 = t % 9; int a = k2 / 3, b2 = k2 % 3;
        sw[t] = w[ch * 9 + (2 - a) * 3 + (2 - b2)];
    }
    const float* x = g_feat[m4(srcm, band)];
    const int tu = threadIdx.x / 16, tv = threadIdx.x % 16;
    float acc = bb[0];
    for (int cg = 0; cg < 8; cg++) {
        __syncthreads();
        for (int t = threadIdx.x; t < 2592; t += 256) {
            int c = t / 324, rr = (t % 324) / 18, cc = t % 18;
            int gy = u0 - 1 + rr, gx = v0 - 1 + cc;
            sx[t] = (gy >= 0 && gy < 96 && gx >= 0 && gx < 96) ? x[(cg * 8 + c) * SP + gy * 96 + gx] : 0.f;
        }
        __syncthreads();
#pragma unroll
        for (int c = 0; c < 8; c++) {
            int ch = cg * 8 + c;
#pragma unroll
            for (int a = 0; a < 3; a++)
#pragma unroll
                for (int b2 = 0; b2 < 3; b2++)
                    acc += sx[c * 324 + (tu + a) * 18 + (tv + b2)] * sw[ch * 9 + a * 3 + b2];
        }
    }
    int u = u0 + tu, v = v0 + tv;
    g_opout[m4(outm, band)][v * 96 + u] = acc;
}

__global__ void __launch_bounds__(256) k_idwt(const float* __restrict__ img, float* __restrict__ out) {
    int idx = blockIdx.x * 256 + threadIdx.x;
    if (idx >= SP) return;
    int i = idx / 96, j = idx % 96;
    float a = g_opout[0][idx], b = g_opout[1][idx], c = g_opout[2][idx], d = g_opout[3][idx];
    int r0 = (2 * i) * 192 + 2 * j;
    int r1 = (2 * i + 1) * 192 + 2 * j;
    out[r0]     = 0.5f * (a + b + c + d) + img[r0];
    out[r0 + 1] = 0.5f * (a - b + c - d) + img[r0 + 1];
    out[r1]     = 0.5f * (a + b - c - d) + img[r1];
    out[r1 + 1] = 0.5f * (a - b - c + d) + img[r1 + 1];
}

extern "C" void kernel_launch(void* const* d_in, const int* in_sizes, int n_in,
                              void* d_out, int out_size) {
    (void)in_sizes; (void)n_in; (void)out_size;
    const float* images = (const float*)d_in[0];
    const float* ip_w  = (const float*)d_in[1];
    const float* ip_b  = (const float*)d_in[2];
    const float* op_w  = (const float*)d_in[3];
    const float* op_b  = (const float*)d_in[4];
    const float* cb_dw = (const float*)d_in[5];
    const float* cb_pw = (const float*)d_in[6];
    const float* cb_l1w = (const float*)d_in[7];
    const float* cb_l1b = (const float*)d_in[8];
    const float* cb_l2w = (const float*)d_in[9];
    const float* cb_l2b = (const float*)d_in[10];
    const float* xqw = (const float*)d_in[11];
    const float* xqb = (const float*)d_in[12];
    const float* xkw = (const float*)d_in[13];
    const float* xkb = (const float*)d_in[14];
    const float* xvw = (const float*)d_in[15];
    const float* xvb = (const float*)d_in[16];
    float* out = (float*)d_out;

    cudaFuncSetAttribute(k_l1mma, cudaFuncAttributeMaxDynamicSharedMemorySize, L1_SMEMB);

    k_dwt<<<36, 256>>>(images);
    k_l1wtb<<<(6 * 16 * 2 * 14 * 128 * 8 + 255) / 256, 256>>>(cb_l1w);
    k_l2wt<<<(6 * 32 * 64 * 8 + 255) / 256, 256>>>(cb_l2w);

    auto cb = [&](int nb, int4 bbm, int4 blkm, int4 srcm, int4 r2m, int4 dstm) {
        k_dw7<<<dim3(4, 4, 64 * nb), 256>>>(srcm, bbm, blkm, cb_dw);
        k_pw<<<dim3(163, nb), 256>>>(bbm, blkm, cb_pw);
        k_l1mma<<<dim3(12, 6, 2 * nb), 256, L1_SMEMB>>>(bbm, blkm, cb_l1b);
        k_l2<<<dim3(72, nb), 256>>>(bbm, blkm, srcm, r2m, dstm, cb_l2b);
    };

    // slots: HF band b (b=0..2): A=2b, B=2b+1 ; LF: lf=6, c1=7, c2=8, xlow=9, c3=10, c4=11
    const int4 bb4   = make_int4(0, 1, 2, 3);
    const int4 bbLF  = make_int4(3, 3, 3, 3);

    // Stage A: ip all 4 bands
    k_ip<<<dim3(36, 4, 4), 256>>>(make_int4(1, 2, 3, 0), make_int4(0, 2, 4, 6), ip_w, ip_b);

    // Stage B: CB-I (HF blk4: A->B ; LF blk0: lf->c1)
    cb(4, bb4, make_int4(4, 4, 4, 0), make_int4(0, 2, 4, 6),
       make_int4(-1, -1, -1, -1), make_int4(1, 3, 5, 7));

    // Stage C: cb1 LF-only (c2 = cb1(c1) + c1)
    cb(1, bbLF, make_int4(1, 1, 1, 1), make_int4(7, 7, 7, 7),
       make_int4(7, 7, 7, 7), make_int4(8, 8, 8, 8));

    // Stage D: XB all 4 bands
    {
        int4 srcm = make_int4(1, 3, 5, 7);
        int4 dstm = make_int4(0, 2, 4, 9);
        k_xg<<<dim3(64, 4), 256>>>(srcm);
        k_xatt<<<4, 256>>>(xqw, xqb, xkw, xkb, xvw, xvb, make_int4(1, 1, 1, 0));
        k_xapply<<<dim3(288, 4), 256>>>(srcm, dstm);
    }

    // Stage E: CB-II (HF blk5: h2 = cb5(hx)+h1 ; LF blk2: c3 = cb2(xlow)+c2)
    cb(4, bb4, make_int4(5, 5, 5, 2), make_int4(0, 2, 4, 9),
       make_int4(1, 3, 5, 8), make_int4(1, 3, 5, 10));

    // Stage F: cb3 LF-only (c4 = cb3(c3) + c1)
    cb(1, bbLF, make_int4(3, 3, 3, 3), make_int4(10, 10, 10, 10),
       make_int4(7, 7, 7, 7), make_int4(11, 11, 11, 11));

    // Stage G: op all 4 bands
    k_op<<<dim3(36, 4), 256>>>(make_int4(1, 3, 5, 11), make_int4(1, 2, 3, 0), op_w, op_b);

    k_idwt<<<36, 256>>>(images, out);
}

// round 16
// speedup vs baseline: 5.6899x; 1.0151x over previous
#include <cuda_runtime.h>
#include <cuda_bf16.h>
#include <math.h>
#include <stdint.h>

#define CC 64
#define SP 9216
#define PP 102
#define SPP 10404
#define NLN 665856
#define CSPP (CC * SPP)
#define L1OSZ (4 * CC * SP)

typedef unsigned long long u64t;

__device__ __forceinline__ int m4(int4 v, int i) { return ((const int*)&v)[i]; }

// ---------------- scratch ----------------
__device__ float g_band[4][SP];
__device__ float g_opout[4][SP];
__device__ float g_feat[12][CC * SP];
__device__ float g_dwo[4 * CSPP];
__device__ float g_pwo[4 * CSPP];
__device__ float g_l1o[4 * L1OSZ];
__device__ __align__(16) uint32_t g_l1w_bf[6 * 16 * 2 * 14 * 128 * 8];
__device__ __align__(16) float g_l2wT[6 * 32 * 64 * 8];
__device__ __align__(16) float g_pwwT[6 * 8 * 64 * 8];   // [blk][k8 8][oc 64][j4*2+e], tf32
__device__ float g_red[8];
__device__ float g_G[4 * 4096];
__device__ float g_s[4 * 64];
__device__ float g_M[4 * 4096];
__device__ float g_bias[4 * 64];

__device__ __forceinline__ float gelu(float x) {
    return 0.5f * x * (1.0f + erff(x * 0.70710678118654752f));
}
__device__ __forceinline__ void mma_bf16(float* c, uint32_t a0, uint32_t a1, uint32_t a2,
                                         uint32_t a3, uint32_t b0, uint32_t b1) {
    asm volatile(
        "mma.sync.aligned.m16n8k16.row.col.f32.bf16.bf16.f32 "
        "{%0,%1,%2,%3}, {%4,%5,%6,%7}, {%8,%9}, {%0,%1,%2,%3};"
        : "+f"(c[0]), "+f"(c[1]), "+f"(c[2]), "+f"(c[3])
        : "r"(a0), "r"(a1), "r"(a2), "r"(a3), "r"(b0), "r"(b1));
}
__device__ __forceinline__ void mma_tf32(float* c, uint32_t a0, uint32_t a1, uint32_t a2,
                                         uint32_t a3, uint32_t b0, uint32_t b1) {
    asm volatile(
        "mma.sync.aligned.m16n8k8.row.col.f32.tf32.tf32.f32 "
        "{%0,%1,%2,%3}, {%4,%5,%6,%7}, {%8,%9}, {%0,%1,%2,%3};"
        : "+f"(c[0]), "+f"(c[1]), "+f"(c[2]), "+f"(c[3])
        : "r"(a0), "r"(a1), "r"(a2), "r"(a3), "r"(b0), "r"(b1));
}
__device__ __forceinline__ uint32_t f2tf32(float x) {
    uint32_t r;
    asm("cvt.rna.tf32.f32 %0, %1;" : "=r"(r) : "f"(x));
    return r;
}

// ---------------- DWT (+ zero attention accumulators) ----------------
__global__ void __launch_bounds__(256) k_dwt(const float* __restrict__ img) {
    if (blockIdx.x == 0) {
        for (int t = threadIdx.x; t < 4 * 4096; t += 256) g_G[t] = 0.f;
        if (threadIdx.x < 4 * 64) g_s[threadIdx.x] = 0.f;
    }
    int idx = blockIdx.x * 256 + threadIdx.x;
    if (idx >= SP) return;
    int i = idx / 96, j = idx % 96;
    float a = img[(2 * i) * 192 + 2 * j];
    float b = img[(2 * i + 1) * 192 + 2 * j];
    float c = img[(2 * i) * 192 + 2 * j + 1];
    float d = img[(2 * i + 1) * 192 + 2 * j + 1];
    g_band[0][idx] = (a + b + c + d) * 0.5f;
    g_band[1][idx] = (a + b - c - d) * 0.5f;
    g_band[2][idx] = (a - b + c - d) * 0.5f;
    g_band[3][idx] = (a - b - c + d) * 0.5f;
}

// ---------------- l1 weight prepack to bf16 ----------------
__global__ void __launch_bounds__(256) k_l1wtb(const float* __restrict__ w) {
    int idx = blockIdx.x * 256 + threadIdx.x;
    const int total = 6 * 16 * 2 * 14 * 128 * 8;
    if (idx >= total) return;
    int q = idx & 7;
    int j4 = q >> 1, h = q & 1;
    int t = idx >> 3;
    int oc_l = t & 127; t >>= 7;
    int seg = t % 14; t /= 14;
    int ochalf = t & 1; t >>= 1;
    int icg = t & 15;
    int blk = t >> 4;
    int pair = seg / 7, a = seg % 7;
    int ic = icg * 4 + pair * 2 + h;
    int oc = ochalf * 128 + oc_l;
    int b0t = 2 * j4, b1t = 2 * j4 + 1;
    const float* wb = w + ((size_t)(blk * 256 + oc) * 64 + ic) * 49 + a * 7;
    float w0 = wb[b0t];
    float w1 = (b1t < 7) ? wb[b1t] : 0.f;
    uint32_t lo = __bfloat16_as_ushort(__float2bfloat16(w0));
    uint32_t hi = __bfloat16_as_ushort(__float2bfloat16(w1));
    g_l1w_bf[idx] = lo | (hi << 16);
}

// ---------------- l2 weight prepack to tf32 ----------------
__global__ void __launch_bounds__(256) k_l2wt(const float* __restrict__ w) {
    int idx = blockIdx.x * 256 + threadIdx.x;
    const int total = 6 * 32 * 64 * 8;
    if (idx >= total) return;
    int e = idx & 1;
    int j4 = (idx >> 1) & 3;
    int oc = (idx >> 3) & 63;
    int k8 = (idx >> 9) & 31;
    int blk = idx >> 14;
    float v = w[(size_t)(blk * 64 + oc) * 256 + k8 * 8 + j4 + 4 * e];
    g_l2wT[idx] = __uint_as_float(f2tf32(v));
}

// ---------------- pw weight prepack to tf32 ----------------
__global__ void __launch_bounds__(256) k_pwwt(const float* __restrict__ w) {
    int idx = blockIdx.x * 256 + threadIdx.x;
    const int total = 6 * 8 * 64 * 8;
    if (idx >= total) return;
    int e = idx & 1;
    int j4 = (idx >> 1) & 3;
    int oc = (idx >> 3) & 63;
    int k8 = (idx >> 9) & 7;
    int blk = idx >> 12;
    float v = w[(size_t)blk * 4096 + oc * 64 + k8 * 8 + j4 + 4 * e];
    g_pwwT[idx] = __uint_as_float(f2tf32(v));
}

// ---------------- ip: smem-tiled ----------------
__global__ void __launch_bounds__(256) k_ip(int4 bim, int4 outm, const float* __restrict__ w,
                                            const float* __restrict__ bb) {
    __shared__ float sw[144];
    __shared__ float sb2[16];
    __shared__ float st[324];
    const int band = blockIdx.z;
    const int cg = blockIdx.y;
    const int tile = blockIdx.x;
    const int u0 = (tile / 6) * 16, v0 = (tile % 6) * 16;
    for (int t = threadIdx.x; t < 144; t += 256) sw[t] = w[cg * 144 + t];
    if (threadIdx.x < 16) sb2[threadIdx.x] = bb[cg * 16 + threadIdx.x];
    const float* src = g_band[m4(bim, band)];
    for (int t = threadIdx.x; t < 324; t += 256) {
        int r = t / 18, c = t % 18;
        int gy = v0 - 1 + r, gx = u0 - 1 + c;
        st[t] = (gy >= 0 && gy < 96 && gx >= 0 && gx < 96) ? src[gy * 96 + gx] : 0.f;
    }
    __syncthreads();
    const int tu = threadIdx.x / 16, tv = threadIdx.x & 15;
    float rv[3][3];
#pragma unroll
    for (int a = 0; a < 3; a++)
#pragma unroll
        for (int b2 = 0; b2 < 3; b2++)
            rv[a][b2] = st[(tv + b2) * 18 + (tu + a)];
    float* dst = g_feat[m4(outm, band)];
    const int u = u0 + tu, v = v0 + tv;
#pragma unroll
    for (int ch = 0; ch < 16; ch++) {
        float acc = sb2[ch];
#pragma unroll
        for (int a = 0; a < 3; a++)
#pragma unroll
            for (int b2 = 0; b2 < 3; b2++)
                acc = fmaf(rv[a][b2], sw[ch * 9 + a * 3 + b2], acc);
        dst[(cg * 16 + ch) * SP + u * 96 + v] = acc;
    }
}

// ---------------- depthwise 7x7, register-blocked 4px/thread ----------------
__global__ void __launch_bounds__(256) k_dw7(int4 srcm, int4 bbm, int4 blkm,
                                             const float* __restrict__ dwwb) {
    __shared__ __align__(16) float sw[64];
    __shared__ __align__(16) float spt[38 * 40];
    const int band = blockIdx.z >> 6;
    const int ch = blockIdx.z & 63;
    const int bb = m4(bbm, band);
    if (blockIdx.x == 0 && blockIdx.y == 0 && ch == 0 && threadIdx.x < 2)
        g_red[bb * 2 + threadIdx.x] = 0.f;
    const float* dww = dwwb + m4(blkm, band) * 3136;
    const int ty0 = blockIdx.y * 32, tx0 = blockIdx.x * 32;
    if (threadIdx.x < 49) sw[threadIdx.x] = dww[ch * 49 + threadIdx.x];
    const float* src = g_feat[m4(srcm, band)] + ch * SP;
    for (int t = threadIdx.x; t < 1520; t += 256) {
        int r = t / 40, c = t % 40;
        int gy = ty0 - 6 + r, gx = tx0 - 6 + c;
        spt[t] = (c < 38 && gy >= 0 && gy < 96 && gx >= 0 && gx < 96) ? src[gy * 96 + gx] : 0.f;
    }
    __syncthreads();
    const int ly = threadIdx.x >> 3, lx0 = (threadIdx.x & 7) * 4;
    const int oy = ty0 + ly;
    if (oy >= PP) return;
    float acc[4] = {0.f, 0.f, 0.f, 0.f};
#pragma unroll
    for (int a = 0; a < 7; a++) {
        const float* row = &spt[(ly + a) * 40 + lx0];
        float4 r0 = *(const float4*)row;
        float4 r1 = *(const float4*)(row + 4);
        float2 r2 = *(const float2*)(row + 8);
        float rr[10] = {r0.x, r0.y, r0.z, r0.w, r1.x, r1.y, r1.z, r1.w, r2.x, r2.y};
#pragma unroll
        for (int b = 0; b < 7; b++) {
            float wv = sw[a * 7 + b];
            acc[0] += rr[b] * wv;
            acc[1] += rr[b + 1] * wv;
            acc[2] += rr[b + 2] * wv;
            acc[3] += rr[b + 3] * wv;
        }
    }
    float* dst = g_dwo + bb * CSPP + ch * SPP + oy * PP;
#pragma unroll
    for (int k = 0; k < 4; k++) {
        int ox = tx0 + lx0 + k;
        if (ox < PP) dst[ox] = acc[k];
    }
}

// ---------------- pointwise via tf32 mma + per-band LN reduction ----------------
// grid: (82 px-tiles of 128, nb); static smem exactly 48 KB
__global__ void __launch_bounds__(256) k_pw(int4 bbm, int4 blkm) {
    __shared__ __align__(16) float swt[4096];   // [k8 8][oc 64][8]
    __shared__ __align__(16) float sin_[8192];  // [ci 64][px 128], tf32
    const int band = blockIdx.y;
    const int bb = m4(bbm, band);
    const int blk = m4(blkm, band);
    const float* dwo = g_dwo + bb * CSPP;
    float* pwo = g_pwo + bb * CSPP;
    const int p0 = blockIdx.x * 128;
    const int tid = threadIdx.x;
    const int wid = tid >> 5, lane = tid & 31;
    const int ocg = wid >> 1, pxg = wid & 1;
    const int g = lane >> 2, j4 = lane & 3;

    {
        const float4* src = (const float4*)(g_pwwT + (size_t)blk * 4096);
        float4* dstw = (float4*)swt;
#pragma unroll
        for (int i = 0; i < 4; i++)
            dstw[tid + i * 256] = src[tid + i * 256];
    }
    for (int t = tid; t < 8192; t += 256) {
        int ch = t >> 7, px = t & 127;
        int gp = p0 + px;
        sin_[t] = (gp < SPP) ? __uint_as_float(f2tf32(dwo[ch * SPP + gp])) : 0.f;
    }
    __syncthreads();

    float c[8][4] = {};
#pragma unroll
    for (int k8 = 0; k8 < 8; k8++) {
        const float* wsrc = swt + (k8 * 64 + ocg * 16) * 8 + j4 * 2;
        float2 lo = *(const float2*)(wsrc + g * 8);
        float2 hi = *(const float2*)(wsrc + (g + 8) * 8);
        uint32_t a0 = __float_as_uint(lo.x), a2 = __float_as_uint(lo.y);
        uint32_t a1 = __float_as_uint(hi.x), a3 = __float_as_uint(hi.y);
        const float* brow0 = sin_ + (k8 * 8 + j4) * 128 + pxg * 64 + g;
        const float* brow1 = brow0 + 4 * 128;
#pragma unroll
        for (int nt = 0; nt < 8; nt++) {
            uint32_t b0 = __float_as_uint(brow0[nt * 8]);
            uint32_t b1 = __float_as_uint(brow1[nt * 8]);
            mma_tf32(c[nt], a0, a1, a2, a3, b0, b1);
        }
    }

    const int oc_lo = ocg * 16 + g, oc_hi = oc_lo + 8;
    float ls = 0.f, ls2 = 0.f;
#pragma unroll
    for (int nt = 0; nt < 8; nt++) {
        int px = p0 + pxg * 64 + nt * 8 + 2 * j4;
        if (px < SPP) {
            float v0 = c[nt][0], v2 = c[nt][2];
            pwo[oc_lo * SPP + px] = v0; ls += v0; ls2 += v0 * v0;
            pwo[oc_hi * SPP + px] = v2; ls += v2; ls2 += v2 * v2;
        }
        if (px + 1 < SPP) {
            float v1 = c[nt][1], v3 = c[nt][3];
            pwo[oc_lo * SPP + px + 1] = v1; ls += v1; ls2 += v1 * v1;
            pwo[oc_hi * SPP + px + 1] = v3; ls += v3; ls2 += v3 * v3;
        }
    }
    for (int off = 16; off; off >>= 1) {
        ls += __shfl_down_sync(0xffffffffu, ls, off);
        ls2 += __shfl_down_sync(0xffffffffu, ls2, off);
    }
    if (lane == 0) {
        atomicAdd(&g_red[bb * 2], ls);
        atomicAdd(&g_red[bb * 2 + 1], ls2);
    }
}

// ---------------- l1 via bf16 mma (z = band*2 + ochalf) ----------------
#define L1_WBUF 14336
#define L1_IN   1408
#define L1_SMEMB ((L1_WBUF + L1_IN) * 4)

__global__ void __launch_bounds__(256) k_l1mma(int4 bbm, int4 blkm, const float* __restrict__ l1bb) {
    extern __shared__ uint32_t sm[];
    uint32_t* s_in = sm + L1_WBUF;
    const int tid = threadIdx.x;
    const int tx = blockIdx.x * 8, ty = blockIdx.y * 16;
    const int band = blockIdx.z >> 1;
    const int ochalf = blockIdx.z & 1;
    const int bb = m4(bbm, band);
    const int blk = m4(blkm, band);
    const float* l1b = l1bb + blk * 256;
    const int wid = tid >> 5, lane = tid & 31;
    const int ocg = wid >> 1, pxg = wid & 1;
    const int g = lane >> 2, j4 = lane & 3;

    const float m = g_red[bb * 2] * (1.0f / (float)NLN);
    const float inv = rsqrtf(g_red[bb * 2 + 1] * (1.0f / (float)NLN) - m * m + 1e-5f);
    const float* pwo = g_pwo + bb * CSPP;
    float* l1o = g_l1o + bb * L1OSZ;

    for (int t = tid; t < L1_IN; t += 256) s_in[t] = 0u;

    float c[2][8][4] = {};
    unsigned short* s_ine = (unsigned short*)s_in;
    unsigned short* s_ino = (unsigned short*)(s_in + 704);

    for (int icg = 0; icg < 16; icg++) {
        __syncthreads();
        {
            size_t chunk = ((size_t)(blk * 16 + icg) * 2 + ochalf) * L1_WBUF;
            const uint4* src = (const uint4*)(g_l1w_bf + chunk);
            uint4* dstw = (uint4*)sm;
#pragma unroll
            for (int i = 0; i < 14; i++)
                dstw[tid + i * 256] = src[tid + i * 256];
        }
        for (int t = tid; t < 1232; t += 256) {
            int ic = t / 308, r2 = t % 308;
            int r = r2 / 14, cx = r2 % 14;
            float v = (pwo[(icg * 4 + ic) * SPP + (ty + r) * PP + (tx + cx)] - m) * inv;
            unsigned short hb = __bfloat16_as_ushort(__float2bfloat16(v));
            int rowb = (ic * 22 + r) * 16;
            s_ine[rowb + cx] = hb;
            if (cx >= 1) s_ino[rowb + cx - 1] = hb;
        }
        __syncthreads();

        const uint32_t* wb = sm;
        const int r0 = ocg * 32 + g;
        const uint32_t* pbase = s_in + (g & 1) * 704 + ((g >> 1) + j4);
#pragma unroll
        for (int pair = 0; pair < 2; pair++) {
#pragma unroll
            for (int a = 0; a < 7; a++) {
                const uint32_t* ws = wb + (pair * 7 + a) * 1024 + 2 * j4;
                u64t A0lo = *(const u64t*)(ws + r0 * 8);
                u64t A0hi = *(const u64t*)(ws + (r0 + 8) * 8);
                u64t A1lo = *(const u64t*)(ws + (r0 + 16) * 8);
                u64t A1hi = *(const u64t*)(ws + (r0 + 24) * 8);
                uint32_t a00 = (uint32_t)A0lo, a02 = (uint32_t)(A0lo >> 32);
                uint32_t a01 = (uint32_t)A0hi, a03 = (uint32_t)(A0hi >> 32);
                uint32_t a10 = (uint32_t)A1lo, a12 = (uint32_t)(A1lo >> 32);
                uint32_t a11 = (uint32_t)A1hi, a13 = (uint32_t)(A1hi >> 32);
                const uint32_t* p0 = pbase + (pair * 2) * 176 + (pxg * 8 + a) * 8;
                const uint32_t* p1 = p0 + 176;
#pragma unroll
                for (int j = 0; j < 8; j++) {
                    uint32_t b0 = p0[j * 8], b1 = p1[j * 8];
                    mma_bf16(c[0][j], a00, a01, a02, a03, b0, b1);
                    mma_bf16(c[1][j], a10, a11, a12, a13, b0, b1);
                }
            }
        }
    }

#pragma unroll
    for (int mm = 0; mm < 2; mm++) {
        int ocb = ochalf * 128 + ocg * 32 + mm * 16 + g;
        float b_lo = l1b[ocb], b_hi = l1b[ocb + 8];
#pragma unroll
        for (int j = 0; j < 8; j++) {
            int y = ty + pxg * 8 + j;
            int xb = tx + 2 * j4;
            float* o_lo = &l1o[ocb * SP + y * 96 + xb];
            float* o_hi = &l1o[(ocb + 8) * SP + y * 96 + xb];
            o_lo[0] = gelu(c[mm][j][0] + b_lo);
            o_lo[1] = gelu(c[mm][j][1] + b_lo);
            o_hi[0] = gelu(c[mm][j][2] + b_hi);
            o_hi[1] = gelu(c[mm][j][3] + b_hi);
        }
    }
}

// ---------------- l2 via tf32 mma ----------------
__global__ void __launch_bounds__(256) k_l2(int4 bbm, int4 blkm, int4 srcm, int4 r2m, int4 dstm,
                                            const float* __restrict__ biasb) {
    __shared__ __align__(16) float swt[4096];
    __shared__ __align__(16) float sin_[8192];
    const int band = blockIdx.y;
    const int bb = m4(bbm, band);
    const int blk = m4(blkm, band);
    const float* bias = biasb + blk * 64;
    const float* l1o = g_l1o + bb * L1OSZ;
    const int p0 = blockIdx.x * 128;
    const int tid = threadIdx.x;
    const int wid = tid >> 5, lane = tid & 31;
    const int ocg = wid >> 1, pxg = wid & 1;
    const int g = lane >> 2, j4 = lane & 3;

    float c[8][4] = {};

    for (int c0 = 0; c0 < 4; c0++) {
        __syncthreads();
        {
            const float4* src = (const float4*)(g_l2wT + ((size_t)blk * 32 + c0 * 8) * 512);
            float4* dstw = (float4*)swt;
#pragma unroll
            for (int i = 0; i < 4; i++)
                dstw[tid + i * 256] = src[tid + i * 256];
        }
        for (int t = tid; t < 8192; t += 256) {
            int ch = t >> 7, px = t & 127;
            sin_[t] = __uint_as_float(f2tf32(l1o[(c0 * 64 + ch) * SP + p0 + px]));
        }
        __syncthreads();
#pragma unroll
        for (int k8 = 0; k8 < 8; k8++) {
            const float* wsrc = swt + (k8 * 64 + ocg * 16) * 8 + j4 * 2;
            float2 lo = *(const float2*)(wsrc + g * 8);
            float2 hi = *(const float2*)(wsrc + (g + 8) * 8);
            uint32_t a0 = __float_as_uint(lo.x), a2 = __float_as_uint(lo.y);
            uint32_t a1 = __float_as_uint(hi.x), a3 = __float_as_uint(hi.y);
            const float* brow0 = sin_ + (k8 * 8 + j4) * 128 + pxg * 64 + g;
            const float* brow1 = brow0 + 4 * 128;
#pragma unroll
            for (int nt = 0; nt < 8; nt++) {
                uint32_t b0 = __float_as_uint(brow0[nt * 8]);
                uint32_t b1 = __float_as_uint(brow1[nt * 8]);
                mma_tf32(c[nt], a0, a1, a2, a3, b0, b1);
            }
        }
    }

    float* dstp = g_feat[m4(dstm, band)];
    const float* rp1 = g_feat[m4(srcm, band)];
    const int r2 = m4(r2m, band);
    const float* rp2 = (r2 >= 0) ? g_feat[r2] : 0;
    const int oc_lo = ocg * 16 + g, oc_hi = oc_lo + 8;
    const float bi_lo = bias[oc_lo], bi_hi = bias[oc_hi];
#pragma unroll
    for (int nt = 0; nt < 8; nt++) {
        int px = p0 + pxg * 64 + nt * 8 + 2 * j4;
        int i_lo = oc_lo * SP + px;
        int i_hi = oc_hi * SP + px;
        float v0 = c[nt][0] + bi_lo + rp1[i_lo];
        float v1 = c[nt][1] + bi_lo + rp1[i_lo + 1];
        float v2 = c[nt][2] + bi_hi + rp1[i_hi];
        float v3 = c[nt][3] + bi_hi + rp1[i_hi + 1];
        if (rp2) { v0 += rp2[i_lo]; v1 += rp2[i_lo + 1]; v2 += rp2[i_hi]; v3 += rp2[i_hi + 1]; }
        dstp[i_lo] = v0; dstp[i_lo + 1] = v1;
        dstp[i_hi] = v2; dstp[i_hi + 1] = v3;
    }
}

// ---------------- xblock Gram + row-sum ----------------
__global__ void __launch_bounds__(256) k_xg(int4 srcm) {
    __shared__ float sf[1024];
    const int band = blockIdx.y;
    const float* f = g_feat[m4(srcm, band)];
    float* Gp = g_G + band * 4096;
    float* sp = g_s + band * 64;
    const int ag = threadIdx.x >> 4, bg = threadIdx.x & 15;
    float acc[4][4] = {};
    float sacc[4] = {};
    const int tok0 = blockIdx.x * 144;
    for (int tb = 0; tb < 144; tb += 16) {
        __syncthreads();
        for (int t2 = threadIdx.x; t2 < 1024; t2 += 256) sf[t2] = f[(tok0 + tb) * 64 + t2];
        __syncthreads();
#pragma unroll
        for (int tk = 0; tk < 16; tk++) {
            float4 fa = *(const float4*)&sf[tk * 64 + ag * 4];
            float4 fb = *(const float4*)&sf[tk * 64 + bg * 4];
            acc[0][0] += fa.x * fb.x; acc[0][1] += fa.x * fb.y; acc[0][2] += fa.x * fb.z; acc[0][3] += fa.x * fb.w;
            acc[1][0] += fa.y * fb.x; acc[1][1] += fa.y * fb.y; acc[1][2] += fa.y * fb.z; acc[1][3] += fa.y * fb.w;
            acc[2][0] += fa.z * fb.x; acc[2][1] += fa.z * fb.y; acc[2][2] += fa.z * fb.z; acc[2][3] += fa.z * fb.w;
            acc[3][0] += fa.w * fb.x; acc[3][1] += fa.w * fb.y; acc[3][2] += fa.w * fb.z; acc[3][3] += fa.w * fb.w;
            if (ag == 0) { sacc[0] += fb.x; sacc[1] += fb.y; sacc[2] += fb.z; sacc[3] += fb.w; }
        }
    }
    for (int i2 = 0; i2 < 4; i2++)
        for (int j2 = 0; j2 < 4; j2++)
            atomicAdd(&Gp[(ag * 4 + i2) * 64 + bg * 4 + j2], acc[i2][j2]);
    if (ag == 0)
        for (int j2 = 0; j2 < 4; j2++) atomicAdd(&sp[bg * 4 + j2], sacc[j2]);
}

// ---------------- attention core ----------------
__global__ void __launch_bounds__(256) k_xatt(const float* __restrict__ xqw, const float* __restrict__ xqb,
                                              const float* __restrict__ xkw, const float* __restrict__ xkb,
                                              const float* __restrict__ xvw, const float* __restrict__ xvb,
                                              int4 imap) {
    __shared__ float sA[4096];
    __shared__ float sGK[4096];
    __shared__ float ss[64], sQs[64], sKs[64];
    const int band = blockIdx.x;
    const int iw = m4(imap, band);
    const float* Qw = xqw + iw * 4096; const float* Qb = xqb + iw * 64;
    const float* Kw = xkw + iw * 4096; const float* Kb = xkb + iw * 64;
    const float* Vw = xvw + iw * 4096; const float* Vb = xvb + iw * 64;
    const float scale = (iw == 0) ? 0.44721359549995793f : 0.70710678118654752f;
    float* Gp = g_G + band * 4096;
    float* sp = g_s + band * 64;
    const int t = threadIdx.x;
    for (int i = t; i < 4096; i += 256) sA[i] = Gp[i];
    if (t < 64) ss[t] = sp[t];
    __syncthreads();
    if (t < 64) {
        float q = 0.f;
        for (int a2 = 0; a2 < 64; a2++) q += Qw[t * 64 + a2] * ss[a2];
        sQs[t] = q;
    } else if (t < 128) {
        int d = t - 64; float q = 0.f;
        for (int b2 = 0; b2 < 64; b2++) q += Kw[d * 64 + b2] * ss[b2];
        sKs[d] = q;
    }
    for (int i = t; i < 4096; i += 256) {
        int a2 = i >> 6, d = i & 63;
        float s2 = 0.f;
        for (int b2 = 0; b2 < 64; b2++) s2 += sA[a2 * 64 + b2] * Kw[d * 64 + b2];
        sGK[i] = s2;
    }
    __syncthreads();
    for (int i = t; i < 4096; i += 256) Gp[i] = 0.f;
    if (t < 64) sp[t] = 0.f;
    for (int i = t; i < 4096; i += 256) {
        int c = i >> 6, d = i & 63;
        float s2 = Qb[c] * sKs[d] + sQs[c] * Kb[d] + 9216.0f * Qb[c] * Kb[d];
        for (int a2 = 0; a2 < 64; a2++) s2 += Qw[c * 64 + a2] * sGK[a2 * 64 + d];
        sA[i] = s2 * scale;
    }
    __syncthreads();
    if (t < 64) {
        float mx = -1e30f;
        for (int d = 0; d < 64; d++) mx = fmaxf(mx, sA[t * 64 + d]);
        float sm = 0.f;
        for (int d = 0; d < 64; d++) { float e = expf(sA[t * 64 + d] - mx); sA[t * 64 + d] = e; sm += e; }
        float r = 1.0f / sm;
        for (int d = 0; d < 64; d++) sA[t * 64 + d] *= r;
    }
    __syncthreads();
    for (int i = t; i < 4096; i += 256) {
        int a2 = i >> 6, d = i & 63;
        float s2 = 0.f;
        for (int c = 0; c < 64; c++) s2 += Vw[c * 64 + a2] * sA[c * 64 + d];
        g_M[band * 4096 + i] = s2;
    }
    if (t < 64) {
        float s2 = 0.f;
        for (int c = 0; c < 64; c++) s2 += Vb[c] * sA[c * 64 + t];
        g_bias[band * 64 + t] = s2;
    }
}

// ---------------- xblock apply ----------------
__global__ void __launch_bounds__(256) k_xapply(int4 srcm, int4 dstm) {
    __shared__ float sM[4096];
    __shared__ float sb[64];
    __shared__ float sf[2048];
    const int band = blockIdx.y;
    for (int t = threadIdx.x; t < 4096; t += 256) sM[t] = g_M[band * 4096 + t];
    if (threadIdx.x < 64) sb[threadIdx.x] = g_bias[band * 64 + threadIdx.x];
    const int tok0 = blockIdx.x * 32;
    const float* f = g_feat[m4(srcm, band)];
    for (int t = threadIdx.x; t < 2048; t += 256) sf[t] = f[tok0 * 64 + t];
    __syncthreads();
    const int tk = threadIdx.x >> 3, dg = threadIdx.x & 7;
    float acc[8] = {};
#pragma unroll 8
    for (int a2 = 0; a2 < 64; a2++) {
        float fa = sf[tk * 64 + a2];
        float4 m0 = *(const float4*)&sM[a2 * 64 + dg * 8];
        float4 m1 = *(const float4*)&sM[a2 * 64 + dg * 8 + 4];
        acc[0] += fa * m0.x; acc[1] += fa * m0.y; acc[2] += fa * m0.z; acc[3] += fa * m0.w;
        acc[4] += fa * m1.x; acc[5] += fa * m1.y; acc[6] += fa * m1.z; acc[7] += fa * m1.w;
    }
    float* dp = g_feat[m4(dstm, band)];
    const int base = (tok0 + tk) * 64 + dg * 8;
#pragma unroll
    for (int d2 = 0; d2 < 8; d2++) dp[base + d2] = sf[tk * 64 + dg * 8 + d2] + acc[d2] + sb[dg * 8 + d2];
}

// ---------------- op: smem-tiled ----------------
__global__ void __launch_bounds__(256) k_op(int4 srcm, int4 outm, const float* __restrict__ w,
                                            const float* __restrict__ bb) {
    __shared__ float sw[576];
    __shared__ float sx[8 * 324];
    const int band = blockIdx.y;
    const int bx = blockIdx.x;
    const int u0 = (bx / 6) * 16, v0 = (bx % 6) * 16;
    for (int t = threadIdx.x; t < 576; t += 256) {
        int ch = t / 9, k2 = t % 9; int a = k2 / 3, b2 = k2 % 3;
        sw[t] = w[ch * 9 + (2 - a) * 3 + (2 - b2)];
    }
    const float* x = g_feat[m4(srcm, band)];
    const int tu = threadIdx.x / 16, tv = threadIdx.x % 16;
    float acc = bb[0];
    for (int cg = 0; cg < 8; cg++) {
        __syncthreads();
        for (int t = threadIdx.x; t < 2592; t += 256) {
            int c = t / 324, rr = (t % 324) / 18, cc = t % 18;
            int gy = u0 - 1 + rr, gx = v0 - 1 + cc;
            sx[t] = (gy >= 0 && gy < 96 && gx >= 0 && gx < 96) ? x[(cg * 8 + c) * SP + gy * 96 + gx] : 0.f;
        }
        __syncthreads();
#pragma unroll
        for (int c = 0; c < 8; c++) {
            int ch = cg * 8 + c;
#pragma unroll
            for (int a = 0; a < 3; a++)
#pragma unroll
                for (int b2 = 0; b2 < 3; b2++)
                    acc += sx[c * 324 + (tu + a) * 18 + (tv + b2)] * sw[ch * 9 + a * 3 + b2];
        }
    }
    int u = u0 + tu, v = v0 + tv;
    g_opout[m4(outm, band)][v * 96 + u] = acc;
}

__global__ void __launch_bounds__(256) k_idwt(const float* __restrict__ img, float* __restrict__ out) {
    int idx = blockIdx.x * 256 + threadIdx.x;
    if (idx >= SP) return;
    int i = idx / 96, j = idx % 96;
    float a = g_opout[0][idx], b = g_opout[1][idx], c = g_opout[2][idx], d = g_opout[3][idx];
    int r0 = (2 * i) * 192 + 2 * j;
    int r1 = (2 * i + 1) * 192 + 2 * j;
    out[r0]     = 0.5f * (a + b + c + d) + img[r0];
    out[r0 + 1] = 0.5f * (a - b + c - d) + img[r0 + 1];
    out[r1]     = 0.5f * (a + b - c - d) + img[r1];
    out[r1 + 1] = 0.5f * (a - b - c + d) + img[r1 + 1];
}

extern "C" void kernel_launch(void* const* d_in, const int* in_sizes, int n_in,
                              void* d_out, int out_size) {
    (void)in_sizes; (void)n_in; (void)out_size;
    const float* images = (const float*)d_in[0];
    const float* ip_w  = (const float*)d_in[1];
    const float* ip_b  = (const float*)d_in[2];
    const float* op_w  = (const float*)d_in[3];
    const float* op_b  = (const float*)d_in[4];
    const float* cb_dw = (const float*)d_in[5];
    const float* cb_pw = (const float*)d_in[6];
    const float* cb_l1w = (const float*)d_in[7];
    const float* cb_l1b = (const float*)d_in[8];
    const float* cb_l2w = (const float*)d_in[9];
    const float* cb_l2b = (const float*)d_in[10];
    const float* xqw = (const float*)d_in[11];
    const float* xqb = (const float*)d_in[12];
    const float* xkw = (const float*)d_in[13];
    const float* xkb = (const float*)d_in[14];
    const float* xvw = (const float*)d_in[15];
    const float* xvb = (const float*)d_in[16];
    float* out = (float*)d_out;

    cudaFuncSetAttribute(k_l1mma, cudaFuncAttributeMaxDynamicSharedMemorySize, L1_SMEMB);

    k_dwt<<<36, 256>>>(images);
    k_l1wtb<<<(6 * 16 * 2 * 14 * 128 * 8 + 255) / 256, 256>>>(cb_l1w);
    k_l2wt<<<(6 * 32 * 64 * 8 + 255) / 256, 256>>>(cb_l2w);
    k_pwwt<<<(6 * 8 * 64 * 8 + 255) / 256, 256>>>(cb_pw);

    auto cb = [&](int nb, int4 bbm, int4 blkm, int4 srcm, int4 r2m, int4 dstm) {
        k_dw7<<<dim3(4, 4, 64 * nb), 256>>>(srcm, bbm, blkm, cb_dw);
        k_pw<<<dim3(82, nb), 256>>>(bbm, blkm);
        k_l1mma<<<dim3(12, 6, 2 * nb), 256, L1_SMEMB>>>(bbm, blkm, cb_l1b);
        k_l2<<<dim3(72, nb), 256>>>(bbm, blkm, srcm, r2m, dstm, cb_l2b);
    };

    // slots: HF band b (b=0..2): A=2b, B=2b+1 ; LF: lf=6, c1=7, c2=8, xlow=9, c3=10, c4=11
    const int4 bb4   = make_int4(0, 1, 2, 3);
    const int4 bbLF  = make_int4(3, 3, 3, 3);

    // Stage A: ip all 4 bands
    k_ip<<<dim3(36, 4, 4), 256>>>(make_int4(1, 2, 3, 0), make_int4(0, 2, 4, 6), ip_w, ip_b);

    // Stage B: CB-I (HF blk4: A->B ; LF blk0: lf->c1)
    cb(4, bb4, make_int4(4, 4, 4, 0), make_int4(0, 2, 4, 6),
       make_int4(-1, -1, -1, -1), make_int4(1, 3, 5, 7));

    // Stage C: cb1 LF-only (c2 = cb1(c1) + c1)
    cb(1, bbLF, make_int4(1, 1, 1, 1), make_int4(7, 7, 7, 7),
       make_int4(7, 7, 7, 7), make_int4(8, 8, 8, 8));

    // Stage D: XB all 4 bands
    {
        int4 srcm = make_int4(1, 3, 5, 7);
        int4 dstm = make_int4(0, 2, 4, 9);
        k_xg<<<dim3(64, 4), 256>>>(srcm);
        k_xatt<<<4, 256>>>(xqw, xqb, xkw, xkb, xvw, xvb, make_int4(1, 1, 1, 0));
        k_xapply<<<dim3(288, 4), 256>>>(srcm, dstm);
    }

    // Stage E: CB-II (HF blk5: h2 = cb5(hx)+h1 ; LF blk2: c3 = cb2(xlow)+c2)
    cb(4, bb4, make_int4(5, 5, 5, 2), make_int4(0, 2, 4, 9),
       make_int4(1, 3, 5, 8), make_int4(1, 3, 5, 10));

    // Stage F: cb3 LF-only (c4 = cb3(c3) + c1)
    cb(1, bbLF, make_int4(3, 3, 3, 3), make_int4(10, 10, 10, 10),
       make_int4(7, 7, 7, 7), make_int4(11, 11, 11, 11));

    // Stage G: op all 4 bands
    k_op<<<dim3(36, 4), 256>>>(make_int4(1, 3, 5, 11), make_int4(1, 2, 3, 0), op_w, op_b);

    k_idwt<<<36, 256>>>(images, out);
}